// round 9
// baseline (speedup 1.0000x reference)
#include <cuda_runtime.h>
#include <cuda_bf16.h>
#include <math.h>
#include <stdint.h>

#define BQ 8
#define TT 512
#define CC 512
#define HH 8
#define DHD 64
#define LL 2
#define MM (BQ * TT)
#define FF (4 * CC)
#define STEPS 4
typedef __nv_bfloat16 bf16;
typedef long long ll;

// ------------------------- scratch (__device__ globals) --------------------
__device__ __align__(16) float g_x[MM * CC];
__device__ __align__(16) float g_att[BQ * HH * TT * TT];
__device__ __align__(16) float g_bqkv[LL * 3 * CC];
__device__ __align__(16) bf16 g_xnh[MM * CC], g_xnl[MM * CC];
__device__ __align__(16) bf16 g_qkvh[MM * 3 * CC], g_qkvl[MM * 3 * CC];
__device__ __align__(16) bf16 g_yh[MM * CC],  g_yl[MM * CC];
__device__ __align__(16) bf16 g_hh[MM * FF],  g_hl[MM * FF];
__device__ __align__(16) bf16 g_ph[BQ * HH * TT * TT], g_pl[BQ * HH * TT * TT];
#define NW 6553600
__device__ __align__(16) bf16 g_wh[NW], g_wl[NW];
#define WOFF_L   3145728
#define WOFF_QKV 0
#define WOFF_P   786432
#define WOFF_1   1048576
#define WOFF_2   2097152
#define WOFF_HD  6291456

// ------------------------- helpers -----------------------------------------
__device__ __forceinline__ void split1(float v, bf16 &h, bf16 &l) {
    h = __float2bfloat16(v);
    l = __float2bfloat16(v - __bfloat162float(h));
}
__device__ __forceinline__ void split2(float x, float y, unsigned &hi, unsigned &lo) {
    bf16 hx, lx, hy, ly;
    split1(x, hx, lx); split1(y, hy, ly);
    hi = ((unsigned)__bfloat16_as_ushort(hy) << 16) | (unsigned)__bfloat16_as_ushort(hx);
    lo = ((unsigned)__bfloat16_as_ushort(ly) << 16) | (unsigned)__bfloat16_as_ushort(lx);
}
__device__ __forceinline__ unsigned smem_u32(const void *p) {
    return (unsigned)__cvta_generic_to_shared(p);
}
__device__ __forceinline__ float gelu_exact(float x) {
    return 0.5f * x * (1.0f + erff(x * 0.7071067811865476f));
}
__device__ __forceinline__ void mma_bf16(float *d, const unsigned *a, unsigned b0, unsigned b1) {
    asm volatile(
        "mma.sync.aligned.m16n8k16.row.col.f32.bf16.bf16.f32 "
        "{%0,%1,%2,%3}, {%4,%5,%6,%7}, {%8,%9}, {%0,%1,%2,%3};\n"
        : "+f"(d[0]), "+f"(d[1]), "+f"(d[2]), "+f"(d[3])
        : "r"(a[0]), "r"(a[1]), "r"(a[2]), "r"(a[3]), "r"(b0), "r"(b1));
}
#define LDSM4(R0, R1, R2, R3, ADDR) \
    asm volatile("ldmatrix.sync.aligned.m8n8.x4.shared.b16 {%0,%1,%2,%3}, [%4];" \
                 : "=r"(R0), "=r"(R1), "=r"(R2), "=r"(R3) : "r"(ADDR))
#define LDSM4T(R0, R1, R2, R3, ADDR) \
    asm volatile("ldmatrix.sync.aligned.m8n8.x4.trans.shared.b16 {%0,%1,%2,%3}, [%4];" \
                 : "=r"(R0), "=r"(R1), "=r"(R2), "=r"(R3) : "r"(ADDR))
#define CP16(dst, src) \
    asm volatile("cp.async.cg.shared.global [%0], [%1], 16;" :: "r"(dst), "l"(src))
#define CP_COMMIT() asm volatile("cp.async.commit_group;" ::: "memory")
#define CP_WAIT1()  asm volatile("cp.async.wait_group 1;" ::: "memory")
#define CP_WAIT0()  asm volatile("cp.async.wait_group 0;" ::: "memory")

// ------------------------- HMMA GEMM (bf16 split, 3-stage pipeline) --------
// D[M,N] = Ahi@Bhi + Ahi@Blo + Alo@Bhi (+bias). A K-major [m][k].
// transB=1: B [N,K] (C=A@B^T); transB=0: B [K,N].
// Tile 128x64xK32, 8 warps (warp 32x32), 3-stage cp.async.
// KEY FIX vs R7: the 3 split-term MMAs per accumulator are issued as three
// separated passes (8 independent MMAs between RAW-dependent ones) instead of
// back-to-back chains; accumulation order per acc unchanged (bit-identical).
// ep: 0 Cf=acc+bias; 1 split(gelu); 2 Cf+=; 3 split store.
#define APITCH 40
#define BPT    40
#define BPN    72
#define STAGE_B 30720u
#define SMEM_BYTES (3 * 30720)

__global__ __launch_bounds__(256, 2)
void gemm_hmma(const bf16 *__restrict__ Ah_, const bf16 *__restrict__ Al_, int lda,
               ll sA0, ll sA1,
               const bf16 *__restrict__ Bh_, const bf16 *__restrict__ Bl_, int ldb,
               ll sB0, ll sB1,
               float *__restrict__ Cf, bf16 *__restrict__ Coh, bf16 *__restrict__ Col,
               int ldc, ll sC0, ll sC1,
               int K, int zdiv, const float *__restrict__ bias, int transB, int ep)
{
    extern __shared__ __align__(16) bf16 sm[];
    int z = blockIdx.z;
    ll zo0 = z / zdiv, zo1 = z % zdiv;
    Ah_ += zo0 * sA0 + zo1 * sA1;  Al_ += zo0 * sA0 + zo1 * sA1;
    Bh_ += zo0 * sB0 + zo1 * sB1;  Bl_ += zo0 * sB0 + zo1 * sB1;
    ll coff = zo0 * sC0 + zo1 * sC1;
    int n0 = blockIdx.x * 64, m0 = blockIdx.y * 128;

    int t = threadIdx.x, lane = t & 31, warp = t >> 5;
    int wm = (warp & 3) << 5, wn = (warp >> 2) << 5;
    int gg = lane >> 2, cc2 = (lane & 3) << 1;

    int a_ck = (t & 3) << 3, a_rw = t >> 2;
    int bt_rw = t >> 2, bt_ck = (t & 3) << 3;
    int bn_rw = t >> 3, bn_ck = (t & 7) << 3;

    unsigned sb = smem_u32(sm);

    int sel = lane >> 3, lr = lane & 7;
    int ar_g = lr + ((sel & 1) ? 8 : 0);
    int a_cs = (sel & 2) ? 8 : 0;
    int btr_g = lr + ((sel & 2) ? 8 : 0);
    int bt_cs = (sel & 1) ? 8 : 0;
    int bnr_g = lr + ((sel & 1) ? 8 : 0);
    int bn_cs = (sel & 2) ? 8 : 0;

    float acc[2][4][4];
#pragma unroll
    for (int mi = 0; mi < 2; mi++)
#pragma unroll
        for (int j = 0; j < 4; j++)
#pragma unroll
            for (int r = 0; r < 4; r++) acc[mi][j][r] = 0.f;

#define ISSUE(S, K0) do { \
    unsigned bb = sb + (unsigned)(S) * STAGE_B; \
    _Pragma("unroll") \
    for (int p = 0; p < 2; p++) { \
        int row = a_rw + 64 * p; \
        ll go = (ll)(m0 + row) * lda + (K0) + a_ck; \
        unsigned d = (unsigned)((row * APITCH + a_ck) * 2); \
        CP16(bb + d, Ah_ + go); \
        CP16(bb + 10240u + d, Al_ + go); \
    } \
    if (transB) { \
        ll go = (ll)(n0 + bt_rw) * ldb + (K0) + bt_ck; \
        unsigned d = (unsigned)((bt_rw * BPT + bt_ck) * 2); \
        CP16(bb + 20480u + d, Bh_ + go); \
        CP16(bb + 25600u + d, Bl_ + go); \
    } else { \
        ll go = (ll)((K0) + bn_rw) * ldb + n0 + bn_ck; \
        unsigned d = (unsigned)((bn_rw * BPN + bn_ck) * 2); \
        CP16(bb + 20480u + d, Bh_ + go); \
        CP16(bb + 25600u + d, Bl_ + go); \
    } \
    CP_COMMIT(); \
} while (0)

    int nk = K >> 5;
    ISSUE(0, 0);
    if (nk > 1) ISSUE(1, 32);

    for (int c = 0; c < nk; c++) {
        if (c + 1 < nk) CP_WAIT1(); else CP_WAIT0();
        __syncthreads();
        if (c + 2 < nk) ISSUE((c + 2) % 3, (c + 2) << 5);

        unsigned bb = sb + (unsigned)(c % 3) * STAGE_B;
        unsigned aoh = bb, aol = bb + 10240u, boh = bb + 20480u, bol = bb + 25600u;
#pragma unroll
        for (int ks = 0; ks < 2; ks++) {
            int kb = ks << 4;
            unsigned ah[2][4], al2[2][4];
#pragma unroll
            for (int mi = 0; mi < 2; mi++) {
                unsigned off = (unsigned)(((wm + 16 * mi + ar_g) * APITCH + kb + a_cs) * 2);
                LDSM4(ah[mi][0], ah[mi][1], ah[mi][2], ah[mi][3], aoh + off);
                LDSM4(al2[mi][0], al2[mi][1], al2[mi][2], al2[mi][3], aol + off);
            }
            unsigned bh[4][2], bl2[4][2];
#pragma unroll
            for (int p = 0; p < 2; p++) {
                if (transB) {
                    unsigned off = (unsigned)(((wn + 16 * p + btr_g) * BPT + kb + bt_cs) * 2);
                    LDSM4(bh[2 * p][0], bh[2 * p][1], bh[2 * p + 1][0], bh[2 * p + 1][1], boh + off);
                    LDSM4(bl2[2 * p][0], bl2[2 * p][1], bl2[2 * p + 1][0], bl2[2 * p + 1][1], bol + off);
                } else {
                    unsigned off = (unsigned)(((kb + bnr_g) * BPN + wn + 16 * p + bn_cs) * 2);
                    LDSM4T(bh[2 * p][0], bh[2 * p][1], bh[2 * p + 1][0], bh[2 * p + 1][1], boh + off);
                    LDSM4T(bl2[2 * p][0], bl2[2 * p][1], bl2[2 * p + 1][0], bl2[2 * p + 1][1], bol + off);
                }
            }
            // PASS 1: all hi*hi (8 independent MMAs)
#pragma unroll
            for (int mi = 0; mi < 2; mi++)
#pragma unroll
                for (int j = 0; j < 4; j++)
                    mma_bf16(acc[mi][j], ah[mi], bh[j][0], bh[j][1]);
            // PASS 2: all hi*lo
#pragma unroll
            for (int mi = 0; mi < 2; mi++)
#pragma unroll
                for (int j = 0; j < 4; j++)
                    mma_bf16(acc[mi][j], ah[mi], bl2[j][0], bl2[j][1]);
            // PASS 3: all lo*hi
#pragma unroll
            for (int mi = 0; mi < 2; mi++)
#pragma unroll
                for (int j = 0; j < 4; j++)
                    mma_bf16(acc[mi][j], al2[mi], bh[j][0], bh[j][1]);
        }
    }

#pragma unroll
    for (int mi = 0; mi < 2; mi++)
#pragma unroll
        for (int j = 0; j < 4; j++) {
            int col = n0 + wn + (j << 3) + cc2;
            int row = m0 + wm + (mi << 4) + gg;
            float b0v = bias ? bias[col] : 0.f;
            float b1v = bias ? bias[col + 1] : 0.f;
            float v00 = acc[mi][j][0] + b0v, v01 = acc[mi][j][1] + b1v;
            float v10 = acc[mi][j][2] + b0v, v11 = acc[mi][j][3] + b1v;
            ll g0 = (ll)row * ldc + col + coff;
            ll g1 = (ll)(row + 8) * ldc + col + coff;
            if (ep == 0) {
                *(float2 *)(Cf + g0) = make_float2(v00, v01);
                *(float2 *)(Cf + g1) = make_float2(v10, v11);
            } else if (ep == 2) {
                float2 o0 = *(float2 *)(Cf + g0), o1 = *(float2 *)(Cf + g1);
                *(float2 *)(Cf + g0) = make_float2(o0.x + v00, o0.y + v01);
                *(float2 *)(Cf + g1) = make_float2(o1.x + v10, o1.y + v11);
            } else {
                if (ep == 1) {
                    v00 = gelu_exact(v00); v01 = gelu_exact(v01);
                    v10 = gelu_exact(v10); v11 = gelu_exact(v11);
                }
                unsigned hi, lo;
                split2(v00, v01, hi, lo);
                *(unsigned *)(Coh + g0) = hi; *(unsigned *)(Col + g0) = lo;
                split2(v10, v11, hi, lo);
                *(unsigned *)(Coh + g1) = hi; *(unsigned *)(Col + g1) = lo;
            }
        }
}

// ------------------------- one-time weight transpose+split -----------------
__global__ __launch_bounds__(256)
void wconv_kernel(const float *__restrict__ W, bf16 *__restrict__ th,
                  bf16 *__restrict__ tl, int K, int N)
{
    __shared__ float tile[32][33];
    int bx = blockIdx.x * 32, by = blockIdx.y * 32;
    int tx = threadIdx.x & 31, ty = threadIdx.x >> 5;
#pragma unroll
    for (int j = 0; j < 4; j++) {
        int kk = ty + j * 8;
        tile[kk][tx] = W[(ll)(by + kk) * N + bx + tx];
    }
    __syncthreads();
#pragma unroll
    for (int j = 0; j < 4; j++) {
        int nn = ty + j * 8;
        float v = tile[tx][nn];
        bf16 h, l;
        split1(v, h, l);
        ll o = (ll)(bx + nn) * K + by + tx;
        th[o] = h; tl[o] = l;
    }
}

__global__ void bcat_kernel(const float *__restrict__ bq, const float *__restrict__ bk,
                            const float *__restrict__ bv, float *__restrict__ dst)
{
    int i = blockIdx.x * 256 + threadIdx.x;
    if (i >= LL * 3 * CC) return;
    int l = i / (3 * CC), c = i % (3 * CC);
    float v;
    if (c < CC) v = bq[l * CC + c];
    else if (c < 2 * CC) v = bk[l * CC + c - CC];
    else v = bv[l * CC + c - 2 * CC];
    dst[i] = v;
}

// ------------------------- element kernels ---------------------------------
__global__ void embed_kernel(const int *__restrict__ idx, const float *__restrict__ tok,
                             const float *__restrict__ pos, float *__restrict__ x)
{
    int i = blockIdx.x * 256 + threadIdx.x;
    if (i >= MM * CC) return;
    int c = i & (CC - 1);
    int bt = i >> 9;
    int tp = bt & (TT - 1);
    x[i] = tok[idx[bt] * CC + c] + pos[tp * CC + c];
}

__global__ __launch_bounds__(256)
void ln_kernel(const float *__restrict__ x, bf16 *__restrict__ oh, bf16 *__restrict__ ol,
               const float *__restrict__ gam, const float *__restrict__ bet)
{
    __shared__ float red[256];
    int row = blockIdx.x, t = threadIdx.x;
    const float *xr = x + (ll)row * CC;
    float a = xr[t], b = xr[t + 256];
    red[t] = a + b;
    __syncthreads();
    for (int off = 128; off > 0; off >>= 1) {
        if (t < off) red[t] += red[t + off];
        __syncthreads();
    }
    float mu = red[0] * (1.0f / CC);
    __syncthreads();
    float da = a - mu, db = b - mu;
    red[t] = da * da + db * db;
    __syncthreads();
    for (int off = 128; off > 0; off >>= 1) {
        if (t < off) red[t] += red[t + off];
        __syncthreads();
    }
    float rstd = rsqrtf(red[0] * (1.0f / CC) + 1e-5f);
    float r0 = da * rstd * gam[t] + bet[t];
    float r1 = db * rstd * gam[t + 256] + bet[t + 256];
    bf16 h, l;
    ll o = (ll)row * CC;
    split1(r0, h, l); oh[o + t] = h;       ol[o + t] = l;
    split1(r1, h, l); oh[o + t + 256] = h; ol[o + t + 256] = l;
}

__global__ __launch_bounds__(128)
void softmax_kernel(const float *__restrict__ att, bf16 *__restrict__ ph,
                    bf16 *__restrict__ pl)
{
    __shared__ float red[128];
    int row = blockIdx.x, t = threadIdx.x;
    const float *p = att + (ll)row * TT;
    float v[4];
    float m = -1e30f;
#pragma unroll
    for (int i = 0; i < 4; i++) { v[i] = p[t + (i << 7)] * 0.125f; m = fmaxf(m, v[i]); }
    red[t] = m; __syncthreads();
    for (int off = 64; off > 0; off >>= 1) {
        if (t < off) red[t] = fmaxf(red[t], red[t + off]);
        __syncthreads();
    }
    m = red[0]; __syncthreads();
    float s = 0.f;
#pragma unroll
    for (int i = 0; i < 4; i++) { v[i] = __expf(v[i] - m); s += v[i]; }
    red[t] = s; __syncthreads();
    for (int off = 64; off > 0; off >>= 1) {
        if (t < off) red[t] += red[t + off];
        __syncthreads();
    }
    float inv = 1.0f / red[0];
    ll o = (ll)row * TT;
#pragma unroll
    for (int i = 0; i < 4; i++) {
        bf16 h, l;
        split1(v[i] * inv, h, l);
        ph[o + t + (i << 7)] = h;
        pl[o + t + (i << 7)] = l;
    }
}

// ------------------------- host orchestration ------------------------------
static void run_hm(const bf16 *Ah, const bf16 *Al, int lda, ll sA0, ll sA1,
                   const bf16 *Bh, const bf16 *Bl, int ldb, ll sB0, ll sB1,
                   float *Cf, bf16 *Coh, bf16 *Col, int ldc, ll sC0, ll sC1,
                   int Mr, int Nc, int K, int zdiv, int Z,
                   const float *bias, int transB, int ep)
{
    dim3 g(Nc / 64, Mr / 128, Z);
    gemm_hmma<<<g, 256, SMEM_BYTES>>>(Ah, Al, lda, sA0, sA1, Bh, Bl, ldb, sB0, sB1,
                                      Cf, Coh, Col, ldc, sC0, sC1, K, zdiv, bias, transB, ep);
}

extern "C" void kernel_launch(void *const *d_in, const int *in_sizes, int n_in,
                              void *d_out, int out_size)
{
    (void)in_sizes; (void)n_in; (void)out_size;
    const int   *idx  = (const int *)d_in[0];
    const float *tok  = (const float *)d_in[1];
    const float *pos  = (const float *)d_in[2];
    const float *ln1g = (const float *)d_in[3];
    const float *ln1b = (const float *)d_in[4];
    const float *Wq   = (const float *)d_in[5];
    const float *bq   = (const float *)d_in[6];
    const float *Wk   = (const float *)d_in[7];
    const float *bk   = (const float *)d_in[8];
    const float *Wv   = (const float *)d_in[9];
    const float *bv   = (const float *)d_in[10];
    const float *Wp   = (const float *)d_in[11];
    const float *bp   = (const float *)d_in[12];
    const float *ln2g = (const float *)d_in[13];
    const float *ln2b = (const float *)d_in[14];
    const float *W1   = (const float *)d_in[15];
    const float *b1   = (const float *)d_in[16];
    const float *W2   = (const float *)d_in[17];
    const float *b2   = (const float *)d_in[18];
    const float *lnfg = (const float *)d_in[19];
    const float *lnfb = (const float *)d_in[20];
    const float *Wh   = (const float *)d_in[21];
    float *out = (float *)d_out;

    static int smem_set = 0;
    if (!smem_set) {
        cudaFuncSetAttribute(gemm_hmma, cudaFuncAttributeMaxDynamicSharedMemorySize, SMEM_BYTES);
        smem_set = 1;
    }

    float *x, *att, *bqkv;
    bf16 *xnh, *xnl, *qkvh, *qkvl, *yh, *yl, *hh, *hl, *ph, *pl, *wh, *wl;
    cudaGetSymbolAddress((void **)&x, g_x);
    cudaGetSymbolAddress((void **)&att, g_att);
    cudaGetSymbolAddress((void **)&bqkv, g_bqkv);
    cudaGetSymbolAddress((void **)&xnh, g_xnh);   cudaGetSymbolAddress((void **)&xnl, g_xnl);
    cudaGetSymbolAddress((void **)&qkvh, g_qkvh); cudaGetSymbolAddress((void **)&qkvl, g_qkvl);
    cudaGetSymbolAddress((void **)&yh, g_yh);     cudaGetSymbolAddress((void **)&yl, g_yl);
    cudaGetSymbolAddress((void **)&hh, g_hh);     cudaGetSymbolAddress((void **)&hl, g_hl);
    cudaGetSymbolAddress((void **)&ph, g_ph);     cudaGetSymbolAddress((void **)&pl, g_pl);
    cudaGetSymbolAddress((void **)&wh, g_wh);     cudaGetSymbolAddress((void **)&wl, g_wl);

    dim3 tb(256);
    for (int l = 0; l < LL; l++) {
        ll wb = (ll)l * WOFF_L;
        wconv_kernel<<<dim3(CC / 32, CC / 32), tb>>>(Wq + l * CC * CC, wh + wb, wl + wb, CC, CC);
        wconv_kernel<<<dim3(CC / 32, CC / 32), tb>>>(Wk + l * CC * CC, wh + wb + 262144, wl + wb + 262144, CC, CC);
        wconv_kernel<<<dim3(CC / 32, CC / 32), tb>>>(Wv + l * CC * CC, wh + wb + 524288, wl + wb + 524288, CC, CC);
        wconv_kernel<<<dim3(CC / 32, CC / 32), tb>>>(Wp + l * CC * CC, wh + wb + WOFF_P, wl + wb + WOFF_P, CC, CC);
        wconv_kernel<<<dim3(FF / 32, CC / 32), tb>>>(W1 + (ll)l * CC * FF, wh + wb + WOFF_1, wl + wb + WOFF_1, CC, FF);
        wconv_kernel<<<dim3(CC / 32, FF / 32), tb>>>(W2 + (ll)l * FF * CC, wh + wb + WOFF_2, wl + wb + WOFF_2, FF, CC);
    }
    wconv_kernel<<<dim3(CC / 32, CC / 32), tb>>>(Wh, wh + WOFF_HD, wl + WOFF_HD, CC, CC);
    bcat_kernel<<<(LL * 3 * CC + 255) / 256, 256>>>(bq, bk, bv, bqkv);

    embed_kernel<<<(MM * CC + 255) / 256, 256>>>(idx, tok, pos, x);

    const ll TC = (ll)TT * CC;
    const ll T2 = (ll)TT * TT;
    const ll QKVROW = 3 * CC;
    const ll SBATCH = (ll)TT * QKVROW;

    for (int s = 0; s < STEPS; s++) {
        for (int l = 0; l < LL; l++) {
            ll wb = (ll)l * WOFF_L;
            ln_kernel<<<MM, 256>>>(x, xnh, xnl, ln1g + l * CC, ln1b + l * CC);
            // fused QKV
            run_hm(xnh, xnl, CC, 0, 0, wh + wb + WOFF_QKV, wl + wb + WOFF_QKV, CC, 0, 0,
                   nullptr, qkvh, qkvl, (int)QKVROW, 0, 0,
                   MM, (int)QKVROW, CC, 1, 1, bqkv + l * QKVROW, 1, 3);
            // scores[b,h] = Q @ K^T
            run_hm(qkvh, qkvl, (int)QKVROW, SBATCH, DHD,
                   qkvh + CC, qkvl + CC, (int)QKVROW, SBATCH, DHD,
                   att, nullptr, nullptr, TT, (ll)HH * T2, T2,
                   TT, TT, DHD, HH, BQ * HH, nullptr, 1, 0);
            softmax_kernel<<<BQ * HH * TT, 128>>>(att, ph, pl);
            // y = P @ V
            run_hm(ph, pl, TT, (ll)HH * T2, T2,
                   qkvh + 2 * CC, qkvl + 2 * CC, (int)QKVROW, SBATCH, DHD,
                   nullptr, yh, yl, CC, TC, DHD,
                   TT, DHD, TT, HH, BQ * HH, nullptr, 0, 3);
            // x += y @ Wp + bp
            run_hm(yh, yl, CC, 0, 0, wh + wb + WOFF_P, wl + wb + WOFF_P, CC, 0, 0,
                   x, nullptr, nullptr, CC, 0, 0, MM, CC, CC, 1, 1, bp + l * CC, 1, 2);
            ln_kernel<<<MM, 256>>>(x, xnh, xnl, ln2g + l * CC, ln2b + l * CC);
            // h = gelu(xn @ W1 + b1)
            run_hm(xnh, xnl, CC, 0, 0, wh + wb + WOFF_1, wl + wb + WOFF_1, CC, 0, 0,
                   nullptr, hh, hl, FF, 0, 0, MM, FF, CC, 1, 1, b1 + l * FF, 1, 1);
            // x += h @ W2 + b2
            run_hm(hh, hl, FF, 0, 0, wh + wb + WOFF_2, wl + wb + WOFF_2, FF, 0, 0,
                   x, nullptr, nullptr, CC, 0, 0, MM, CC, FF, 1, 1, b2 + l * CC, 1, 2);
        }
    }
    ln_kernel<<<MM, 256>>>(x, xnh, xnl, lnfg, lnfb);
    run_hm(xnh, xnl, CC, 0, 0, wh + WOFF_HD, wl + WOFF_HD, CC, 0, 0,
           out, nullptr, nullptr, CC, 0, 0, MM, CC, CC, 1, 1, nullptr, 1, 0);
}

// round 10
// speedup vs baseline: 1.1290x; 1.1290x over previous
#include <cuda_runtime.h>
#include <cuda_bf16.h>
#include <math.h>
#include <stdint.h>

#define BQ 8
#define TT 512
#define CC 512
#define HH 8
#define DHD 64
#define LL 2
#define MM (BQ * TT)
#define FF (4 * CC)
#define STEPS 4
typedef __nv_bfloat16 bf16;
typedef long long ll;

// ------------------------- scratch (__device__ globals) --------------------
__device__ __align__(16) float g_x[MM * CC];
__device__ __align__(16) float g_bqkv[LL * 3 * CC];
__device__ __align__(16) bf16 g_xnh[MM * CC], g_xnl[MM * CC];
__device__ __align__(16) bf16 g_qkvh[MM * 3 * CC], g_qkvl[MM * 3 * CC];
__device__ __align__(16) bf16 g_yh[MM * CC],  g_yl[MM * CC];
__device__ __align__(16) bf16 g_hh[MM * FF],  g_hl[MM * FF];
#define NW 6553600
__device__ __align__(16) bf16 g_wh[NW], g_wl[NW];
#define WOFF_L   3145728
#define WOFF_QKV 0
#define WOFF_P   786432
#define WOFF_1   1048576
#define WOFF_2   2097152
#define WOFF_HD  6291456

// ------------------------- helpers -----------------------------------------
__device__ __forceinline__ void split1(float v, bf16 &h, bf16 &l) {
    h = __float2bfloat16(v);
    l = __float2bfloat16(v - __bfloat162float(h));
}
__device__ __forceinline__ void split2(float x, float y, unsigned &hi, unsigned &lo) {
    bf16 hx, lx, hy, ly;
    split1(x, hx, lx); split1(y, hy, ly);
    hi = ((unsigned)__bfloat16_as_ushort(hy) << 16) | (unsigned)__bfloat16_as_ushort(hx);
    lo = ((unsigned)__bfloat16_as_ushort(ly) << 16) | (unsigned)__bfloat16_as_ushort(lx);
}
__device__ __forceinline__ unsigned smem_u32(const void *p) {
    return (unsigned)__cvta_generic_to_shared(p);
}
__device__ __forceinline__ float gelu_exact(float x) {
    return 0.5f * x * (1.0f + erff(x * 0.7071067811865476f));
}
__device__ __forceinline__ void mma_bf16(float *d, const unsigned *a, unsigned b0, unsigned b1) {
    asm volatile(
        "mma.sync.aligned.m16n8k16.row.col.f32.bf16.bf16.f32 "
        "{%0,%1,%2,%3}, {%4,%5,%6,%7}, {%8,%9}, {%0,%1,%2,%3};\n"
        : "+f"(d[0]), "+f"(d[1]), "+f"(d[2]), "+f"(d[3])
        : "r"(a[0]), "r"(a[1]), "r"(a[2]), "r"(a[3]), "r"(b0), "r"(b1));
}
#define LDSM4(R0, R1, R2, R3, ADDR) \
    asm volatile("ldmatrix.sync.aligned.m8n8.x4.shared.b16 {%0,%1,%2,%3}, [%4];" \
                 : "=r"(R0), "=r"(R1), "=r"(R2), "=r"(R3) : "r"(ADDR))
#define LDSM4T(R0, R1, R2, R3, ADDR) \
    asm volatile("ldmatrix.sync.aligned.m8n8.x4.trans.shared.b16 {%0,%1,%2,%3}, [%4];" \
                 : "=r"(R0), "=r"(R1), "=r"(R2), "=r"(R3) : "r"(ADDR))
#define CP16(dst, src) \
    asm volatile("cp.async.cg.shared.global [%0], [%1], 16;" :: "r"(dst), "l"(src))
#define CP_COMMIT() asm volatile("cp.async.commit_group;" ::: "memory")
#define CP_WAIT1()  asm volatile("cp.async.wait_group 1;" ::: "memory")
#define CP_WAIT0()  asm volatile("cp.async.wait_group 0;" ::: "memory")

// ------------------------- HMMA GEMM (unchanged core from R7/R8) -----------
#define APITCH 40
#define BPT    40
#define BPN    72
#define STAGE_B 30720u
#define SMEM_BYTES (3 * 30720)

__global__ __launch_bounds__(256, 2)
void gemm_hmma(const bf16 *__restrict__ Ah_, const bf16 *__restrict__ Al_, int lda,
               ll sA0, ll sA1,
               const bf16 *__restrict__ Bh_, const bf16 *__restrict__ Bl_, int ldb,
               ll sB0, ll sB1,
               float *__restrict__ Cf, bf16 *__restrict__ Coh, bf16 *__restrict__ Col,
               int ldc, ll sC0, ll sC1,
               int K, int zdiv, const float *__restrict__ bias, int transB, int ep)
{
    extern __shared__ __align__(16) bf16 sm[];
    int z = blockIdx.z;
    ll zo0 = z / zdiv, zo1 = z % zdiv;
    Ah_ += zo0 * sA0 + zo1 * sA1;  Al_ += zo0 * sA0 + zo1 * sA1;
    Bh_ += zo0 * sB0 + zo1 * sB1;  Bl_ += zo0 * sB0 + zo1 * sB1;
    ll coff = zo0 * sC0 + zo1 * sC1;
    int n0 = blockIdx.x * 64, m0 = blockIdx.y * 128;

    int t = threadIdx.x, lane = t & 31, warp = t >> 5;
    int wm = (warp & 3) << 5, wn = (warp >> 2) << 5;
    int gg = lane >> 2, cc2 = (lane & 3) << 1;

    int a_ck = (t & 3) << 3, a_rw = t >> 2;
    int bt_rw = t >> 2, bt_ck = (t & 3) << 3;
    int bn_rw = t >> 3, bn_ck = (t & 7) << 3;

    unsigned sb = smem_u32(sm);

    int sel = lane >> 3, lr = lane & 7;
    int ar_g = lr + ((sel & 1) ? 8 : 0);
    int a_cs = (sel & 2) ? 8 : 0;
    int btr_g = lr + ((sel & 2) ? 8 : 0);
    int bt_cs = (sel & 1) ? 8 : 0;
    int bnr_g = lr + ((sel & 1) ? 8 : 0);
    int bn_cs = (sel & 2) ? 8 : 0;

    float acc[2][4][4];
#pragma unroll
    for (int mi = 0; mi < 2; mi++)
#pragma unroll
        for (int j = 0; j < 4; j++)
#pragma unroll
            for (int r = 0; r < 4; r++) acc[mi][j][r] = 0.f;

#define ISSUE(S, K0) do { \
    unsigned bb = sb + (unsigned)(S) * STAGE_B; \
    _Pragma("unroll") \
    for (int p = 0; p < 2; p++) { \
        int row = a_rw + 64 * p; \
        ll go = (ll)(m0 + row) * lda + (K0) + a_ck; \
        unsigned d = (unsigned)((row * APITCH + a_ck) * 2); \
        CP16(bb + d, Ah_ + go); \
        CP16(bb + 10240u + d, Al_ + go); \
    } \
    if (transB) { \
        ll go = (ll)(n0 + bt_rw) * ldb + (K0) + bt_ck; \
        unsigned d = (unsigned)((bt_rw * BPT + bt_ck) * 2); \
        CP16(bb + 20480u + d, Bh_ + go); \
        CP16(bb + 25600u + d, Bl_ + go); \
    } else { \
        ll go = (ll)((K0) + bn_rw) * ldb + n0 + bn_ck; \
        unsigned d = (unsigned)((bn_rw * BPN + bn_ck) * 2); \
        CP16(bb + 20480u + d, Bh_ + go); \
        CP16(bb + 25600u + d, Bl_ + go); \
    } \
    CP_COMMIT(); \
} while (0)

    int nk = K >> 5;
    ISSUE(0, 0);
    if (nk > 1) ISSUE(1, 32);

    for (int c = 0; c < nk; c++) {
        if (c + 1 < nk) CP_WAIT1(); else CP_WAIT0();
        __syncthreads();
        if (c + 2 < nk) ISSUE((c + 2) % 3, (c + 2) << 5);

        unsigned bb = sb + (unsigned)(c % 3) * STAGE_B;
        unsigned aoh = bb, aol = bb + 10240u, boh = bb + 20480u, bol = bb + 25600u;
#pragma unroll
        for (int ks = 0; ks < 2; ks++) {
            int kb = ks << 4;
            unsigned ah[2][4], al2[2][4];
#pragma unroll
            for (int mi = 0; mi < 2; mi++) {
                unsigned off = (unsigned)(((wm + 16 * mi + ar_g) * APITCH + kb + a_cs) * 2);
                LDSM4(ah[mi][0], ah[mi][1], ah[mi][2], ah[mi][3], aoh + off);
                LDSM4(al2[mi][0], al2[mi][1], al2[mi][2], al2[mi][3], aol + off);
            }
            unsigned bh[4][2], bl2[4][2];
#pragma unroll
            for (int p = 0; p < 2; p++) {
                if (transB) {
                    unsigned off = (unsigned)(((wn + 16 * p + btr_g) * BPT + kb + bt_cs) * 2);
                    LDSM4(bh[2 * p][0], bh[2 * p][1], bh[2 * p + 1][0], bh[2 * p + 1][1], boh + off);
                    LDSM4(bl2[2 * p][0], bl2[2 * p][1], bl2[2 * p + 1][0], bl2[2 * p + 1][1], bol + off);
                } else {
                    unsigned off = (unsigned)(((kb + bnr_g) * BPN + wn + 16 * p + bn_cs) * 2);
                    LDSM4T(bh[2 * p][0], bh[2 * p][1], bh[2 * p + 1][0], bh[2 * p + 1][1], boh + off);
                    LDSM4T(bl2[2 * p][0], bl2[2 * p][1], bl2[2 * p + 1][0], bl2[2 * p + 1][1], bol + off);
                }
            }
#pragma unroll
            for (int mi = 0; mi < 2; mi++)
#pragma unroll
                for (int j = 0; j < 4; j++)
                    mma_bf16(acc[mi][j], ah[mi], bh[j][0], bh[j][1]);
#pragma unroll
            for (int mi = 0; mi < 2; mi++)
#pragma unroll
                for (int j = 0; j < 4; j++)
                    mma_bf16(acc[mi][j], ah[mi], bl2[j][0], bl2[j][1]);
#pragma unroll
            for (int mi = 0; mi < 2; mi++)
#pragma unroll
                for (int j = 0; j < 4; j++)
                    mma_bf16(acc[mi][j], al2[mi], bh[j][0], bh[j][1]);
        }
    }

#pragma unroll
    for (int mi = 0; mi < 2; mi++)
#pragma unroll
        for (int j = 0; j < 4; j++) {
            int col = n0 + wn + (j << 3) + cc2;
            int row = m0 + wm + (mi << 4) + gg;
            float b0v = bias ? bias[col] : 0.f;
            float b1v = bias ? bias[col + 1] : 0.f;
            float v00 = acc[mi][j][0] + b0v, v01 = acc[mi][j][1] + b1v;
            float v10 = acc[mi][j][2] + b0v, v11 = acc[mi][j][3] + b1v;
            ll g0 = (ll)row * ldc + col + coff;
            ll g1 = (ll)(row + 8) * ldc + col + coff;
            if (ep == 0) {
                *(float2 *)(Cf + g0) = make_float2(v00, v01);
                *(float2 *)(Cf + g1) = make_float2(v10, v11);
            } else if (ep == 2) {
                float2 o0 = *(float2 *)(Cf + g0), o1 = *(float2 *)(Cf + g1);
                *(float2 *)(Cf + g0) = make_float2(o0.x + v00, o0.y + v01);
                *(float2 *)(Cf + g1) = make_float2(o1.x + v10, o1.y + v11);
            } else {
                if (ep == 1) {
                    v00 = gelu_exact(v00); v01 = gelu_exact(v01);
                    v10 = gelu_exact(v10); v11 = gelu_exact(v11);
                }
                unsigned hi, lo;
                split2(v00, v01, hi, lo);
                *(unsigned *)(Coh + g0) = hi; *(unsigned *)(Col + g0) = lo;
                split2(v10, v11, hi, lo);
                *(unsigned *)(Coh + g1) = hi; *(unsigned *)(Col + g1) = lo;
            }
        }
}

// ------------------------- flash attention ---------------------------------
// grid (4 qtiles, 64 bh), 256 thr (8 warps x 16 q-rows). Q tile 128x64.
// K/V tiles 64x64 per iteration, online softmax, split-bf16 3-term MMAs.
#define FP 72
#define FL_QH 0
#define FL_QL 9216
#define FL_KH 18432
#define FL_KL 23040
#define FL_VH 27648
#define FL_VL 32256
#define FL_BYTES 73728

__global__ __launch_bounds__(256)
void flash_kernel(const bf16 *__restrict__ qkvh, const bf16 *__restrict__ qkvl,
                  bf16 *__restrict__ yh, bf16 *__restrict__ yl)
{
    extern __shared__ __align__(16) bf16 fs[];
    int qt = blockIdx.x, bh = blockIdx.y;
    int b = bh >> 3, h = bh & 7;
    int t = threadIdx.x, lane = t & 31, w = t >> 5;
    ll rowbase = (ll)b * 512 * 1536 + h * 64;
    const bf16 *Qg = qkvh + rowbase,        *Qgl = qkvl + rowbase;
    const bf16 *Kg = qkvh + rowbase + 512,  *Kgl = qkvl + rowbase + 512;
    const bf16 *Vg = qkvh + rowbase + 1024, *Vgl = qkvl + rowbase + 1024;

    // load Q tile
    for (int i = t; i < 1024; i += 256) {
        int r = i >> 3, ck = (i & 7) << 3;
        ll go = (ll)(qt * 128 + r) * 1536 + ck;
        *(uint4 *)(fs + FL_QH + r * FP + ck) = *(const uint4 *)(Qg + go);
        *(uint4 *)(fs + FL_QL + r * FP + ck) = *(const uint4 *)(Qgl + go);
    }

    int sel = lane >> 3, lr = lane & 7;
    int a_r = lr + ((sel & 1) ? 8 : 0), a_c = (sel & 2) ? 8 : 0;
    int bt_r = lr + ((sel & 2) ? 8 : 0), bt_c = (sel & 1) ? 8 : 0;
    int bn_r = lr + ((sel & 1) ? 8 : 0), bn_c = (sel & 2) ? 8 : 0;
    unsigned sb = smem_u32(fs);
    int g = lane >> 2, q4 = lane & 3;

    float acc_o[8][4];
#pragma unroll
    for (int j = 0; j < 8; j++)
#pragma unroll
        for (int r = 0; r < 4; r++) acc_o[j][r] = 0.f;
    float m0 = -1e30f, m1 = -1e30f, l0 = 0.f, l1 = 0.f;

    for (int kt = 0; kt < 8; kt++) {
        __syncthreads();
        for (int i = t; i < 512; i += 256) {
            int r = i >> 3, ck = (i & 7) << 3;
            ll go = (ll)(kt * 64 + r) * 1536 + ck;
            *(uint4 *)(fs + FL_KH + r * FP + ck) = *(const uint4 *)(Kg + go);
            *(uint4 *)(fs + FL_KL + r * FP + ck) = *(const uint4 *)(Kgl + go);
            *(uint4 *)(fs + FL_VH + r * FP + ck) = *(const uint4 *)(Vg + go);
            *(uint4 *)(fs + FL_VL + r * FP + ck) = *(const uint4 *)(Vgl + go);
        }
        __syncthreads();

        // S = Q @ K^T (split 3-term), warp rows w*16..+15, cols 0..63
        float s[8][4];
#pragma unroll
        for (int j = 0; j < 8; j++)
#pragma unroll
            for (int r = 0; r < 4; r++) s[j][r] = 0.f;
#pragma unroll
        for (int kc = 0; kc < 4; kc++) {
            int kb = kc << 4;
            unsigned qh_[4], ql_[4];
            unsigned qoff = (unsigned)(((w * 16 + a_r) * FP + kb + a_c) * 2);
            LDSM4(qh_[0], qh_[1], qh_[2], qh_[3], sb + FL_QH * 2 + qoff);
            LDSM4(ql_[0], ql_[1], ql_[2], ql_[3], sb + FL_QL * 2 + qoff);
            unsigned kh_[8][2], kl_[8][2];
#pragma unroll
            for (int p = 0; p < 4; p++) {
                unsigned koff = (unsigned)(((p * 16 + bt_r) * FP + kb + bt_c) * 2);
                LDSM4(kh_[2 * p][0], kh_[2 * p][1], kh_[2 * p + 1][0], kh_[2 * p + 1][1],
                      sb + FL_KH * 2 + koff);
                LDSM4(kl_[2 * p][0], kl_[2 * p][1], kl_[2 * p + 1][0], kl_[2 * p + 1][1],
                      sb + FL_KL * 2 + koff);
            }
#pragma unroll
            for (int j = 0; j < 8; j++) mma_bf16(s[j], qh_, kh_[j][0], kh_[j][1]);
#pragma unroll
            for (int j = 0; j < 8; j++) mma_bf16(s[j], qh_, kl_[j][0], kl_[j][1]);
#pragma unroll
            for (int j = 0; j < 8; j++) mma_bf16(s[j], ql_, kh_[j][0], kh_[j][1]);
        }

        // online softmax (rows g and g+8)
        float tm0 = -1e30f, tm1 = -1e30f;
#pragma unroll
        for (int j = 0; j < 8; j++) {
            s[j][0] *= 0.125f; s[j][1] *= 0.125f; s[j][2] *= 0.125f; s[j][3] *= 0.125f;
            tm0 = fmaxf(tm0, fmaxf(s[j][0], s[j][1]));
            tm1 = fmaxf(tm1, fmaxf(s[j][2], s[j][3]));
        }
        tm0 = fmaxf(tm0, __shfl_xor_sync(0xffffffffu, tm0, 1));
        tm0 = fmaxf(tm0, __shfl_xor_sync(0xffffffffu, tm0, 2));
        tm1 = fmaxf(tm1, __shfl_xor_sync(0xffffffffu, tm1, 1));
        tm1 = fmaxf(tm1, __shfl_xor_sync(0xffffffffu, tm1, 2));
        float nm0 = fmaxf(m0, tm0), nm1 = fmaxf(m1, tm1);
        float al0 = __expf(m0 - nm0), al1 = __expf(m1 - nm1);
        m0 = nm0; m1 = nm1;
        float sum0 = 0.f, sum1 = 0.f;
#pragma unroll
        for (int j = 0; j < 8; j++) {
            s[j][0] = __expf(s[j][0] - nm0); sum0 += s[j][0];
            s[j][1] = __expf(s[j][1] - nm0); sum0 += s[j][1];
            s[j][2] = __expf(s[j][2] - nm1); sum1 += s[j][2];
            s[j][3] = __expf(s[j][3] - nm1); sum1 += s[j][3];
        }
        sum0 += __shfl_xor_sync(0xffffffffu, sum0, 1);
        sum0 += __shfl_xor_sync(0xffffffffu, sum0, 2);
        sum1 += __shfl_xor_sync(0xffffffffu, sum1, 1);
        sum1 += __shfl_xor_sync(0xffffffffu, sum1, 2);
        l0 = l0 * al0 + sum0; l1 = l1 * al1 + sum1;
#pragma unroll
        for (int j = 0; j < 8; j++) {
            acc_o[j][0] *= al0; acc_o[j][1] *= al0;
            acc_o[j][2] *= al1; acc_o[j][3] *= al1;
        }

        // O += P @ V (split 3-term); P frags built from s (C-frag -> A-frag)
#pragma unroll
        for (int kc = 0; kc < 4; kc++) {
            unsigned pah[4], pal[4];
            split2(s[2 * kc][0],     s[2 * kc][1],     pah[0], pal[0]);
            split2(s[2 * kc][2],     s[2 * kc][3],     pah[1], pal[1]);
            split2(s[2 * kc + 1][0], s[2 * kc + 1][1], pah[2], pal[2]);
            split2(s[2 * kc + 1][2], s[2 * kc + 1][3], pah[3], pal[3]);
            unsigned vh_[8][2], vl_[8][2];
#pragma unroll
            for (int p = 0; p < 4; p++) {
                unsigned voff = (unsigned)((((kc << 4) + bn_r) * FP + p * 16 + bn_c) * 2);
                LDSM4T(vh_[2 * p][0], vh_[2 * p][1], vh_[2 * p + 1][0], vh_[2 * p + 1][1],
                       sb + FL_VH * 2 + voff);
                LDSM4T(vl_[2 * p][0], vl_[2 * p][1], vl_[2 * p + 1][0], vl_[2 * p + 1][1],
                       sb + FL_VL * 2 + voff);
            }
#pragma unroll
            for (int j = 0; j < 8; j++) mma_bf16(acc_o[j], pah, vh_[j][0], vh_[j][1]);
#pragma unroll
            for (int j = 0; j < 8; j++) mma_bf16(acc_o[j], pah, vl_[j][0], vl_[j][1]);
#pragma unroll
            for (int j = 0; j < 8; j++) mma_bf16(acc_o[j], pal, vh_[j][0], vh_[j][1]);
        }
    }

    // epilogue: O /= l, split-store into y
    float i0 = 1.f / l0, i1 = 1.f / l1;
    int r0 = qt * 128 + w * 16 + g;
#pragma unroll
    for (int j = 0; j < 8; j++) {
        int col = h * 64 + j * 8 + 2 * q4;
        unsigned hi, lo;
        ll g0 = ((ll)(b * 512 + r0)) * 512 + col;
        ll g1 = ((ll)(b * 512 + r0 + 8)) * 512 + col;
        split2(acc_o[j][0] * i0, acc_o[j][1] * i0, hi, lo);
        *(unsigned *)(yh + g0) = hi; *(unsigned *)(yl + g0) = lo;
        split2(acc_o[j][2] * i1, acc_o[j][3] * i1, hi, lo);
        *(unsigned *)(yh + g1) = hi; *(unsigned *)(yl + g1) = lo;
    }
}

// ------------------------- merged one-time weight transpose+split ----------
struct WA {
    const float *src[13];
    ll doff[13];
    int K[13], N[13];
};

__global__ __launch_bounds__(256)
void wconv_all(WA a, bf16 *__restrict__ wh, bf16 *__restrict__ wl)
{
    int m = blockIdx.z;
    int K = a.K[m], N = a.N[m];
    int bx = blockIdx.x * 32, by = blockIdx.y * 32;
    if (bx >= N || by >= K) return;
    const float *W = a.src[m];
    bf16 *th = wh + a.doff[m], *tl = wl + a.doff[m];
    __shared__ float tile[32][33];
    int tx = threadIdx.x & 31, ty = threadIdx.x >> 5;
#pragma unroll
    for (int j = 0; j < 4; j++) {
        int kk = ty + j * 8;
        tile[kk][tx] = W[(ll)(by + kk) * N + bx + tx];
    }
    __syncthreads();
#pragma unroll
    for (int j = 0; j < 4; j++) {
        int nn = ty + j * 8;
        float v = tile[tx][nn];
        bf16 h, l;
        split1(v, h, l);
        ll o = (ll)(bx + nn) * K + by + tx;
        th[o] = h; tl[o] = l;
    }
}

__global__ void bcat_kernel(const float *__restrict__ bq, const float *__restrict__ bk,
                            const float *__restrict__ bv, float *__restrict__ dst)
{
    int i = blockIdx.x * 256 + threadIdx.x;
    if (i >= LL * 3 * CC) return;
    int l = i / (3 * CC), c = i % (3 * CC);
    float v;
    if (c < CC) v = bq[l * CC + c];
    else if (c < 2 * CC) v = bk[l * CC + c - CC];
    else v = bv[l * CC + c - 2 * CC];
    dst[i] = v;
}

// ------------------------- element kernels ---------------------------------
__global__ void embed_kernel(const int *__restrict__ idx, const float *__restrict__ tok,
                             const float *__restrict__ pos, float *__restrict__ x)
{
    int i = blockIdx.x * 256 + threadIdx.x;
    if (i >= MM * CC) return;
    int c = i & (CC - 1);
    int bt = i >> 9;
    int tp = bt & (TT - 1);
    x[i] = tok[idx[bt] * CC + c] + pos[tp * CC + c];
}

__global__ __launch_bounds__(256)
void ln_kernel(const float *__restrict__ x, bf16 *__restrict__ oh, bf16 *__restrict__ ol,
               const float *__restrict__ gam, const float *__restrict__ bet)
{
    __shared__ float red[256];
    int row = blockIdx.x, t = threadIdx.x;
    const float *xr = x + (ll)row * CC;
    float a = xr[t], b = xr[t + 256];
    red[t] = a + b;
    __syncthreads();
    for (int off = 128; off > 0; off >>= 1) {
        if (t < off) red[t] += red[t + off];
        __syncthreads();
    }
    float mu = red[0] * (1.0f / CC);
    __syncthreads();
    float da = a - mu, db = b - mu;
    red[t] = da * da + db * db;
    __syncthreads();
    for (int off = 128; off > 0; off >>= 1) {
        if (t < off) red[t] += red[t + off];
        __syncthreads();
    }
    float rstd = rsqrtf(red[0] * (1.0f / CC) + 1e-5f);
    float r0 = da * rstd * gam[t] + bet[t];
    float r1 = db * rstd * gam[t + 256] + bet[t + 256];
    bf16 h, l;
    ll o = (ll)row * CC;
    split1(r0, h, l); oh[o + t] = h;       ol[o + t] = l;
    split1(r1, h, l); oh[o + t + 256] = h; ol[o + t + 256] = l;
}

// ------------------------- host orchestration ------------------------------
static void run_hm(const bf16 *Ah, const bf16 *Al, int lda, ll sA0, ll sA1,
                   const bf16 *Bh, const bf16 *Bl, int ldb, ll sB0, ll sB1,
                   float *Cf, bf16 *Coh, bf16 *Col, int ldc, ll sC0, ll sC1,
                   int Mr, int Nc, int K, int zdiv, int Z,
                   const float *bias, int transB, int ep)
{
    dim3 g(Nc / 64, Mr / 128, Z);
    gemm_hmma<<<g, 256, SMEM_BYTES>>>(Ah, Al, lda, sA0, sA1, Bh, Bl, ldb, sB0, sB1,
                                      Cf, Coh, Col, ldc, sC0, sC1, K, zdiv, bias, transB, ep);
}

extern "C" void kernel_launch(void *const *d_in, const int *in_sizes, int n_in,
                              void *d_out, int out_size)
{
    (void)in_sizes; (void)n_in; (void)out_size;
    const int   *idx  = (const int *)d_in[0];
    const float *tok  = (const float *)d_in[1];
    const float *pos  = (const float *)d_in[2];
    const float *ln1g = (const float *)d_in[3];
    const float *ln1b = (const float *)d_in[4];
    const float *Wq   = (const float *)d_in[5];
    const float *bq   = (const float *)d_in[6];
    const float *Wk   = (const float *)d_in[7];
    const float *bk   = (const float *)d_in[8];
    const float *Wv   = (const float *)d_in[9];
    const float *bv   = (const float *)d_in[10];
    const float *Wp   = (const float *)d_in[11];
    const float *bp   = (const float *)d_in[12];
    const float *ln2g = (const float *)d_in[13];
    const float *ln2b = (const float *)d_in[14];
    const float *W1   = (const float *)d_in[15];
    const float *b1   = (const float *)d_in[16];
    const float *W2   = (const float *)d_in[17];
    const float *b2   = (const float *)d_in[18];
    const float *lnfg = (const float *)d_in[19];
    const float *lnfb = (const float *)d_in[20];
    const float *Wh   = (const float *)d_in[21];
    float *out = (float *)d_out;

    static int attr_set = 0;
    if (!attr_set) {
        cudaFuncSetAttribute(gemm_hmma, cudaFuncAttributeMaxDynamicSharedMemorySize, SMEM_BYTES);
        cudaFuncSetAttribute(flash_kernel, cudaFuncAttributeMaxDynamicSharedMemorySize, FL_BYTES);
        attr_set = 1;
    }

    float *x, *bqkv;
    bf16 *xnh, *xnl, *qkvh, *qkvl, *yh, *yl, *hh, *hl, *wh, *wl;
    cudaGetSymbolAddress((void **)&x, g_x);
    cudaGetSymbolAddress((void **)&bqkv, g_bqkv);
    cudaGetSymbolAddress((void **)&xnh, g_xnh);   cudaGetSymbolAddress((void **)&xnl, g_xnl);
    cudaGetSymbolAddress((void **)&qkvh, g_qkvh); cudaGetSymbolAddress((void **)&qkvl, g_qkvl);
    cudaGetSymbolAddress((void **)&yh, g_yh);     cudaGetSymbolAddress((void **)&yl, g_yl);
    cudaGetSymbolAddress((void **)&hh, g_hh);     cudaGetSymbolAddress((void **)&hl, g_hl);
    cudaGetSymbolAddress((void **)&wh, g_wh);     cudaGetSymbolAddress((void **)&wl, g_wl);

    // merged one-time weight transpose+split (single launch)
    WA wa;
    for (int l = 0; l < LL; l++) {
        ll wb = (ll)l * WOFF_L;
        int base = l * 6;
        wa.src[base + 0] = Wq + (ll)l * CC * CC; wa.doff[base + 0] = wb;           wa.K[base + 0] = CC; wa.N[base + 0] = CC;
        wa.src[base + 1] = Wk + (ll)l * CC * CC; wa.doff[base + 1] = wb + 262144;  wa.K[base + 1] = CC; wa.N[base + 1] = CC;
        wa.src[base + 2] = Wv + (ll)l * CC * CC; wa.doff[base + 2] = wb + 524288;  wa.K[base + 2] = CC; wa.N[base + 2] = CC;
        wa.src[base + 3] = Wp + (ll)l * CC * CC; wa.doff[base + 3] = wb + WOFF_P;  wa.K[base + 3] = CC; wa.N[base + 3] = CC;
        wa.src[base + 4] = W1 + (ll)l * CC * FF; wa.doff[base + 4] = wb + WOFF_1;  wa.K[base + 4] = CC; wa.N[base + 4] = FF;
        wa.src[base + 5] = W2 + (ll)l * FF * CC; wa.doff[base + 5] = wb + WOFF_2;  wa.K[base + 5] = FF; wa.N[base + 5] = CC;
    }
    wa.src[12] = Wh; wa.doff[12] = WOFF_HD; wa.K[12] = CC; wa.N[12] = CC;
    wconv_all<<<dim3(64, 64, 13), 256>>>(wa, wh, wl);
    bcat_kernel<<<(LL * 3 * CC + 255) / 256, 256>>>(bq, bk, bv, bqkv);
    embed_kernel<<<(MM * CC + 255) / 256, 256>>>(idx, tok, pos, x);

    const ll QKVROW = 3 * CC;

    for (int s = 0; s < STEPS; s++) {
        for (int l = 0; l < LL; l++) {
            ll wb = (ll)l * WOFF_L;
            ln_kernel<<<MM, 256>>>(x, xnh, xnl, ln1g + l * CC, ln1b + l * CC);
            // fused QKV
            run_hm(xnh, xnl, CC, 0, 0, wh + wb + WOFF_QKV, wl + wb + WOFF_QKV, CC, 0, 0,
                   nullptr, qkvh, qkvl, (int)QKVROW, 0, 0,
                   MM, (int)QKVROW, CC, 1, 1, bqkv + l * QKVROW, 1, 3);
            // flash attention: qkv -> y (split)
            flash_kernel<<<dim3(4, 64), 256, FL_BYTES>>>(qkvh, qkvl, yh, yl);
            // x += y @ Wp + bp
            run_hm(yh, yl, CC, 0, 0, wh + wb + WOFF_P, wl + wb + WOFF_P, CC, 0, 0,
                   x, nullptr, nullptr, CC, 0, 0, MM, CC, CC, 1, 1, bp + l * CC, 1, 2);
            ln_kernel<<<MM, 256>>>(x, xnh, xnl, ln2g + l * CC, ln2b + l * CC);
            // h = gelu(xn @ W1 + b1)
            run_hm(xnh, xnl, CC, 0, 0, wh + wb + WOFF_1, wl + wb + WOFF_1, CC, 0, 0,
                   nullptr, hh, hl, FF, 0, 0, MM, FF, CC, 1, 1, b1 + l * FF, 1, 1);
            // x += h @ W2 + b2
            run_hm(hh, hl, FF, 0, 0, wh + wb + WOFF_2, wl + wb + WOFF_2, FF, 0, 0,
                   x, nullptr, nullptr, CC, 0, 0, MM, CC, FF, 1, 1, b2 + l * CC, 1, 2);
        }
    }
    ln_kernel<<<MM, 256>>>(x, xnh, xnl, lnfg, lnfb);
    run_hm(xnh, xnl, CC, 0, 0, wh + WOFF_HD, wl + WOFF_HD, CC, 0, 0,
           out, nullptr, nullptr, CC, 0, 0, MM, CC, CC, 1, 1, nullptr, 1, 0);
}

// round 12
// speedup vs baseline: 1.1642x; 1.0312x over previous
#include <cuda_runtime.h>
#include <cuda_bf16.h>
#include <math.h>
#include <stdint.h>

#define BQ 8
#define TT 512
#define CC 512
#define HH 8
#define DHD 64
#define LL 2
#define MM (BQ * TT)
#define FF (4 * CC)
#define STEPS 4
typedef __nv_bfloat16 bf16;
typedef long long ll;

// ------------------------- scratch (__device__ globals) --------------------
__device__ __align__(16) float g_x[MM * CC];
__device__ __align__(16) float g_bqkv[LL * 3 * CC];
__device__ __align__(16) bf16 g_xnh[MM * CC], g_xnl[MM * CC];
__device__ __align__(16) bf16 g_qkvh[MM * 3 * CC], g_qkvl[MM * 3 * CC];
__device__ __align__(16) bf16 g_yh[MM * CC],  g_yl[MM * CC];
__device__ __align__(16) bf16 g_hh[MM * FF],  g_hl[MM * FF];
#define NW 6553600
__device__ __align__(16) bf16 g_wh[NW], g_wl[NW];
#define WOFF_L   3145728
#define WOFF_QKV 0
#define WOFF_P   786432
#define WOFF_1   1048576
#define WOFF_2   2097152
#define WOFF_HD  6291456

// ------------------------- helpers -----------------------------------------
__device__ __forceinline__ void split1(float v, bf16 &h, bf16 &l) {
    h = __float2bfloat16(v);
    l = __float2bfloat16(v - __bfloat162float(h));
}
__device__ __forceinline__ void split2(float x, float y, unsigned &hi, unsigned &lo) {
    bf16 hx, lx, hy, ly;
    split1(x, hx, lx); split1(y, hy, ly);
    hi = ((unsigned)__bfloat16_as_ushort(hy) << 16) | (unsigned)__bfloat16_as_ushort(hx);
    lo = ((unsigned)__bfloat16_as_ushort(ly) << 16) | (unsigned)__bfloat16_as_ushort(lx);
}
__device__ __forceinline__ unsigned smem_u32(const void *p) {
    return (unsigned)__cvta_generic_to_shared(p);
}
__device__ __forceinline__ float gelu_exact(float x) {
    return 0.5f * x * (1.0f + erff(x * 0.7071067811865476f));
}
__device__ __forceinline__ void mma_bf16(float *d, const unsigned *a, unsigned b0, unsigned b1) {
    asm volatile(
        "mma.sync.aligned.m16n8k16.row.col.f32.bf16.bf16.f32 "
        "{%0,%1,%2,%3}, {%4,%5,%6,%7}, {%8,%9}, {%0,%1,%2,%3};\n"
        : "+f"(d[0]), "+f"(d[1]), "+f"(d[2]), "+f"(d[3])
        : "r"(a[0]), "r"(a[1]), "r"(a[2]), "r"(a[3]), "r"(b0), "r"(b1));
}
#define LDSM4(R0, R1, R2, R3, ADDR) \
    asm volatile("ldmatrix.sync.aligned.m8n8.x4.shared.b16 {%0,%1,%2,%3}, [%4];" \
                 : "=r"(R0), "=r"(R1), "=r"(R2), "=r"(R3) : "r"(ADDR))
#define LDSM4T(R0, R1, R2, R3, ADDR) \
    asm volatile("ldmatrix.sync.aligned.m8n8.x4.trans.shared.b16 {%0,%1,%2,%3}, [%4];" \
                 : "=r"(R0), "=r"(R1), "=r"(R2), "=r"(R3) : "r"(ADDR))
#define CP16(dst, src) \
    asm volatile("cp.async.cg.shared.global [%0], [%1], 16;" :: "r"(dst), "l"(src))
#define CP_COMMIT() asm volatile("cp.async.commit_group;" ::: "memory")
#define CP_WAIT1()  asm volatile("cp.async.wait_group 1;" ::: "memory")
#define CP_WAIT0()  asm volatile("cp.async.wait_group 0;" ::: "memory")

// ------------------------- HMMA GEMM (unchanged core) ----------------------
#define APITCH 40
#define BPT    40
#define BPN    72
#define STAGE_B 30720u
#define SMEM_BYTES (3 * 30720)

__global__ __launch_bounds__(256, 2)
void gemm_hmma(const bf16 *__restrict__ Ah_, const bf16 *__restrict__ Al_, int lda,
               ll sA0, ll sA1,
               const bf16 *__restrict__ Bh_, const bf16 *__restrict__ Bl_, int ldb,
               ll sB0, ll sB1,
               float *__restrict__ Cf, bf16 *__restrict__ Coh, bf16 *__restrict__ Col,
               int ldc, ll sC0, ll sC1,
               int K, int zdiv, const float *__restrict__ bias, int transB, int ep)
{
    extern __shared__ __align__(16) bf16 sm[];
    int z = blockIdx.z;
    ll zo0 = z / zdiv, zo1 = z % zdiv;
    Ah_ += zo0 * sA0 + zo1 * sA1;  Al_ += zo0 * sA0 + zo1 * sA1;
    Bh_ += zo0 * sB0 + zo1 * sB1;  Bl_ += zo0 * sB0 + zo1 * sB1;
    ll coff = zo0 * sC0 + zo1 * sC1;
    int n0 = blockIdx.x * 64, m0 = blockIdx.y * 128;

    int t = threadIdx.x, lane = t & 31, warp = t >> 5;
    int wm = (warp & 3) << 5, wn = (warp >> 2) << 5;
    int gg = lane >> 2, cc2 = (lane & 3) << 1;

    int a_ck = (t & 3) << 3, a_rw = t >> 2;
    int bt_rw = t >> 2, bt_ck = (t & 3) << 3;
    int bn_rw = t >> 3, bn_ck = (t & 7) << 3;

    unsigned sb = smem_u32(sm);

    int sel = lane >> 3, lr = lane & 7;
    int ar_g = lr + ((sel & 1) ? 8 : 0);
    int a_cs = (sel & 2) ? 8 : 0;
    int btr_g = lr + ((sel & 2) ? 8 : 0);
    int bt_cs = (sel & 1) ? 8 : 0;
    int bnr_g = lr + ((sel & 1) ? 8 : 0);
    int bn_cs = (sel & 2) ? 8 : 0;

    float acc[2][4][4];
#pragma unroll
    for (int mi = 0; mi < 2; mi++)
#pragma unroll
        for (int j = 0; j < 4; j++)
#pragma unroll
            for (int r = 0; r < 4; r++) acc[mi][j][r] = 0.f;

#define ISSUE(S, K0) do { \
    unsigned bb = sb + (unsigned)(S) * STAGE_B; \
    _Pragma("unroll") \
    for (int p = 0; p < 2; p++) { \
        int row = a_rw + 64 * p; \
        ll go = (ll)(m0 + row) * lda + (K0) + a_ck; \
        unsigned d = (unsigned)((row * APITCH + a_ck) * 2); \
        CP16(bb + d, Ah_ + go); \
        CP16(bb + 10240u + d, Al_ + go); \
    } \
    if (transB) { \
        ll go = (ll)(n0 + bt_rw) * ldb + (K0) + bt_ck; \
        unsigned d = (unsigned)((bt_rw * BPT + bt_ck) * 2); \
        CP16(bb + 20480u + d, Bh_ + go); \
        CP16(bb + 25600u + d, Bl_ + go); \
    } else { \
        ll go = (ll)((K0) + bn_rw) * ldb + n0 + bn_ck; \
        unsigned d = (unsigned)((bn_rw * BPN + bn_ck) * 2); \
        CP16(bb + 20480u + d, Bh_ + go); \
        CP16(bb + 25600u + d, Bl_ + go); \
    } \
    CP_COMMIT(); \
} while (0)

    int nk = K >> 5;
    ISSUE(0, 0);
    if (nk > 1) ISSUE(1, 32);

    for (int c = 0; c < nk; c++) {
        if (c + 1 < nk) CP_WAIT1(); else CP_WAIT0();
        __syncthreads();
        if (c + 2 < nk) ISSUE((c + 2) % 3, (c + 2) << 5);

        unsigned bb = sb + (unsigned)(c % 3) * STAGE_B;
        unsigned aoh = bb, aol = bb + 10240u, boh = bb + 20480u, bol = bb + 25600u;
#pragma unroll
        for (int ks = 0; ks < 2; ks++) {
            int kb = ks << 4;
            unsigned ah[2][4], al2[2][4];
#pragma unroll
            for (int mi = 0; mi < 2; mi++) {
                unsigned off = (unsigned)(((wm + 16 * mi + ar_g) * APITCH + kb + a_cs) * 2);
                LDSM4(ah[mi][0], ah[mi][1], ah[mi][2], ah[mi][3], aoh + off);
                LDSM4(al2[mi][0], al2[mi][1], al2[mi][2], al2[mi][3], aol + off);
            }
            unsigned bh[4][2], bl2[4][2];
#pragma unroll
            for (int p = 0; p < 2; p++) {
                if (transB) {
                    unsigned off = (unsigned)(((wn + 16 * p + btr_g) * BPT + kb + bt_cs) * 2);
                    LDSM4(bh[2 * p][0], bh[2 * p][1], bh[2 * p + 1][0], bh[2 * p + 1][1], boh + off);
                    LDSM4(bl2[2 * p][0], bl2[2 * p][1], bl2[2 * p + 1][0], bl2[2 * p + 1][1], bol + off);
                } else {
                    unsigned off = (unsigned)(((kb + bnr_g) * BPN + wn + 16 * p + bn_cs) * 2);
                    LDSM4T(bh[2 * p][0], bh[2 * p][1], bh[2 * p + 1][0], bh[2 * p + 1][1], boh + off);
                    LDSM4T(bl2[2 * p][0], bl2[2 * p][1], bl2[2 * p + 1][0], bl2[2 * p + 1][1], bol + off);
                }
            }
#pragma unroll
            for (int mi = 0; mi < 2; mi++)
#pragma unroll
                for (int j = 0; j < 4; j++)
                    mma_bf16(acc[mi][j], ah[mi], bh[j][0], bh[j][1]);
#pragma unroll
            for (int mi = 0; mi < 2; mi++)
#pragma unroll
                for (int j = 0; j < 4; j++)
                    mma_bf16(acc[mi][j], ah[mi], bl2[j][0], bl2[j][1]);
#pragma unroll
            for (int mi = 0; mi < 2; mi++)
#pragma unroll
                for (int j = 0; j < 4; j++)
                    mma_bf16(acc[mi][j], al2[mi], bh[j][0], bh[j][1]);
        }
    }

#pragma unroll
    for (int mi = 0; mi < 2; mi++)
#pragma unroll
        for (int j = 0; j < 4; j++) {
            int col = n0 + wn + (j << 3) + cc2;
            int row = m0 + wm + (mi << 4) + gg;
            float b0v = bias ? bias[col] : 0.f;
            float b1v = bias ? bias[col + 1] : 0.f;
            float v00 = acc[mi][j][0] + b0v, v01 = acc[mi][j][1] + b1v;
            float v10 = acc[mi][j][2] + b0v, v11 = acc[mi][j][3] + b1v;
            ll g0 = (ll)row * ldc + col + coff;
            ll g1 = (ll)(row + 8) * ldc + col + coff;
            if (ep == 0) {
                *(float2 *)(Cf + g0) = make_float2(v00, v01);
                *(float2 *)(Cf + g1) = make_float2(v10, v11);
            } else if (ep == 2) {
                float2 o0 = *(float2 *)(Cf + g0), o1 = *(float2 *)(Cf + g1);
                *(float2 *)(Cf + g0) = make_float2(o0.x + v00, o0.y + v01);
                *(float2 *)(Cf + g1) = make_float2(o1.x + v10, o1.y + v11);
            } else {
                if (ep == 1) {
                    v00 = gelu_exact(v00); v01 = gelu_exact(v01);
                    v10 = gelu_exact(v10); v11 = gelu_exact(v11);
                }
                unsigned hi, lo;
                split2(v00, v01, hi, lo);
                *(unsigned *)(Coh + g0) = hi; *(unsigned *)(Col + g0) = lo;
                split2(v10, v11, hi, lo);
                *(unsigned *)(Coh + g1) = hi; *(unsigned *)(Col + g1) = lo;
            }
        }
}

// ------------------------- flash attention (unchanged) ---------------------
#define FP 72
#define FL_QH 0
#define FL_QL 9216
#define FL_KH 18432
#define FL_KL 23040
#define FL_VH 27648
#define FL_VL 32256
#define FL_BYTES 73728

__global__ __launch_bounds__(256)
void flash_kernel(const bf16 *__restrict__ qkvh, const bf16 *__restrict__ qkvl,
                  bf16 *__restrict__ yh, bf16 *__restrict__ yl)
{
    extern __shared__ __align__(16) bf16 fs[];
    int qt = blockIdx.x, bh = blockIdx.y;
    int b = bh >> 3, h = bh & 7;
    int t = threadIdx.x, lane = t & 31, w = t >> 5;
    ll rowbase = (ll)b * 512 * 1536 + h * 64;
    const bf16 *Qg = qkvh + rowbase,        *Qgl = qkvl + rowbase;
    const bf16 *Kg = qkvh + rowbase + 512,  *Kgl = qkvl + rowbase + 512;
    const bf16 *Vg = qkvh + rowbase + 1024, *Vgl = qkvl + rowbase + 1024;

    for (int i = t; i < 1024; i += 256) {
        int r = i >> 3, ck = (i & 7) << 3;
        ll go = (ll)(qt * 128 + r) * 1536 + ck;
        *(uint4 *)(fs + FL_QH + r * FP + ck) = *(const uint4 *)(Qg + go);
        *(uint4 *)(fs + FL_QL + r * FP + ck) = *(const uint4 *)(Qgl + go);
    }

    int sel = lane >> 3, lr = lane & 7;
    int a_r = lr + ((sel & 1) ? 8 : 0), a_c = (sel & 2) ? 8 : 0;
    int bt_r = lr + ((sel & 2) ? 8 : 0), bt_c = (sel & 1) ? 8 : 0;
    int bn_r = lr + ((sel & 1) ? 8 : 0), bn_c = (sel & 2) ? 8 : 0;
    unsigned sb = smem_u32(fs);
    int g = lane >> 2, q4 = lane & 3;

    float acc_o[8][4];
#pragma unroll
    for (int j = 0; j < 8; j++)
#pragma unroll
        for (int r = 0; r < 4; r++) acc_o[j][r] = 0.f;
    float m0 = -1e30f, m1 = -1e30f, l0 = 0.f, l1 = 0.f;

    for (int kt = 0; kt < 8; kt++) {
        __syncthreads();
        for (int i = t; i < 512; i += 256) {
            int r = i >> 3, ck = (i & 7) << 3;
            ll go = (ll)(kt * 64 + r) * 1536 + ck;
            *(uint4 *)(fs + FL_KH + r * FP + ck) = *(const uint4 *)(Kg + go);
            *(uint4 *)(fs + FL_KL + r * FP + ck) = *(const uint4 *)(Kgl + go);
            *(uint4 *)(fs + FL_VH + r * FP + ck) = *(const uint4 *)(Vg + go);
            *(uint4 *)(fs + FL_VL + r * FP + ck) = *(const uint4 *)(Vgl + go);
        }
        __syncthreads();

        float s[8][4];
#pragma unroll
        for (int j = 0; j < 8; j++)
#pragma unroll
            for (int r = 0; r < 4; r++) s[j][r] = 0.f;
#pragma unroll
        for (int kc = 0; kc < 4; kc++) {
            int kb = kc << 4;
            unsigned qh_[4], ql_[4];
            unsigned qoff = (unsigned)(((w * 16 + a_r) * FP + kb + a_c) * 2);
            LDSM4(qh_[0], qh_[1], qh_[2], qh_[3], sb + FL_QH * 2 + qoff);
            LDSM4(ql_[0], ql_[1], ql_[2], ql_[3], sb + FL_QL * 2 + qoff);
            unsigned kh_[8][2], kl_[8][2];
#pragma unroll
            for (int p = 0; p < 4; p++) {
                unsigned koff = (unsigned)(((p * 16 + bt_r) * FP + kb + bt_c) * 2);
                LDSM4(kh_[2 * p][0], kh_[2 * p][1], kh_[2 * p + 1][0], kh_[2 * p + 1][1],
                      sb + FL_KH * 2 + koff);
                LDSM4(kl_[2 * p][0], kl_[2 * p][1], kl_[2 * p + 1][0], kl_[2 * p + 1][1],
                      sb + FL_KL * 2 + koff);
            }
#pragma unroll
            for (int j = 0; j < 8; j++) mma_bf16(s[j], qh_, kh_[j][0], kh_[j][1]);
#pragma unroll
            for (int j = 0; j < 8; j++) mma_bf16(s[j], qh_, kl_[j][0], kl_[j][1]);
#pragma unroll
            for (int j = 0; j < 8; j++) mma_bf16(s[j], ql_, kh_[j][0], kh_[j][1]);
        }

        float tm0 = -1e30f, tm1 = -1e30f;
#pragma unroll
        for (int j = 0; j < 8; j++) {
            s[j][0] *= 0.125f; s[j][1] *= 0.125f; s[j][2] *= 0.125f; s[j][3] *= 0.125f;
            tm0 = fmaxf(tm0, fmaxf(s[j][0], s[j][1]));
            tm1 = fmaxf(tm1, fmaxf(s[j][2], s[j][3]));
        }
        tm0 = fmaxf(tm0, __shfl_xor_sync(0xffffffffu, tm0, 1));
        tm0 = fmaxf(tm0, __shfl_xor_sync(0xffffffffu, tm0, 2));
        tm1 = fmaxf(tm1, __shfl_xor_sync(0xffffffffu, tm1, 1));
        tm1 = fmaxf(tm1, __shfl_xor_sync(0xffffffffu, tm1, 2));
        float nm0 = fmaxf(m0, tm0), nm1 = fmaxf(m1, tm1);
        float al0 = __expf(m0 - nm0), al1 = __expf(m1 - nm1);
        m0 = nm0; m1 = nm1;
        float sum0 = 0.f, sum1 = 0.f;
#pragma unroll
        for (int j = 0; j < 8; j++) {
            s[j][0] = __expf(s[j][0] - nm0); sum0 += s[j][0];
            s[j][1] = __expf(s[j][1] - nm0); sum0 += s[j][1];
            s[j][2] = __expf(s[j][2] - nm1); sum1 += s[j][2];
            s[j][3] = __expf(s[j][3] - nm1); sum1 += s[j][3];
        }
        sum0 += __shfl_xor_sync(0xffffffffu, sum0, 1);
        sum0 += __shfl_xor_sync(0xffffffffu, sum0, 2);
        sum1 += __shfl_xor_sync(0xffffffffu, sum1, 1);
        sum1 += __shfl_xor_sync(0xffffffffu, sum1, 2);
        l0 = l0 * al0 + sum0; l1 = l1 * al1 + sum1;
#pragma unroll
        for (int j = 0; j < 8; j++) {
            acc_o[j][0] *= al0; acc_o[j][1] *= al0;
            acc_o[j][2] *= al1; acc_o[j][3] *= al1;
        }

#pragma unroll
        for (int kc = 0; kc < 4; kc++) {
            unsigned pah[4], pal[4];
            split2(s[2 * kc][0],     s[2 * kc][1],     pah[0], pal[0]);
            split2(s[2 * kc][2],     s[2 * kc][3],     pah[1], pal[1]);
            split2(s[2 * kc + 1][0], s[2 * kc + 1][1], pah[2], pal[2]);
            split2(s[2 * kc + 1][2], s[2 * kc + 1][3], pah[3], pal[3]);
            unsigned vh_[8][2], vl_[8][2];
#pragma unroll
            for (int p = 0; p < 4; p++) {
                unsigned voff = (unsigned)((((kc << 4) + bn_r) * FP + p * 16 + bn_c) * 2);
                LDSM4T(vh_[2 * p][0], vh_[2 * p][1], vh_[2 * p + 1][0], vh_[2 * p + 1][1],
                       sb + FL_VH * 2 + voff);
                LDSM4T(vl_[2 * p][0], vl_[2 * p][1], vl_[2 * p + 1][0], vl_[2 * p + 1][1],
                       sb + FL_VL * 2 + voff);
            }
#pragma unroll
            for (int j = 0; j < 8; j++) mma_bf16(acc_o[j], pah, vh_[j][0], vh_[j][1]);
#pragma unroll
            for (int j = 0; j < 8; j++) mma_bf16(acc_o[j], pah, vl_[j][0], vl_[j][1]);
#pragma unroll
            for (int j = 0; j < 8; j++) mma_bf16(acc_o[j], pal, vh_[j][0], vh_[j][1]);
        }
    }

    float i0 = 1.f / l0, i1 = 1.f / l1;
    int r0 = qt * 128 + w * 16 + g;
#pragma unroll
    for (int j = 0; j < 8; j++) {
        int col = h * 64 + j * 8 + 2 * q4;
        unsigned hi, lo;
        ll g0 = ((ll)(b * 512 + r0)) * 512 + col;
        ll g1 = ((ll)(b * 512 + r0 + 8)) * 512 + col;
        split2(acc_o[j][0] * i0, acc_o[j][1] * i0, hi, lo);
        *(unsigned *)(yh + g0) = hi; *(unsigned *)(yl + g0) = lo;
        split2(acc_o[j][2] * i1, acc_o[j][3] * i1, hi, lo);
        *(unsigned *)(yh + g1) = hi; *(unsigned *)(yl + g1) = lo;
    }
}

// ------------------------- merged one-time weight conv + bias cat ----------
struct WA {
    const float *src[13];
    ll doff[13];
    int K[13], N[13];
    const float *bq, *bk, *bv;
    float *bqkv;
};

__global__ __launch_bounds__(256)
void wconv_all(WA a, bf16 *__restrict__ wh, bf16 *__restrict__ wl)
{
    int m = blockIdx.z;
    if (m == 13) {   // bias concat (single block does all 3072)
        if (blockIdx.x == 0 && blockIdx.y == 0) {
            for (int i = threadIdx.x; i < LL * 3 * CC; i += 256) {
                int l = i / (3 * CC), c = i % (3 * CC);
                float v;
                if (c < CC) v = a.bq[l * CC + c];
                else if (c < 2 * CC) v = a.bk[l * CC + c - CC];
                else v = a.bv[l * CC + c - 2 * CC];
                a.bqkv[i] = v;
            }
        }
        return;
    }
    int K = a.K[m], N = a.N[m];
    int bx = blockIdx.x * 32, by = blockIdx.y * 32;
    if (bx >= N || by >= K) return;
    const float *W = a.src[m];
    bf16 *th = wh + a.doff[m], *tl = wl + a.doff[m];
    __shared__ float tile[32][33];
    int tx = threadIdx.x & 31, ty = threadIdx.x >> 5;
#pragma unroll
    for (int j = 0; j < 4; j++) {
        int kk = ty + j * 8;
        tile[kk][tx] = W[(ll)(by + kk) * N + bx + tx];
    }
    __syncthreads();
#pragma unroll
    for (int j = 0; j < 4; j++) {
        int nn = ty + j * 8;
        float v = tile[tx][nn];
        bf16 h, l;
        split1(v, h, l);
        ll o = (ll)(bx + nn) * K + by + tx;
        th[o] = h; tl[o] = l;
    }
}

// ------------------------- warp-per-row LN ---------------------------------
__device__ __forceinline__ void ln_row_body(float4 *v, int lane, ll orow,
                                            const float *__restrict__ gam,
                                            const float *__restrict__ bet,
                                            bf16 *__restrict__ oh, bf16 *__restrict__ ol)
{
    float sum = 0.f;
#pragma unroll
    for (int k = 0; k < 4; k++) sum += v[k].x + v[k].y + v[k].z + v[k].w;
#pragma unroll
    for (int o = 16; o > 0; o >>= 1) sum += __shfl_xor_sync(0xffffffffu, sum, o);
    float mu = sum * (1.0f / CC);
    float var = 0.f;
#pragma unroll
    for (int k = 0; k < 4; k++) {
        v[k].x -= mu; v[k].y -= mu; v[k].z -= mu; v[k].w -= mu;
        var += v[k].x * v[k].x + v[k].y * v[k].y + v[k].z * v[k].z + v[k].w * v[k].w;
    }
#pragma unroll
    for (int o = 16; o > 0; o >>= 1) var += __shfl_xor_sync(0xffffffffu, var, o);
    float rstd = rsqrtf(var * (1.0f / CC) + 1e-5f);
#pragma unroll
    for (int k = 0; k < 4; k++) {
        int c = k * 128 + lane * 4;
        float r0 = v[k].x * rstd * gam[c]     + bet[c];
        float r1 = v[k].y * rstd * gam[c + 1] + bet[c + 1];
        float r2 = v[k].z * rstd * gam[c + 2] + bet[c + 2];
        float r3 = v[k].w * rstd * gam[c + 3] + bet[c + 3];
        unsigned h0, l0, h1, l1;
        split2(r0, r1, h0, l0);
        split2(r2, r3, h1, l1);
        *(uint2 *)(oh + orow + c) = make_uint2(h0, h1);
        *(uint2 *)(ol + orow + c) = make_uint2(l0, l1);
    }
}

__global__ __launch_bounds__(256)
void ln_kernel(const float *__restrict__ x, bf16 *__restrict__ oh, bf16 *__restrict__ ol,
               const float *__restrict__ gam, const float *__restrict__ bet)
{
    int w = threadIdx.x >> 5, lane = threadIdx.x & 31;
    int row = blockIdx.x * 8 + w;
    const float *xr = x + (ll)row * CC;
    float4 v[4];
#pragma unroll
    for (int k = 0; k < 4; k++) v[k] = *(const float4 *)(xr + k * 128 + lane * 4);
    ln_row_body(v, lane, (ll)row * CC, gam, bet, oh, ol);
}

// embed + first LN fused (x = tok[idx]+pos; xn = LN(x))
__global__ __launch_bounds__(256)
void embed_ln_kernel(const int *__restrict__ idx, const float *__restrict__ tok,
                     const float *__restrict__ pos, float *__restrict__ x,
                     bf16 *__restrict__ oh, bf16 *__restrict__ ol,
                     const float *__restrict__ gam, const float *__restrict__ bet)
{
    int w = threadIdx.x >> 5, lane = threadIdx.x & 31;
    int row = blockIdx.x * 8 + w;
    int tp = row & (TT - 1);
    int tr = idx[row];
    float4 v[4];
#pragma unroll
    for (int k = 0; k < 4; k++) {
        int c = k * 128 + lane * 4;
        float4 tv = *(const float4 *)(tok + (ll)tr * CC + c);
        float4 pv = *(const float4 *)(pos + (ll)tp * CC + c);
        v[k] = make_float4(tv.x + pv.x, tv.y + pv.y, tv.z + pv.z, tv.w + pv.w);
        *(float4 *)(x + (ll)row * CC + c) = v[k];
    }
    ln_row_body(v, lane, (ll)row * CC, gam, bet, oh, ol);
}

// ------------------------- host orchestration ------------------------------
static void run_hm(const bf16 *Ah, const bf16 *Al, int lda, ll sA0, ll sA1,
                   const bf16 *Bh, const bf16 *Bl, int ldb, ll sB0, ll sB1,
                   float *Cf, bf16 *Coh, bf16 *Col, int ldc, ll sC0, ll sC1,
                   int Mr, int Nc, int K, int zdiv, int Z,
                   const float *bias, int transB, int ep)
{
    dim3 g(Nc / 64, Mr / 128, Z);
    gemm_hmma<<<g, 256, SMEM_BYTES>>>(Ah, Al, lda, sA0, sA1, Bh, Bl, ldb, sB0, sB1,
                                      Cf, Coh, Col, ldc, sC0, sC1, K, zdiv, bias, transB, ep);
}

extern "C" void kernel_launch(void *const *d_in, const int *in_sizes, int n_in,
                              void *d_out, int out_size)
{
    (void)in_sizes; (void)n_in; (void)out_size;
    const int   *idx  = (const int *)d_in[0];
    const float *tok  = (const float *)d_in[1];
    const float *pos  = (const float *)d_in[2];
    const float *ln1g = (const float *)d_in[3];
    const float *ln1b = (const float *)d_in[4];
    const float *Wq   = (const float *)d_in[5];
    const float *bq   = (const float *)d_in[6];
    const float *Wk   = (const float *)d_in[7];
    const float *bk   = (const float *)d_in[8];
    const float *Wv   = (const float *)d_in[9];
    const float *bv   = (const float *)d_in[10];
    const float *Wp   = (const float *)d_in[11];
    const float *bp   = (const float *)d_in[12];
    const float *ln2g = (const float *)d_in[13];
    const float *ln2b = (const float *)d_in[14];
    const float *W1   = (const float *)d_in[15];
    const float *b1   = (const float *)d_in[16];
    const float *W2   = (const float *)d_in[17];
    const float *b2   = (const float *)d_in[18];
    const float *lnfg = (const float *)d_in[19];
    const float *lnfb = (const float *)d_in[20];
    const float *Wh   = (const float *)d_in[21];
    float *out = (float *)d_out;

    static int attr_set = 0;
    if (!attr_set) {
        cudaFuncSetAttribute(gemm_hmma, cudaFuncAttributeMaxDynamicSharedMemorySize, SMEM_BYTES);
        cudaFuncSetAttribute(flash_kernel, cudaFuncAttributeMaxDynamicSharedMemorySize, FL_BYTES);
        attr_set = 1;
    }

    float *x, *bqkv;
    bf16 *xnh, *xnl, *qkvh, *qkvl, *yh, *yl, *hh, *hl, *wh, *wl;
    cudaGetSymbolAddress((void **)&x, g_x);
    cudaGetSymbolAddress((void **)&bqkv, g_bqkv);
    cudaGetSymbolAddress((void **)&xnh, g_xnh);   cudaGetSymbolAddress((void **)&xnl, g_xnl);
    cudaGetSymbolAddress((void **)&qkvh, g_qkvh); cudaGetSymbolAddress((void **)&qkvl, g_qkvl);
    cudaGetSymbolAddress((void **)&yh, g_yh);     cudaGetSymbolAddress((void **)&yl, g_yl);
    cudaGetSymbolAddress((void **)&hh, g_hh);     cudaGetSymbolAddress((void **)&hl, g_hl);
    cudaGetSymbolAddress((void **)&wh, g_wh);     cudaGetSymbolAddress((void **)&wl, g_wl);

    WA wa;
    for (int l = 0; l < LL; l++) {
        ll wb = (ll)l * WOFF_L;
        int base = l * 6;
        wa.src[base + 0] = Wq + (ll)l * CC * CC; wa.doff[base + 0] = wb;           wa.K[base + 0] = CC; wa.N[base + 0] = CC;
        wa.src[base + 1] = Wk + (ll)l * CC * CC; wa.doff[base + 1] = wb + 262144;  wa.K[base + 1] = CC; wa.N[base + 1] = CC;
        wa.src[base + 2] = Wv + (ll)l * CC * CC; wa.doff[base + 2] = wb + 524288;  wa.K[base + 2] = CC; wa.N[base + 2] = CC;
        wa.src[base + 3] = Wp + (ll)l * CC * CC; wa.doff[base + 3] = wb + WOFF_P;  wa.K[base + 3] = CC; wa.N[base + 3] = CC;
        wa.src[base + 4] = W1 + (ll)l * CC * FF; wa.doff[base + 4] = wb + WOFF_1;  wa.K[base + 4] = CC; wa.N[base + 4] = FF;
        wa.src[base + 5] = W2 + (ll)l * FF * CC; wa.doff[base + 5] = wb + WOFF_2;  wa.K[base + 5] = FF; wa.N[base + 5] = CC;
    }
    wa.src[12] = Wh; wa.doff[12] = WOFF_HD; wa.K[12] = CC; wa.N[12] = CC;
    wa.bq = bq; wa.bk = bk; wa.bv = bv; wa.bqkv = bqkv;
    wconv_all<<<dim3(64, 64, 14), 256>>>(wa, wh, wl);           // launch 1
    embed_ln_kernel<<<MM / 8, 256>>>(idx, tok, pos, x, xnh, xnl, ln1g, ln1b); // launch 2

    const ll QKVROW = 3 * CC;

    for (int s = 0; s < STEPS; s++) {
        for (int l = 0; l < LL; l++) {
            ll wb = (ll)l * WOFF_L;
            if (!(s == 0 && l == 0))
                ln_kernel<<<MM / 8, 256>>>(x, xnh, xnl, ln1g + l * CC, ln1b + l * CC);
            // fused QKV  (launch 3 on first iteration)
            run_hm(xnh, xnl, CC, 0, 0, wh + wb + WOFF_QKV, wl + wb + WOFF_QKV, CC, 0, 0,
                   nullptr, qkvh, qkvl, (int)QKVROW, 0, 0,
                   MM, (int)QKVROW, CC, 1, 1, bqkv + l * QKVROW, 1, 3);
            // flash attention  (launch 4 on first iteration)
            flash_kernel<<<dim3(4, 64), 256, FL_BYTES>>>(qkvh, qkvl, yh, yl);
            // x += y @ Wp + bp
            run_hm(yh, yl, CC, 0, 0, wh + wb + WOFF_P, wl + wb + WOFF_P, CC, 0, 0,
                   x, nullptr, nullptr, CC, 0, 0, MM, CC, CC, 1, 1, bp + l * CC, 1, 2);
            ln_kernel<<<MM / 8, 256>>>(x, xnh, xnl, ln2g + l * CC, ln2b + l * CC);
            // h = gelu(xn @ W1 + b1)
            run_hm(xnh, xnl, CC, 0, 0, wh + wb + WOFF_1, wl + wb + WOFF_1, CC, 0, 0,
                   nullptr, hh, hl, FF, 0, 0, MM, FF, CC, 1, 1, b1 + l * FF, 1, 1);
            // x += h @ W2 + b2
            run_hm(hh, hl, FF, 0, 0, wh + wb + WOFF_2, wl + wb + WOFF_2, FF, 0, 0,
                   x, nullptr, nullptr, CC, 0, 0, MM, CC, FF, 1, 1, b2 + l * CC, 1, 2);
        }
    }
    ln_kernel<<<MM / 8, 256>>>(x, xnh, xnl, lnfg, lnfb);
    run_hm(xnh, xnl, CC, 0, 0, wh + WOFF_HD, wl + WOFF_HD, CC, 0, 0,
           out, nullptr, nullptr, CC, 0, 0, MM, CC, CC, 1, 1, nullptr, 1, 0);
}

// round 13
// speedup vs baseline: 1.5715x; 1.3499x over previous
#include <cuda_runtime.h>
#include <cuda_fp16.h>
#include <math.h>
#include <stdint.h>

#define BQ 8
#define TT 512
#define CC 512
#define HH 8
#define DHD 64
#define LL 2
#define MM (BQ * TT)
#define FF (4 * CC)
#define STEPS 4
typedef __half f16;
typedef long long ll;

// ------------------------- scratch (__device__ globals) --------------------
__device__ __align__(16) float g_x[MM * CC];
__device__ __align__(16) float g_bqkv[LL * 3 * CC];
__device__ __align__(16) f16 g_xn[MM * CC];                 // single plane
__device__ __align__(16) f16 g_qkvh[MM * 3 * CC], g_qkvl[MM * 3 * CC];
__device__ __align__(16) f16 g_y[MM * CC];                  // single plane
__device__ __align__(16) f16 g_h[MM * FF];                  // single plane
#define NW 6553600
__device__ __align__(16) f16 g_wh[NW], g_wl[NW];
#define WOFF_L   3145728
#define WOFF_QKV 0
#define WOFF_P   786432
#define WOFF_1   1048576
#define WOFF_2   2097152
#define WOFF_HD  6291456

// ------------------------- helpers -----------------------------------------
__device__ __forceinline__ void split1h(float v, f16 &h, f16 &l) {
    h = __float2half_rn(v);
    l = __float2half_rn(v - __half2float(h));
}
__device__ __forceinline__ unsigned pack2h(float x, float y) {
    __half2 r = __floats2half2_rn(x, y);
    return *(unsigned *)&r;
}
__device__ __forceinline__ void split2h(float x, float y, unsigned &hi, unsigned &lo) {
    f16 hx, lx, hy, ly;
    split1h(x, hx, lx); split1h(y, hy, ly);
    hi = ((unsigned)__half_as_ushort(hy) << 16) | (unsigned)__half_as_ushort(hx);
    lo = ((unsigned)__half_as_ushort(ly) << 16) | (unsigned)__half_as_ushort(lx);
}
__device__ __forceinline__ unsigned smem_u32(const void *p) {
    return (unsigned)__cvta_generic_to_shared(p);
}
__device__ __forceinline__ float gelu_exact(float x) {
    return 0.5f * x * (1.0f + erff(x * 0.7071067811865476f));
}
__device__ __forceinline__ void mma_f16(float *d, const unsigned *a, unsigned b0, unsigned b1) {
    asm volatile(
        "mma.sync.aligned.m16n8k16.row.col.f32.f16.f16.f32 "
        "{%0,%1,%2,%3}, {%4,%5,%6,%7}, {%8,%9}, {%0,%1,%2,%3};\n"
        : "+f"(d[0]), "+f"(d[1]), "+f"(d[2]), "+f"(d[3])
        : "r"(a[0]), "r"(a[1]), "r"(a[2]), "r"(a[3]), "r"(b0), "r"(b1));
}
#define LDSM4(R0, R1, R2, R3, ADDR) \
    asm volatile("ldmatrix.sync.aligned.m8n8.x4.shared.b16 {%0,%1,%2,%3}, [%4];" \
                 : "=r"(R0), "=r"(R1), "=r"(R2), "=r"(R3) : "r"(ADDR))
#define LDSM4T(R0, R1, R2, R3, ADDR) \
    asm volatile("ldmatrix.sync.aligned.m8n8.x4.trans.shared.b16 {%0,%1,%2,%3}, [%4];" \
                 : "=r"(R0), "=r"(R1), "=r"(R2), "=r"(R3) : "r"(ADDR))
#define CP16(dst, src) \
    asm volatile("cp.async.cg.shared.global [%0], [%1], 16;" :: "r"(dst), "l"(src))
#define CP_COMMIT() asm volatile("cp.async.commit_group;" ::: "memory")
#define CP_WAIT1()  asm volatile("cp.async.wait_group 1;" ::: "memory")
#define CP_WAIT0()  asm volatile("cp.async.wait_group 0;" ::: "memory")

// ------------------------- HMMA GEMM: A single fp16 x B fp16 hi/lo ---------
// D = A@B via 2 MMAs/logical-MMA: a*bh + a*bl. A K-major [m][k] single plane.
// transB=1: B [N,K]; transB=0: B [K,N]. Tile 128x64xK32, 8 warps, 3-stage.
// ep: 0 fp32 store; 1 gelu->single f16; 2 fp32 +=; 3 split f16 hi/lo store.
#define APITCH 40
#define BPT    40
#define BPN    72
// per-stage (f16 elems): A 5120 | Bh 2560 | Bl 2560 = 10240 (20480 B)
#define STAGE_B 20480u
#define SMEM_BYTES (3 * 20480)

__global__ __launch_bounds__(256, 2)
void gemm_hmma(const f16 *__restrict__ A_, int lda, ll sA0, ll sA1,
               const f16 *__restrict__ Bh_, const f16 *__restrict__ Bl_, int ldb,
               ll sB0, ll sB1,
               float *__restrict__ Cf, f16 *__restrict__ Coh, f16 *__restrict__ Col,
               int ldc, ll sC0, ll sC1,
               int K, int zdiv, const float *__restrict__ bias, int transB, int ep)
{
    extern __shared__ __align__(16) f16 sm[];
    int z = blockIdx.z;
    ll zo0 = z / zdiv, zo1 = z % zdiv;
    A_  += zo0 * sA0 + zo1 * sA1;
    Bh_ += zo0 * sB0 + zo1 * sB1;  Bl_ += zo0 * sB0 + zo1 * sB1;
    ll coff = zo0 * sC0 + zo1 * sC1;
    int n0 = blockIdx.x * 64, m0 = blockIdx.y * 128;

    int t = threadIdx.x, lane = t & 31, warp = t >> 5;
    int wm = (warp & 3) << 5, wn = (warp >> 2) << 5;
    int gg = lane >> 2, cc2 = (lane & 3) << 1;

    int a_ck = (t & 3) << 3, a_rw = t >> 2;
    int bt_rw = t >> 2, bt_ck = (t & 3) << 3;
    int bn_rw = t >> 3, bn_ck = (t & 7) << 3;

    unsigned sb = smem_u32(sm);

    int sel = lane >> 3, lr = lane & 7;
    int ar_g = lr + ((sel & 1) ? 8 : 0);
    int a_cs = (sel & 2) ? 8 : 0;
    int btr_g = lr + ((sel & 2) ? 8 : 0);
    int bt_cs = (sel & 1) ? 8 : 0;
    int bnr_g = lr + ((sel & 1) ? 8 : 0);
    int bn_cs = (sel & 2) ? 8 : 0;

    float acc[2][4][4];
#pragma unroll
    for (int mi = 0; mi < 2; mi++)
#pragma unroll
        for (int j = 0; j < 4; j++)
#pragma unroll
            for (int r = 0; r < 4; r++) acc[mi][j][r] = 0.f;

#define ISSUE(S, K0) do { \
    unsigned bb = sb + (unsigned)(S) * STAGE_B; \
    _Pragma("unroll") \
    for (int p = 0; p < 2; p++) { \
        int row = a_rw + 64 * p; \
        ll go = (ll)(m0 + row) * lda + (K0) + a_ck; \
        unsigned d = (unsigned)((row * APITCH + a_ck) * 2); \
        CP16(bb + d, A_ + go); \
    } \
    if (transB) { \
        ll go = (ll)(n0 + bt_rw) * ldb + (K0) + bt_ck; \
        unsigned d = (unsigned)((bt_rw * BPT + bt_ck) * 2); \
        CP16(bb + 10240u + d, Bh_ + go); \
        CP16(bb + 15360u + d, Bl_ + go); \
    } else { \
        ll go = (ll)((K0) + bn_rw) * ldb + n0 + bn_ck; \
        unsigned d = (unsigned)((bn_rw * BPN + bn_ck) * 2); \
        CP16(bb + 10240u + d, Bh_ + go); \
        CP16(bb + 15360u + d, Bl_ + go); \
    } \
    CP_COMMIT(); \
} while (0)

    int nk = K >> 5;
    ISSUE(0, 0);
    if (nk > 1) ISSUE(1, 32);

    for (int c = 0; c < nk; c++) {
        if (c + 1 < nk) CP_WAIT1(); else CP_WAIT0();
        __syncthreads();
        if (c + 2 < nk) ISSUE((c + 2) % 3, (c + 2) << 5);

        unsigned bb = sb + (unsigned)(c % 3) * STAGE_B;
        unsigned ao = bb, boh = bb + 10240u, bol = bb + 15360u;
#pragma unroll
        for (int ks = 0; ks < 2; ks++) {
            int kb = ks << 4;
            unsigned ah[2][4];
#pragma unroll
            for (int mi = 0; mi < 2; mi++) {
                unsigned off = (unsigned)(((wm + 16 * mi + ar_g) * APITCH + kb + a_cs) * 2);
                LDSM4(ah[mi][0], ah[mi][1], ah[mi][2], ah[mi][3], ao + off);
            }
            unsigned bh[4][2], bl2[4][2];
#pragma unroll
            for (int p = 0; p < 2; p++) {
                if (transB) {
                    unsigned off = (unsigned)(((wn + 16 * p + btr_g) * BPT + kb + bt_cs) * 2);
                    LDSM4(bh[2 * p][0], bh[2 * p][1], bh[2 * p + 1][0], bh[2 * p + 1][1], boh + off);
                    LDSM4(bl2[2 * p][0], bl2[2 * p][1], bl2[2 * p + 1][0], bl2[2 * p + 1][1], bol + off);
                } else {
                    unsigned off = (unsigned)(((kb + bnr_g) * BPN + wn + 16 * p + bn_cs) * 2);
                    LDSM4T(bh[2 * p][0], bh[2 * p][1], bh[2 * p + 1][0], bh[2 * p + 1][1], boh + off);
                    LDSM4T(bl2[2 * p][0], bl2[2 * p][1], bl2[2 * p + 1][0], bl2[2 * p + 1][1], bol + off);
                }
            }
#pragma unroll
            for (int mi = 0; mi < 2; mi++)
#pragma unroll
                for (int j = 0; j < 4; j++)
                    mma_f16(acc[mi][j], ah[mi], bh[j][0], bh[j][1]);
#pragma unroll
            for (int mi = 0; mi < 2; mi++)
#pragma unroll
                for (int j = 0; j < 4; j++)
                    mma_f16(acc[mi][j], ah[mi], bl2[j][0], bl2[j][1]);
        }
    }

#pragma unroll
    for (int mi = 0; mi < 2; mi++)
#pragma unroll
        for (int j = 0; j < 4; j++) {
            int col = n0 + wn + (j << 3) + cc2;
            int row = m0 + wm + (mi << 4) + gg;
            float b0v = bias ? bias[col] : 0.f;
            float b1v = bias ? bias[col + 1] : 0.f;
            float v00 = acc[mi][j][0] + b0v, v01 = acc[mi][j][1] + b1v;
            float v10 = acc[mi][j][2] + b0v, v11 = acc[mi][j][3] + b1v;
            ll g0 = (ll)row * ldc + col + coff;
            ll g1 = (ll)(row + 8) * ldc + col + coff;
            if (ep == 0) {
                *(float2 *)(Cf + g0) = make_float2(v00, v01);
                *(float2 *)(Cf + g1) = make_float2(v10, v11);
            } else if (ep == 2) {
                float2 o0 = *(float2 *)(Cf + g0), o1 = *(float2 *)(Cf + g1);
                *(float2 *)(Cf + g0) = make_float2(o0.x + v00, o0.y + v01);
                *(float2 *)(Cf + g1) = make_float2(o1.x + v10, o1.y + v11);
            } else if (ep == 1) {
                *(unsigned *)(Coh + g0) = pack2h(gelu_exact(v00), gelu_exact(v01));
                *(unsigned *)(Coh + g1) = pack2h(gelu_exact(v10), gelu_exact(v11));
            } else {   // ep == 3: split f16 hi/lo
                unsigned hi, lo;
                split2h(v00, v01, hi, lo);
                *(unsigned *)(Coh + g0) = hi; *(unsigned *)(Col + g0) = lo;
                split2h(v10, v11, hi, lo);
                *(unsigned *)(Coh + g1) = hi; *(unsigned *)(Col + g1) = lo;
            }
        }
}

// ------------------------- flash attention ---------------------------------
// Q single fp16 x K split (QK^T, 2 MMAs); P split (regs) x V single (PV, 2 MMAs).
#define FP 72
#define FL_Q  0
#define FL_KH 9216
#define FL_KL 13824
#define FL_VH 18432
#define FL_BYTES 46080

__global__ __launch_bounds__(256)
void flash_kernel(const f16 *__restrict__ qkvh, const f16 *__restrict__ qkvl,
                  f16 *__restrict__ y)
{
    extern __shared__ __align__(16) f16 fs[];
    int qt = blockIdx.x, bh = blockIdx.y;
    int b = bh >> 3, h = bh & 7;
    int t = threadIdx.x, lane = t & 31, w = t >> 5;
    ll rowbase = (ll)b * 512 * 1536 + h * 64;
    const f16 *Qg = qkvh + rowbase;
    const f16 *Kg = qkvh + rowbase + 512, *Kgl = qkvl + rowbase + 512;
    const f16 *Vg = qkvh + rowbase + 1024;

    for (int i = t; i < 1024; i += 256) {
        int r = i >> 3, ck = (i & 7) << 3;
        ll go = (ll)(qt * 128 + r) * 1536 + ck;
        *(uint4 *)(fs + FL_Q + r * FP + ck) = *(const uint4 *)(Qg + go);
    }

    int sel = lane >> 3, lr = lane & 7;
    int a_r = lr + ((sel & 1) ? 8 : 0), a_c = (sel & 2) ? 8 : 0;
    int bt_r = lr + ((sel & 2) ? 8 : 0), bt_c = (sel & 1) ? 8 : 0;
    int bn_r = lr + ((sel & 1) ? 8 : 0), bn_c = (sel & 2) ? 8 : 0;
    unsigned sb = smem_u32(fs);
    int g = lane >> 2, q4 = lane & 3;

    float acc_o[8][4];
#pragma unroll
    for (int j = 0; j < 8; j++)
#pragma unroll
        for (int r = 0; r < 4; r++) acc_o[j][r] = 0.f;
    float m0 = -1e30f, m1 = -1e30f, l0 = 0.f, l1 = 0.f;

    for (int kt = 0; kt < 8; kt++) {
        __syncthreads();
        for (int i = t; i < 512; i += 256) {
            int r = i >> 3, ck = (i & 7) << 3;
            ll go = (ll)(kt * 64 + r) * 1536 + ck;
            *(uint4 *)(fs + FL_KH + r * FP + ck) = *(const uint4 *)(Kg + go);
            *(uint4 *)(fs + FL_KL + r * FP + ck) = *(const uint4 *)(Kgl + go);
            *(uint4 *)(fs + FL_VH + r * FP + ck) = *(const uint4 *)(Vg + go);
        }
        __syncthreads();

        float s[8][4];
#pragma unroll
        for (int j = 0; j < 8; j++)
#pragma unroll
            for (int r = 0; r < 4; r++) s[j][r] = 0.f;
#pragma unroll
        for (int kc = 0; kc < 4; kc++) {
            int kb = kc << 4;
            unsigned qh_[4];
            unsigned qoff = (unsigned)(((w * 16 + a_r) * FP + kb + a_c) * 2);
            LDSM4(qh_[0], qh_[1], qh_[2], qh_[3], sb + FL_Q * 2 + qoff);
            unsigned kh_[8][2], kl_[8][2];
#pragma unroll
            for (int p = 0; p < 4; p++) {
                unsigned koff = (unsigned)(((p * 16 + bt_r) * FP + kb + bt_c) * 2);
                LDSM4(kh_[2 * p][0], kh_[2 * p][1], kh_[2 * p + 1][0], kh_[2 * p + 1][1],
                      sb + FL_KH * 2 + koff);
                LDSM4(kl_[2 * p][0], kl_[2 * p][1], kl_[2 * p + 1][0], kl_[2 * p + 1][1],
                      sb + FL_KL * 2 + koff);
            }
#pragma unroll
            for (int j = 0; j < 8; j++) mma_f16(s[j], qh_, kh_[j][0], kh_[j][1]);
#pragma unroll
            for (int j = 0; j < 8; j++) mma_f16(s[j], qh_, kl_[j][0], kl_[j][1]);
        }

        float tm0 = -1e30f, tm1 = -1e30f;
#pragma unroll
        for (int j = 0; j < 8; j++) {
            s[j][0] *= 0.125f; s[j][1] *= 0.125f; s[j][2] *= 0.125f; s[j][3] *= 0.125f;
            tm0 = fmaxf(tm0, fmaxf(s[j][0], s[j][1]));
            tm1 = fmaxf(tm1, fmaxf(s[j][2], s[j][3]));
        }
        tm0 = fmaxf(tm0, __shfl_xor_sync(0xffffffffu, tm0, 1));
        tm0 = fmaxf(tm0, __shfl_xor_sync(0xffffffffu, tm0, 2));
        tm1 = fmaxf(tm1, __shfl_xor_sync(0xffffffffu, tm1, 1));
        tm1 = fmaxf(tm1, __shfl_xor_sync(0xffffffffu, tm1, 2));
        float nm0 = fmaxf(m0, tm0), nm1 = fmaxf(m1, tm1);
        float al0 = __expf(m0 - nm0), al1 = __expf(m1 - nm1);
        m0 = nm0; m1 = nm1;
        float sum0 = 0.f, sum1 = 0.f;
#pragma unroll
        for (int j = 0; j < 8; j++) {
            s[j][0] = __expf(s[j][0] - nm0); sum0 += s[j][0];
            s[j][1] = __expf(s[j][1] - nm0); sum0 += s[j][1];
            s[j][2] = __expf(s[j][2] - nm1); sum1 += s[j][2];
            s[j][3] = __expf(s[j][3] - nm1); sum1 += s[j][3];
        }
        sum0 += __shfl_xor_sync(0xffffffffu, sum0, 1);
        sum0 += __shfl_xor_sync(0xffffffffu, sum0, 2);
        sum1 += __shfl_xor_sync(0xffffffffu, sum1, 1);
        sum1 += __shfl_xor_sync(0xffffffffu, sum1, 2);
        l0 = l0 * al0 + sum0; l1 = l1 * al1 + sum1;
#pragma unroll
        for (int j = 0; j < 8; j++) {
            acc_o[j][0] *= al0; acc_o[j][1] *= al0;
            acc_o[j][2] *= al1; acc_o[j][3] *= al1;
        }

#pragma unroll
        for (int kc = 0; kc < 4; kc++) {
            unsigned pah[4], pal[4];
            split2h(s[2 * kc][0],     s[2 * kc][1],     pah[0], pal[0]);
            split2h(s[2 * kc][2],     s[2 * kc][3],     pah[1], pal[1]);
            split2h(s[2 * kc + 1][0], s[2 * kc + 1][1], pah[2], pal[2]);
            split2h(s[2 * kc + 1][2], s[2 * kc + 1][3], pah[3], pal[3]);
            unsigned vh_[8][2];
#pragma unroll
            for (int p = 0; p < 4; p++) {
                unsigned voff = (unsigned)((((kc << 4) + bn_r) * FP + p * 16 + bn_c) * 2);
                LDSM4T(vh_[2 * p][0], vh_[2 * p][1], vh_[2 * p + 1][0], vh_[2 * p + 1][1],
                       sb + FL_VH * 2 + voff);
            }
#pragma unroll
            for (int j = 0; j < 8; j++) mma_f16(acc_o[j], pah, vh_[j][0], vh_[j][1]);
#pragma unroll
            for (int j = 0; j < 8; j++) mma_f16(acc_o[j], pal, vh_[j][0], vh_[j][1]);
        }
    }

    float i0 = 1.f / l0, i1 = 1.f / l1;
    int r0 = qt * 128 + w * 16 + g;
#pragma unroll
    for (int j = 0; j < 8; j++) {
        int col = h * 64 + j * 8 + 2 * q4;
        ll g0 = ((ll)(b * 512 + r0)) * 512 + col;
        ll g1 = ((ll)(b * 512 + r0 + 8)) * 512 + col;
        *(unsigned *)(y + g0) = pack2h(acc_o[j][0] * i0, acc_o[j][1] * i0);
        *(unsigned *)(y + g1) = pack2h(acc_o[j][2] * i1, acc_o[j][3] * i1);
    }
}

// ------------------------- merged one-time weight conv + bias cat ----------
struct WA {
    const float *src[13];
    ll doff[13];
    int K[13], N[13];
    const float *bq, *bk, *bv;
    float *bqkv;
};

__global__ __launch_bounds__(256)
void wconv_all(WA a, f16 *__restrict__ wh, f16 *__restrict__ wl)
{
    int m = blockIdx.z;
    if (m == 13) {
        if (blockIdx.x == 0 && blockIdx.y == 0) {
            for (int i = threadIdx.x; i < LL * 3 * CC; i += 256) {
                int l = i / (3 * CC), c = i % (3 * CC);
                float v;
                if (c < CC) v = a.bq[l * CC + c];
                else if (c < 2 * CC) v = a.bk[l * CC + c - CC];
                else v = a.bv[l * CC + c - 2 * CC];
                a.bqkv[i] = v;
            }
        }
        return;
    }
    int K = a.K[m], N = a.N[m];
    int bx = blockIdx.x * 32, by = blockIdx.y * 32;
    if (bx >= N || by >= K) return;
    const float *W = a.src[m];
    f16 *th = wh + a.doff[m], *tl = wl + a.doff[m];
    __shared__ float tile[32][33];
    int tx = threadIdx.x & 31, ty = threadIdx.x >> 5;
#pragma unroll
    for (int j = 0; j < 4; j++) {
        int kk = ty + j * 8;
        tile[kk][tx] = W[(ll)(by + kk) * N + bx + tx];
    }
    __syncthreads();
#pragma unroll
    for (int j = 0; j < 4; j++) {
        int nn = ty + j * 8;
        float v = tile[tx][nn];
        f16 h, l;
        split1h(v, h, l);
        ll o = (ll)(bx + nn) * K + by + tx;
        th[o] = h; tl[o] = l;
    }
}

// ------------------------- warp-per-row LN (single-plane output) -----------
__device__ __forceinline__ void ln_row_body(float4 *v, int lane, ll orow,
                                            const float *__restrict__ gam,
                                            const float *__restrict__ bet,
                                            f16 *__restrict__ oh)
{
    float sum = 0.f;
#pragma unroll
    for (int k = 0; k < 4; k++) sum += v[k].x + v[k].y + v[k].z + v[k].w;
#pragma unroll
    for (int o = 16; o > 0; o >>= 1) sum += __shfl_xor_sync(0xffffffffu, sum, o);
    float mu = sum * (1.0f / CC);
    float var = 0.f;
#pragma unroll
    for (int k = 0; k < 4; k++) {
        v[k].x -= mu; v[k].y -= mu; v[k].z -= mu; v[k].w -= mu;
        var += v[k].x * v[k].x + v[k].y * v[k].y + v[k].z * v[k].z + v[k].w * v[k].w;
    }
#pragma unroll
    for (int o = 16; o > 0; o >>= 1) var += __shfl_xor_sync(0xffffffffu, var, o);
    float rstd = rsqrtf(var * (1.0f / CC) + 1e-5f);
#pragma unroll
    for (int k = 0; k < 4; k++) {
        int c = k * 128 + lane * 4;
        float r0 = v[k].x * rstd * gam[c]     + bet[c];
        float r1 = v[k].y * rstd * gam[c + 1] + bet[c + 1];
        float r2 = v[k].z * rstd * gam[c + 2] + bet[c + 2];
        float r3 = v[k].w * rstd * gam[c + 3] + bet[c + 3];
        *(uint2 *)(oh + orow + c) = make_uint2(pack2h(r0, r1), pack2h(r2, r3));
    }
}

__global__ __launch_bounds__(256)
void ln_kernel(const float *__restrict__ x, f16 *__restrict__ oh,
               const float *__restrict__ gam, const float *__restrict__ bet)
{
    int w = threadIdx.x >> 5, lane = threadIdx.x & 31;
    int row = blockIdx.x * 8 + w;
    const float *xr = x + (ll)row * CC;
    float4 v[4];
#pragma unroll
    for (int k = 0; k < 4; k++) v[k] = *(const float4 *)(xr + k * 128 + lane * 4);
    ln_row_body(v, lane, (ll)row * CC, gam, bet, oh);
}

__global__ __launch_bounds__(256)
void embed_ln_kernel(const int *__restrict__ idx, const float *__restrict__ tok,
                     const float *__restrict__ pos, float *__restrict__ x,
                     f16 *__restrict__ oh,
                     const float *__restrict__ gam, const float *__restrict__ bet)
{
    int w = threadIdx.x >> 5, lane = threadIdx.x & 31;
    int row = blockIdx.x * 8 + w;
    int tp = row & (TT - 1);
    int tr = idx[row];
    float4 v[4];
#pragma unroll
    for (int k = 0; k < 4; k++) {
        int c = k * 128 + lane * 4;
        float4 tv = *(const float4 *)(tok + (ll)tr * CC + c);
        float4 pv = *(const float4 *)(pos + (ll)tp * CC + c);
        v[k] = make_float4(tv.x + pv.x, tv.y + pv.y, tv.z + pv.z, tv.w + pv.w);
        *(float4 *)(x + (ll)row * CC + c) = v[k];
    }
    ln_row_body(v, lane, (ll)row * CC, gam, bet, oh);
}

// ------------------------- host orchestration ------------------------------
static void run_hm(const f16 *A, int lda, ll sA0, ll sA1,
                   const f16 *Bh, const f16 *Bl, int ldb, ll sB0, ll sB1,
                   float *Cf, f16 *Coh, f16 *Col, int ldc, ll sC0, ll sC1,
                   int Mr, int Nc, int K, int zdiv, int Z,
                   const float *bias, int transB, int ep)
{
    dim3 g(Nc / 64, Mr / 128, Z);
    gemm_hmma<<<g, 256, SMEM_BYTES>>>(A, lda, sA0, sA1, Bh, Bl, ldb, sB0, sB1,
                                      Cf, Coh, Col, ldc, sC0, sC1, K, zdiv, bias, transB, ep);
}

extern "C" void kernel_launch(void *const *d_in, const int *in_sizes, int n_in,
                              void *d_out, int out_size)
{
    (void)in_sizes; (void)n_in; (void)out_size;
    const int   *idx  = (const int *)d_in[0];
    const float *tok  = (const float *)d_in[1];
    const float *pos  = (const float *)d_in[2];
    const float *ln1g = (const float *)d_in[3];
    const float *ln1b = (const float *)d_in[4];
    const float *Wq   = (const float *)d_in[5];
    const float *bq   = (const float *)d_in[6];
    const float *Wk   = (const float *)d_in[7];
    const float *bk   = (const float *)d_in[8];
    const float *Wv   = (const float *)d_in[9];
    const float *bv   = (const float *)d_in[10];
    const float *Wp   = (const float *)d_in[11];
    const float *bp   = (const float *)d_in[12];
    const float *ln2g = (const float *)d_in[13];
    const float *ln2b = (const float *)d_in[14];
    const float *W1   = (const float *)d_in[15];
    const float *b1   = (const float *)d_in[16];
    const float *W2   = (const float *)d_in[17];
    const float *b2   = (const float *)d_in[18];
    const float *lnfg = (const float *)d_in[19];
    const float *lnfb = (const float *)d_in[20];
    const float *Wh   = (const float *)d_in[21];
    float *out = (float *)d_out;

    static int attr_set = 0;
    if (!attr_set) {
        cudaFuncSetAttribute(gemm_hmma, cudaFuncAttributeMaxDynamicSharedMemorySize, SMEM_BYTES);
        cudaFuncSetAttribute(flash_kernel, cudaFuncAttributeMaxDynamicSharedMemorySize, FL_BYTES);
        attr_set = 1;
    }

    float *x, *bqkv;
    f16 *xn, *qkvh, *qkvl, *y, *h, *wh, *wl;
    cudaGetSymbolAddress((void **)&x, g_x);
    cudaGetSymbolAddress((void **)&bqkv, g_bqkv);
    cudaGetSymbolAddress((void **)&xn, g_xn);
    cudaGetSymbolAddress((void **)&qkvh, g_qkvh); cudaGetSymbolAddress((void **)&qkvl, g_qkvl);
    cudaGetSymbolAddress((void **)&y, g_y);
    cudaGetSymbolAddress((void **)&h, g_h);
    cudaGetSymbolAddress((void **)&wh, g_wh);     cudaGetSymbolAddress((void **)&wl, g_wl);

    WA wa;
    for (int l = 0; l < LL; l++) {
        ll wb = (ll)l * WOFF_L;
        int base = l * 6;
        wa.src[base + 0] = Wq + (ll)l * CC * CC; wa.doff[base + 0] = wb;           wa.K[base + 0] = CC; wa.N[base + 0] = CC;
        wa.src[base + 1] = Wk + (ll)l * CC * CC; wa.doff[base + 1] = wb + 262144;  wa.K[base + 1] = CC; wa.N[base + 1] = CC;
        wa.src[base + 2] = Wv + (ll)l * CC * CC; wa.doff[base + 2] = wb + 524288;  wa.K[base + 2] = CC; wa.N[base + 2] = CC;
        wa.src[base + 3] = Wp + (ll)l * CC * CC; wa.doff[base + 3] = wb + WOFF_P;  wa.K[base + 3] = CC; wa.N[base + 3] = CC;
        wa.src[base + 4] = W1 + (ll)l * CC * FF; wa.doff[base + 4] = wb + WOFF_1;  wa.K[base + 4] = CC; wa.N[base + 4] = FF;
        wa.src[base + 5] = W2 + (ll)l * FF * CC; wa.doff[base + 5] = wb + WOFF_2;  wa.K[base + 5] = FF; wa.N[base + 5] = CC;
    }
    wa.src[12] = Wh; wa.doff[12] = WOFF_HD; wa.K[12] = CC; wa.N[12] = CC;
    wa.bq = bq; wa.bk = bk; wa.bv = bv; wa.bqkv = bqkv;
    wconv_all<<<dim3(64, 64, 14), 256>>>(wa, wh, wl);
    embed_ln_kernel<<<MM / 8, 256>>>(idx, tok, pos, x, xn, ln1g, ln1b);

    const ll QKVROW = 3 * CC;

    for (int s = 0; s < STEPS; s++) {
        for (int l = 0; l < LL; l++) {
            ll wb = (ll)l * WOFF_L;
            if (!(s == 0 && l == 0))
                ln_kernel<<<MM / 8, 256>>>(x, xn, ln1g + l * CC, ln1b + l * CC);
            // fused QKV: split-store hi/lo (K needs lo for QK; Q/V use hi plane)
            run_hm(xn, CC, 0, 0, wh + wb + WOFF_QKV, wl + wb + WOFF_QKV, CC, 0, 0,
                   nullptr, qkvh, qkvl, (int)QKVROW, 0, 0,
                   MM, (int)QKVROW, CC, 1, 1, bqkv + l * QKVROW, 1, 3);
            flash_kernel<<<dim3(4, 64), 256, FL_BYTES>>>(qkvh, qkvl, y);
            // x += y @ Wp + bp
            run_hm(y, CC, 0, 0, wh + wb + WOFF_P, wl + wb + WOFF_P, CC, 0, 0,
                   x, nullptr, nullptr, CC, 0, 0, MM, CC, CC, 1, 1, bp + l * CC, 1, 2);
            ln_kernel<<<MM / 8, 256>>>(x, xn, ln2g + l * CC, ln2b + l * CC);
            // h = gelu(xn @ W1 + b1), single-plane store
            run_hm(xn, CC, 0, 0, wh + wb + WOFF_1, wl + wb + WOFF_1, CC, 0, 0,
                   nullptr, h, nullptr, FF, 0, 0, MM, FF, CC, 1, 1, b1 + l * FF, 1, 1);
            // x += h @ W2 + b2
            run_hm(h, FF, 0, 0, wh + wb + WOFF_2, wl + wb + WOFF_2, FF, 0, 0,
                   x, nullptr, nullptr, CC, 0, 0, MM, CC, FF, 1, 1, b2 + l * CC, 1, 2);
        }
    }
    ln_kernel<<<MM / 8, 256>>>(x, xn, lnfg, lnfb);
    run_hm(xn, CC, 0, 0, wh + WOFF_HD, wl + WOFF_HD, CC, 0, 0,
           out, nullptr, nullptr, CC, 0, 0, MM, CC, CC, 1, 1, nullptr, 1, 0);
}

// round 14
// speedup vs baseline: 2.3215x; 1.4772x over previous
#include <cuda_runtime.h>
#include <cuda_fp16.h>
#include <math.h>
#include <stdint.h>

#define BQ 8
#define TT 512
#define CC 512
#define HH 8
#define DHD 64
#define LL 2
#define MM (BQ * TT)
#define FF (4 * CC)
#define STEPS 4
typedef __half f16;
typedef long long ll;

// ------------------------- scratch (__device__ globals) --------------------
__device__ __align__(16) float g_x[MM * CC];
__device__ __align__(16) float g_bqkv[LL * 3 * CC];
__device__ __align__(16) f16 g_xn[MM * CC];
__device__ __align__(16) f16 g_qkv[MM * 3 * CC];
__device__ __align__(16) f16 g_y[MM * CC];
__device__ __align__(16) f16 g_h[MM * FF];
#define NW 6553600
__device__ __align__(16) f16 g_wh[NW];
#define WOFF_L   3145728
#define WOFF_QKV 0
#define WOFF_P   786432
#define WOFF_1   1048576
#define WOFF_2   2097152
#define WOFF_HD  6291456

// ------------------------- helpers -----------------------------------------
__device__ __forceinline__ unsigned pack2h(float x, float y) {
    __half2 r = __floats2half2_rn(x, y);
    return *(unsigned *)&r;
}
__device__ __forceinline__ unsigned smem_u32(const void *p) {
    return (unsigned)__cvta_generic_to_shared(p);
}
__device__ __forceinline__ float gelu_exact(float x) {
    return 0.5f * x * (1.0f + erff(x * 0.7071067811865476f));
}
__device__ __forceinline__ void mma_f16(float *d, const unsigned *a, unsigned b0, unsigned b1) {
    asm volatile(
        "mma.sync.aligned.m16n8k16.row.col.f32.f16.f16.f32 "
        "{%0,%1,%2,%3}, {%4,%5,%6,%7}, {%8,%9}, {%0,%1,%2,%3};\n"
        : "+f"(d[0]), "+f"(d[1]), "+f"(d[2]), "+f"(d[3])
        : "r"(a[0]), "r"(a[1]), "r"(a[2]), "r"(a[3]), "r"(b0), "r"(b1));
}
#define LDSM4(R0, R1, R2, R3, ADDR) \
    asm volatile("ldmatrix.sync.aligned.m8n8.x4.shared.b16 {%0,%1,%2,%3}, [%4];" \
                 : "=r"(R0), "=r"(R1), "=r"(R2), "=r"(R3) : "r"(ADDR))
#define LDSM4T(R0, R1, R2, R3, ADDR) \
    asm volatile("ldmatrix.sync.aligned.m8n8.x4.trans.shared.b16 {%0,%1,%2,%3}, [%4];" \
                 : "=r"(R0), "=r"(R1), "=r"(R2), "=r"(R3) : "r"(ADDR))
#define CP16(dst, src) \
    asm volatile("cp.async.cg.shared.global [%0], [%1], 16;" :: "r"(dst), "l"(src))
#define CP_COMMIT() asm volatile("cp.async.commit_group;" ::: "memory")
#define CP_WAIT1()  asm volatile("cp.async.wait_group 1;" ::: "memory")
#define CP_WAIT0()  asm volatile("cp.async.wait_group 0;" ::: "memory")

// ------------------------- HMMA GEMM: single fp16 x single fp16 ------------
// D = A@B, 1 MMA per logical MMA. A K-major [m][k].
// transB=1: B [N,K]; transB=0: B [K,N]. Tile 128x64xK32, 8 warps, 3-stage.
// ep: 0 fp32 store; 1 gelu->f16; 2 fp32 +=; 3 f16 store.
#define APITCH 40
#define BPT    40
#define BPN    72
// per-stage (f16 elems): A 5120 | B 2560 = 7680 (15360 B)
#define STAGE_B 15360u
#define SMEM_BYTES (3 * 15360)

__global__ __launch_bounds__(256, 2)
void gemm_hmma(const f16 *__restrict__ A_, int lda, ll sA0, ll sA1,
               const f16 *__restrict__ B_, int ldb, ll sB0, ll sB1,
               float *__restrict__ Cf, f16 *__restrict__ Co,
               int ldc, ll sC0, ll sC1,
               int K, int zdiv, const float *__restrict__ bias, int transB, int ep)
{
    extern __shared__ __align__(16) f16 sm[];
    int z = blockIdx.z;
    ll zo0 = z / zdiv, zo1 = z % zdiv;
    A_ += zo0 * sA0 + zo1 * sA1;
    B_ += zo0 * sB0 + zo1 * sB1;
    ll coff = zo0 * sC0 + zo1 * sC1;
    int n0 = blockIdx.x * 64, m0 = blockIdx.y * 128;

    int t = threadIdx.x, lane = t & 31, warp = t >> 5;
    int wm = (warp & 3) << 5, wn = (warp >> 2) << 5;
    int gg = lane >> 2, cc2 = (lane & 3) << 1;

    int a_ck = (t & 3) << 3, a_rw = t >> 2;
    int bt_rw = t >> 2, bt_ck = (t & 3) << 3;
    int bn_rw = t >> 3, bn_ck = (t & 7) << 3;

    unsigned sb = smem_u32(sm);

    int sel = lane >> 3, lr = lane & 7;
    int ar_g = lr + ((sel & 1) ? 8 : 0);
    int a_cs = (sel & 2) ? 8 : 0;
    int btr_g = lr + ((sel & 2) ? 8 : 0);
    int bt_cs = (sel & 1) ? 8 : 0;
    int bnr_g = lr + ((sel & 1) ? 8 : 0);
    int bn_cs = (sel & 2) ? 8 : 0;

    float acc[2][4][4];
#pragma unroll
    for (int mi = 0; mi < 2; mi++)
#pragma unroll
        for (int j = 0; j < 4; j++)
#pragma unroll
            for (int r = 0; r < 4; r++) acc[mi][j][r] = 0.f;

#define ISSUE(S, K0) do { \
    unsigned bb = sb + (unsigned)(S) * STAGE_B; \
    _Pragma("unroll") \
    for (int p = 0; p < 2; p++) { \
        int row = a_rw + 64 * p; \
        ll go = (ll)(m0 + row) * lda + (K0) + a_ck; \
        unsigned d = (unsigned)((row * APITCH + a_ck) * 2); \
        CP16(bb + d, A_ + go); \
    } \
    if (transB) { \
        ll go = (ll)(n0 + bt_rw) * ldb + (K0) + bt_ck; \
        unsigned d = (unsigned)((bt_rw * BPT + bt_ck) * 2); \
        CP16(bb + 10240u + d, B_ + go); \
    } else { \
        ll go = (ll)((K0) + bn_rw) * ldb + n0 + bn_ck; \
        unsigned d = (unsigned)((bn_rw * BPN + bn_ck) * 2); \
        CP16(bb + 10240u + d, B_ + go); \
    } \
    CP_COMMIT(); \
} while (0)

    int nk = K >> 5;
    ISSUE(0, 0);
    if (nk > 1) ISSUE(1, 32);

    for (int c = 0; c < nk; c++) {
        if (c + 1 < nk) CP_WAIT1(); else CP_WAIT0();
        __syncthreads();
        if (c + 2 < nk) ISSUE((c + 2) % 3, (c + 2) << 5);

        unsigned bb = sb + (unsigned)(c % 3) * STAGE_B;
        unsigned ao = bb, bo = bb + 10240u;
#pragma unroll
        for (int ks = 0; ks < 2; ks++) {
            int kb = ks << 4;
            unsigned ah[2][4];
#pragma unroll
            for (int mi = 0; mi < 2; mi++) {
                unsigned off = (unsigned)(((wm + 16 * mi + ar_g) * APITCH + kb + a_cs) * 2);
                LDSM4(ah[mi][0], ah[mi][1], ah[mi][2], ah[mi][3], ao + off);
            }
            unsigned bh[4][2];
#pragma unroll
            for (int p = 0; p < 2; p++) {
                if (transB) {
                    unsigned off = (unsigned)(((wn + 16 * p + btr_g) * BPT + kb + bt_cs) * 2);
                    LDSM4(bh[2 * p][0], bh[2 * p][1], bh[2 * p + 1][0], bh[2 * p + 1][1], bo + off);
                } else {
                    unsigned off = (unsigned)(((kb + bnr_g) * BPN + wn + 16 * p + bn_cs) * 2);
                    LDSM4T(bh[2 * p][0], bh[2 * p][1], bh[2 * p + 1][0], bh[2 * p + 1][1], bo + off);
                }
            }
#pragma unroll
            for (int mi = 0; mi < 2; mi++)
#pragma unroll
                for (int j = 0; j < 4; j++)
                    mma_f16(acc[mi][j], ah[mi], bh[j][0], bh[j][1]);
        }
    }

#pragma unroll
    for (int mi = 0; mi < 2; mi++)
#pragma unroll
        for (int j = 0; j < 4; j++) {
            int col = n0 + wn + (j << 3) + cc2;
            int row = m0 + wm + (mi << 4) + gg;
            float b0v = bias ? bias[col] : 0.f;
            float b1v = bias ? bias[col + 1] : 0.f;
            float v00 = acc[mi][j][0] + b0v, v01 = acc[mi][j][1] + b1v;
            float v10 = acc[mi][j][2] + b0v, v11 = acc[mi][j][3] + b1v;
            ll g0 = (ll)row * ldc + col + coff;
            ll g1 = (ll)(row + 8) * ldc + col + coff;
            if (ep == 0) {
                *(float2 *)(Cf + g0) = make_float2(v00, v01);
                *(float2 *)(Cf + g1) = make_float2(v10, v11);
            } else if (ep == 2) {
                float2 o0 = *(float2 *)(Cf + g0), o1 = *(float2 *)(Cf + g1);
                *(float2 *)(Cf + g0) = make_float2(o0.x + v00, o0.y + v01);
                *(float2 *)(Cf + g1) = make_float2(o1.x + v10, o1.y + v11);
            } else if (ep == 1) {
                *(unsigned *)(Co + g0) = pack2h(gelu_exact(v00), gelu_exact(v01));
                *(unsigned *)(Co + g1) = pack2h(gelu_exact(v10), gelu_exact(v11));
            } else {   // ep == 3: plain f16 store
                *(unsigned *)(Co + g0) = pack2h(v00, v01);
                *(unsigned *)(Co + g1) = pack2h(v10, v11);
            }
        }
}

// ------------------------- flash attention (all single fp16) ---------------
#define FP 72
#define FL_Q  0
#define FL_K  9216
#define FL_V  13824
#define FL_BYTES 36864

__global__ __launch_bounds__(256)
void flash_kernel(const f16 *__restrict__ qkv, f16 *__restrict__ y)
{
    extern __shared__ __align__(16) f16 fs[];
    int qt = blockIdx.x, bh = blockIdx.y;
    int b = bh >> 3, h = bh & 7;
    int t = threadIdx.x, lane = t & 31, w = t >> 5;
    ll rowbase = (ll)b * 512 * 1536 + h * 64;
    const f16 *Qg = qkv + rowbase;
    const f16 *Kg = qkv + rowbase + 512;
    const f16 *Vg = qkv + rowbase + 1024;

    for (int i = t; i < 1024; i += 256) {
        int r = i >> 3, ck = (i & 7) << 3;
        ll go = (ll)(qt * 128 + r) * 1536 + ck;
        *(uint4 *)(fs + FL_Q + r * FP + ck) = *(const uint4 *)(Qg + go);
    }

    int sel = lane >> 3, lr = lane & 7;
    int a_r = lr + ((sel & 1) ? 8 : 0), a_c = (sel & 2) ? 8 : 0;
    int bt_r = lr + ((sel & 2) ? 8 : 0), bt_c = (sel & 1) ? 8 : 0;
    int bn_r = lr + ((sel & 1) ? 8 : 0), bn_c = (sel & 2) ? 8 : 0;
    unsigned sb = smem_u32(fs);
    int g = lane >> 2, q4 = lane & 3;

    float acc_o[8][4];
#pragma unroll
    for (int j = 0; j < 8; j++)
#pragma unroll
        for (int r = 0; r < 4; r++) acc_o[j][r] = 0.f;
    float m0 = -1e30f, m1 = -1e30f, l0 = 0.f, l1 = 0.f;

    for (int kt = 0; kt < 8; kt++) {
        __syncthreads();
        for (int i = t; i < 512; i += 256) {
            int r = i >> 3, ck = (i & 7) << 3;
            ll go = (ll)(kt * 64 + r) * 1536 + ck;
            *(uint4 *)(fs + FL_K + r * FP + ck) = *(const uint4 *)(Kg + go);
            *(uint4 *)(fs + FL_V + r * FP + ck) = *(const uint4 *)(Vg + go);
        }
        __syncthreads();

        float s[8][4];
#pragma unroll
        for (int j = 0; j < 8; j++)
#pragma unroll
            for (int r = 0; r < 4; r++) s[j][r] = 0.f;
#pragma unroll
        for (int kc = 0; kc < 4; kc++) {
            int kb = kc << 4;
            unsigned qh_[4];
            unsigned qoff = (unsigned)(((w * 16 + a_r) * FP + kb + a_c) * 2);
            LDSM4(qh_[0], qh_[1], qh_[2], qh_[3], sb + FL_Q * 2 + qoff);
            unsigned kh_[8][2];
#pragma unroll
            for (int p = 0; p < 4; p++) {
                unsigned koff = (unsigned)(((p * 16 + bt_r) * FP + kb + bt_c) * 2);
                LDSM4(kh_[2 * p][0], kh_[2 * p][1], kh_[2 * p + 1][0], kh_[2 * p + 1][1],
                      sb + FL_K * 2 + koff);
            }
#pragma unroll
            for (int j = 0; j < 8; j++) mma_f16(s[j], qh_, kh_[j][0], kh_[j][1]);
        }

        float tm0 = -1e30f, tm1 = -1e30f;
#pragma unroll
        for (int j = 0; j < 8; j++) {
            s[j][0] *= 0.125f; s[j][1] *= 0.125f; s[j][2] *= 0.125f; s[j][3] *= 0.125f;
            tm0 = fmaxf(tm0, fmaxf(s[j][0], s[j][1]));
            tm1 = fmaxf(tm1, fmaxf(s[j][2], s[j][3]));
        }
        tm0 = fmaxf(tm0, __shfl_xor_sync(0xffffffffu, tm0, 1));
        tm0 = fmaxf(tm0, __shfl_xor_sync(0xffffffffu, tm0, 2));
        tm1 = fmaxf(tm1, __shfl_xor_sync(0xffffffffu, tm1, 1));
        tm1 = fmaxf(tm1, __shfl_xor_sync(0xffffffffu, tm1, 2));
        float nm0 = fmaxf(m0, tm0), nm1 = fmaxf(m1, tm1);
        float al0 = __expf(m0 - nm0), al1 = __expf(m1 - nm1);
        m0 = nm0; m1 = nm1;
        float sum0 = 0.f, sum1 = 0.f;
#pragma unroll
        for (int j = 0; j < 8; j++) {
            s[j][0] = __expf(s[j][0] - nm0); sum0 += s[j][0];
            s[j][1] = __expf(s[j][1] - nm0); sum0 += s[j][1];
            s[j][2] = __expf(s[j][2] - nm1); sum1 += s[j][2];
            s[j][3] = __expf(s[j][3] - nm1); sum1 += s[j][3];
        }
        sum0 += __shfl_xor_sync(0xffffffffu, sum0, 1);
        sum0 += __shfl_xor_sync(0xffffffffu, sum0, 2);
        sum1 += __shfl_xor_sync(0xffffffffu, sum1, 1);
        sum1 += __shfl_xor_sync(0xffffffffu, sum1, 2);
        l0 = l0 * al0 + sum0; l1 = l1 * al1 + sum1;
#pragma unroll
        for (int j = 0; j < 8; j++) {
            acc_o[j][0] *= al0; acc_o[j][1] *= al0;
            acc_o[j][2] *= al1; acc_o[j][3] *= al1;
        }

#pragma unroll
        for (int kc = 0; kc < 4; kc++) {
            unsigned pa[4];
            pa[0] = pack2h(s[2 * kc][0],     s[2 * kc][1]);
            pa[1] = pack2h(s[2 * kc][2],     s[2 * kc][3]);
            pa[2] = pack2h(s[2 * kc + 1][0], s[2 * kc + 1][1]);
            pa[3] = pack2h(s[2 * kc + 1][2], s[2 * kc + 1][3]);
            unsigned vh_[8][2];
#pragma unroll
            for (int p = 0; p < 4; p++) {
                unsigned voff = (unsigned)((((kc << 4) + bn_r) * FP + p * 16 + bn_c) * 2);
                LDSM4T(vh_[2 * p][0], vh_[2 * p][1], vh_[2 * p + 1][0], vh_[2 * p + 1][1],
                       sb + FL_V * 2 + voff);
            }
#pragma unroll
            for (int j = 0; j < 8; j++) mma_f16(acc_o[j], pa, vh_[j][0], vh_[j][1]);
        }
    }

    float i0 = 1.f / l0, i1 = 1.f / l1;
    int r0 = qt * 128 + w * 16 + g;
#pragma unroll
    for (int j = 0; j < 8; j++) {
        int col = h * 64 + j * 8 + 2 * q4;
        ll g0 = ((ll)(b * 512 + r0)) * 512 + col;
        ll g1 = ((ll)(b * 512 + r0 + 8)) * 512 + col;
        *(unsigned *)(y + g0) = pack2h(acc_o[j][0] * i0, acc_o[j][1] * i0);
        *(unsigned *)(y + g1) = pack2h(acc_o[j][2] * i1, acc_o[j][3] * i1);
    }
}

// ------------------------- merged one-time weight conv + bias cat ----------
struct WA {
    const float *src[13];
    ll doff[13];
    int K[13], N[13];
    const float *bq, *bk, *bv;
    float *bqkv;
};

__global__ __launch_bounds__(256)
void wconv_all(WA a, f16 *__restrict__ wh)
{
    int m = blockIdx.z;
    if (m == 13) {
        if (blockIdx.x == 0 && blockIdx.y == 0) {
            for (int i = threadIdx.x; i < LL * 3 * CC; i += 256) {
                int l = i / (3 * CC), c = i % (3 * CC);
                float v;
                if (c < CC) v = a.bq[l * CC + c];
                else if (c < 2 * CC) v = a.bk[l * CC + c - CC];
                else v = a.bv[l * CC + c - 2 * CC];
                a.bqkv[i] = v;
            }
        }
        return;
    }
    int K = a.K[m], N = a.N[m];
    int bx = blockIdx.x * 32, by = blockIdx.y * 32;
    if (bx >= N || by >= K) return;
    const float *W = a.src[m];
    f16 *th = wh + a.doff[m];
    __shared__ float tile[32][33];
    int tx = threadIdx.x & 31, ty = threadIdx.x >> 5;
#pragma unroll
    for (int j = 0; j < 4; j++) {
        int kk = ty + j * 8;
        tile[kk][tx] = W[(ll)(by + kk) * N + bx + tx];
    }
    __syncthreads();
#pragma unroll
    for (int j = 0; j < 4; j++) {
        int nn = ty + j * 8;
        th[(ll)(bx + nn) * K + by + tx] = __float2half_rn(tile[tx][nn]);
    }
}

// ------------------------- warp-per-row LN ---------------------------------
__device__ __forceinline__ void ln_row_body(float4 *v, int lane, ll orow,
                                            const float *__restrict__ gam,
                                            const float *__restrict__ bet,
                                            f16 *__restrict__ oh)
{
    float sum = 0.f;
#pragma unroll
    for (int k = 0; k < 4; k++) sum += v[k].x + v[k].y + v[k].z + v[k].w;
#pragma unroll
    for (int o = 16; o > 0; o >>= 1) sum += __shfl_xor_sync(0xffffffffu, sum, o);
    float mu = sum * (1.0f / CC);
    float var = 0.f;
#pragma unroll
    for (int k = 0; k < 4; k++) {
        v[k].x -= mu; v[k].y -= mu; v[k].z -= mu; v[k].w -= mu;
        var += v[k].x * v[k].x + v[k].y * v[k].y + v[k].z * v[k].z + v[k].w * v[k].w;
    }
#pragma unroll
    for (int o = 16; o > 0; o >>= 1) var += __shfl_xor_sync(0xffffffffu, var, o);
    float rstd = rsqrtf(var * (1.0f / CC) + 1e-5f);
#pragma unroll
    for (int k = 0; k < 4; k++) {
        int c = k * 128 + lane * 4;
        float r0 = v[k].x * rstd * gam[c]     + bet[c];
        float r1 = v[k].y * rstd * gam[c + 1] + bet[c + 1];
        float r2 = v[k].z * rstd * gam[c + 2] + bet[c + 2];
        float r3 = v[k].w * rstd * gam[c + 3] + bet[c + 3];
        *(uint2 *)(oh + orow + c) = make_uint2(pack2h(r0, r1), pack2h(r2, r3));
    }
}

__global__ __launch_bounds__(256)
void ln_kernel(const float *__restrict__ x, f16 *__restrict__ oh,
               const float *__restrict__ gam, const float *__restrict__ bet)
{
    int w = threadIdx.x >> 5, lane = threadIdx.x & 31;
    int row = blockIdx.x * 8 + w;
    const float *xr = x + (ll)row * CC;
    float4 v[4];
#pragma unroll
    for (int k = 0; k < 4; k++) v[k] = *(const float4 *)(xr + k * 128 + lane * 4);
    ln_row_body(v, lane, (ll)row * CC, gam, bet, oh);
}

__global__ __launch_bounds__(256)
void embed_ln_kernel(const int *__restrict__ idx, const float *__restrict__ tok,
                     const float *__restrict__ pos, float *__restrict__ x,
                     f16 *__restrict__ oh,
                     const float *__restrict__ gam, const float *__restrict__ bet)
{
    int w = threadIdx.x >> 5, lane = threadIdx.x & 31;
    int row = blockIdx.x * 8 + w;
    int tp = row & (TT - 1);
    int tr = idx[row];
    float4 v[4];
#pragma unroll
    for (int k = 0; k < 4; k++) {
        int c = k * 128 + lane * 4;
        float4 tv = *(const float4 *)(tok + (ll)tr * CC + c);
        float4 pv = *(const float4 *)(pos + (ll)tp * CC + c);
        v[k] = make_float4(tv.x + pv.x, tv.y + pv.y, tv.z + pv.z, tv.w + pv.w);
        *(float4 *)(x + (ll)row * CC + c) = v[k];
    }
    ln_row_body(v, lane, (ll)row * CC, gam, bet, oh);
}

// ------------------------- host orchestration ------------------------------
static void run_hm(const f16 *A, int lda, ll sA0, ll sA1,
                   const f16 *B, int ldb, ll sB0, ll sB1,
                   float *Cf, f16 *Co, int ldc, ll sC0, ll sC1,
                   int Mr, int Nc, int K, int zdiv, int Z,
                   const float *bias, int transB, int ep)
{
    dim3 g(Nc / 64, Mr / 128, Z);
    gemm_hmma<<<g, 256, SMEM_BYTES>>>(A, lda, sA0, sA1, B, ldb, sB0, sB1,
                                      Cf, Co, ldc, sC0, sC1, K, zdiv, bias, transB, ep);
}

extern "C" void kernel_launch(void *const *d_in, const int *in_sizes, int n_in,
                              void *d_out, int out_size)
{
    (void)in_sizes; (void)n_in; (void)out_size;
    const int   *idx  = (const int *)d_in[0];
    const float *tok  = (const float *)d_in[1];
    const float *pos  = (const float *)d_in[2];
    const float *ln1g = (const float *)d_in[3];
    const float *ln1b = (const float *)d_in[4];
    const float *Wq   = (const float *)d_in[5];
    const float *bq   = (const float *)d_in[6];
    const float *Wk   = (const float *)d_in[7];
    const float *bk   = (const float *)d_in[8];
    const float *Wv   = (const float *)d_in[9];
    const float *bv   = (const float *)d_in[10];
    const float *Wp   = (const float *)d_in[11];
    const float *bp   = (const float *)d_in[12];
    const float *ln2g = (const float *)d_in[13];
    const float *ln2b = (const float *)d_in[14];
    const float *W1   = (const float *)d_in[15];
    const float *b1   = (const float *)d_in[16];
    const float *W2   = (const float *)d_in[17];
    const float *b2   = (const float *)d_in[18];
    const float *lnfg = (const float *)d_in[19];
    const float *lnfb = (const float *)d_in[20];
    const float *Wh   = (const float *)d_in[21];
    float *out = (float *)d_out;

    static int attr_set = 0;
    if (!attr_set) {
        cudaFuncSetAttribute(gemm_hmma, cudaFuncAttributeMaxDynamicSharedMemorySize, SMEM_BYTES);
        cudaFuncSetAttribute(flash_kernel, cudaFuncAttributeMaxDynamicSharedMemorySize, FL_BYTES);
        attr_set = 1;
    }

    float *x, *bqkv;
    f16 *xn, *qkv, *y, *h, *wh;
    cudaGetSymbolAddress((void **)&x, g_x);
    cudaGetSymbolAddress((void **)&bqkv, g_bqkv);
    cudaGetSymbolAddress((void **)&xn, g_xn);
    cudaGetSymbolAddress((void **)&qkv, g_qkv);
    cudaGetSymbolAddress((void **)&y, g_y);
    cudaGetSymbolAddress((void **)&h, g_h);
    cudaGetSymbolAddress((void **)&wh, g_wh);

    WA wa;
    for (int l = 0; l < LL; l++) {
        ll wb = (ll)l * WOFF_L;
        int base = l * 6;
        wa.src[base + 0] = Wq + (ll)l * CC * CC; wa.doff[base + 0] = wb;           wa.K[base + 0] = CC; wa.N[base + 0] = CC;
        wa.src[base + 1] = Wk + (ll)l * CC * CC; wa.doff[base + 1] = wb + 262144;  wa.K[base + 1] = CC; wa.N[base + 1] = CC;
        wa.src[base + 2] = Wv + (ll)l * CC * CC; wa.doff[base + 2] = wb + 524288;  wa.K[base + 2] = CC; wa.N[base + 2] = CC;
        wa.src[base + 3] = Wp + (ll)l * CC * CC; wa.doff[base + 3] = wb + WOFF_P;  wa.K[base + 3] = CC; wa.N[base + 3] = CC;
        wa.src[base + 4] = W1 + (ll)l * CC * FF; wa.doff[base + 4] = wb + WOFF_1;  wa.K[base + 4] = CC; wa.N[base + 4] = FF;
        wa.src[base + 5] = W2 + (ll)l * FF * CC; wa.doff[base + 5] = wb + WOFF_2;  wa.K[base + 5] = FF; wa.N[base + 5] = CC;
    }
    wa.src[12] = Wh; wa.doff[12] = WOFF_HD; wa.K[12] = CC; wa.N[12] = CC;
    wa.bq = bq; wa.bk = bk; wa.bv = bv; wa.bqkv = bqkv;
    wconv_all<<<dim3(64, 64, 14), 256>>>(wa, wh);
    embed_ln_kernel<<<MM / 8, 256>>>(idx, tok, pos, x, xn, ln1g, ln1b);

    const ll QKVROW = 3 * CC;

    for (int s = 0; s < STEPS; s++) {
        for (int l = 0; l < LL; l++) {
            ll wb = (ll)l * WOFF_L;
            if (!(s == 0 && l == 0))
                ln_kernel<<<MM / 8, 256>>>(x, xn, ln1g + l * CC, ln1b + l * CC);
            // fused QKV -> single-plane f16
            run_hm(xn, CC, 0, 0, wh + wb + WOFF_QKV, CC, 0, 0,
                   nullptr, qkv, (int)QKVROW, 0, 0,
                   MM, (int)QKVROW, CC, 1, 1, bqkv + l * QKVROW, 1, 3);
            flash_kernel<<<dim3(4, 64), 256, FL_BYTES>>>(qkv, y);
            // x += y @ Wp + bp
            run_hm(y, CC, 0, 0, wh + wb + WOFF_P, CC, 0, 0,
                   x, nullptr, CC, 0, 0, MM, CC, CC, 1, 1, bp + l * CC, 1, 2);
            ln_kernel<<<MM / 8, 256>>>(x, xn, ln2g + l * CC, ln2b + l * CC);
            // h = gelu(xn @ W1 + b1)
            run_hm(xn, CC, 0, 0, wh + wb + WOFF_1, CC, 0, 0,
                   nullptr, h, FF, 0, 0, MM, FF, CC, 1, 1, b1 + l * FF, 1, 1);
            // x += h @ W2 + b2
            run_hm(h, FF, 0, 0, wh + wb + WOFF_2, FF, 0, 0,
                   x, nullptr, CC, 0, 0, MM, CC, FF, 1, 1, b2 + l * CC, 1, 2);
        }
    }
    ln_kernel<<<MM / 8, 256>>>(x, xn, lnfg, lnfb);
    run_hm(xn, CC, 0, 0, wh + WOFF_HD, CC, 0, 0,
           out, nullptr, CC, 0, 0, MM, CC, CC, 1, 1, nullptr, 1, 0);
}

// round 15
// speedup vs baseline: 2.7503x; 1.1847x over previous
#include <cuda_runtime.h>
#include <cuda_fp16.h>
#include <math.h>
#include <stdint.h>

#define BQ 8
#define TT 512
#define CC 512
#define HH 8
#define DHD 64
#define LL 2
#define MM (BQ * TT)
#define FF (4 * CC)
#define STEPS 4
typedef __half f16;
typedef long long ll;

// ------------------------- scratch (__device__ globals) --------------------
__device__ __align__(16) float g_x[MM * CC];
__device__ __align__(16) float g_bqkv[LL * 3 * CC];
__device__ __align__(16) f16 g_xn[MM * CC];
__device__ __align__(16) f16 g_qkv[MM * 3 * CC];
__device__ __align__(16) f16 g_y[MM * CC];
__device__ __align__(16) f16 g_h[MM * FF];
#define NW 6553600
__device__ __align__(16) f16 g_wh[NW];
#define WOFF_L   3145728
#define WOFF_QKV 0
#define WOFF_P   786432
#define WOFF_1   1048576
#define WOFF_2   2097152
#define WOFF_HD  6291456

// ------------------------- helpers -----------------------------------------
__device__ __forceinline__ unsigned pack2h(float x, float y) {
    __half2 r = __floats2half2_rn(x, y);
    return *(unsigned *)&r;
}
__device__ __forceinline__ unsigned smem_u32(const void *p) {
    return (unsigned)__cvta_generic_to_shared(p);
}
__device__ __forceinline__ float gelu_exact(float x) {
    return 0.5f * x * (1.0f + erff(x * 0.7071067811865476f));
}
__device__ __forceinline__ void mma_f16(float *d, const unsigned *a, unsigned b0, unsigned b1) {
    asm volatile(
        "mma.sync.aligned.m16n8k16.row.col.f32.f16.f16.f32 "
        "{%0,%1,%2,%3}, {%4,%5,%6,%7}, {%8,%9}, {%0,%1,%2,%3};\n"
        : "+f"(d[0]), "+f"(d[1]), "+f"(d[2]), "+f"(d[3])
        : "r"(a[0]), "r"(a[1]), "r"(a[2]), "r"(a[3]), "r"(b0), "r"(b1));
}
#define LDSM4(R0, R1, R2, R3, ADDR) \
    asm volatile("ldmatrix.sync.aligned.m8n8.x4.shared.b16 {%0,%1,%2,%3}, [%4];" \
                 : "=r"(R0), "=r"(R1), "=r"(R2), "=r"(R3) : "r"(ADDR))
#define LDSM4T(R0, R1, R2, R3, ADDR) \
    asm volatile("ldmatrix.sync.aligned.m8n8.x4.trans.shared.b16 {%0,%1,%2,%3}, [%4];" \
                 : "=r"(R0), "=r"(R1), "=r"(R2), "=r"(R3) : "r"(ADDR))
#define CP16(dst, src) \
    asm volatile("cp.async.cg.shared.global [%0], [%1], 16;" :: "r"(dst), "l"(src))
#define CP_COMMIT() asm volatile("cp.async.commit_group;" ::: "memory")
#define CP_WAIT1()  asm volatile("cp.async.wait_group 1;" ::: "memory")
#define CP_WAIT0()  asm volatile("cp.async.wait_group 0;" ::: "memory")

// ------------------------- HMMA GEMM: fp16 x fp16, K-chunk 64 --------------
// D = A@B^T. A K-major [m][k], B [N,K]. Tile 128x64xK64, 8 warps, 3-stage.
// ep: 0 fp32 store; 1 gelu->f16; 2 fp32 +=; 3 f16 store.
#define APITCH 72
// per-stage (f16 elems): A 128*72=9216 | B 64*72=4608 -> 13824 (27648 B)
#define STAGE_B 27648u
#define SMEM_BYTES (3 * 27648)

__global__ __launch_bounds__(256, 2)
void gemm_hmma(const f16 *__restrict__ A_, int lda, ll sA0, ll sA1,
               const f16 *__restrict__ B_, int ldb, ll sB0, ll sB1,
               float *__restrict__ Cf, f16 *__restrict__ Co,
               int ldc, ll sC0, ll sC1,
               int K, int zdiv, const float *__restrict__ bias, int ep)
{
    extern __shared__ __align__(16) f16 sm[];
    int z = blockIdx.z;
    ll zo0 = z / zdiv, zo1 = z % zdiv;
    A_ += zo0 * sA0 + zo1 * sA1;
    B_ += zo0 * sB0 + zo1 * sB1;
    ll coff = zo0 * sC0 + zo1 * sC1;
    int n0 = blockIdx.x * 64, m0 = blockIdx.y * 128;

    int t = threadIdx.x, lane = t & 31, warp = t >> 5;
    int wm = (warp & 3) << 5, wn = (warp >> 2) << 5;
    int gg = lane >> 2, cc2 = (lane & 3) << 1;

    int a_ck = (t & 7) << 3, a_rw = t >> 3;   // 32 rows/pass, 8 chunks/row

    unsigned sb = smem_u32(sm);

    int sel = lane >> 3, lr = lane & 7;
    int ar_g = lr + ((sel & 1) ? 8 : 0);
    int a_cs = (sel & 2) ? 8 : 0;
    int btr_g = lr + ((sel & 2) ? 8 : 0);
    int bt_cs = (sel & 1) ? 8 : 0;

    float acc[2][4][4];
#pragma unroll
    for (int mi = 0; mi < 2; mi++)
#pragma unroll
        for (int j = 0; j < 4; j++)
#pragma unroll
            for (int r = 0; r < 4; r++) acc[mi][j][r] = 0.f;

#define ISSUE(S, K0) do { \
    unsigned bb = sb + (unsigned)(S) * STAGE_B; \
    _Pragma("unroll") \
    for (int p = 0; p < 4; p++) { \
        int row = a_rw + 32 * p; \
        ll go = (ll)(m0 + row) * lda + (K0) + a_ck; \
        CP16(bb + (unsigned)((row * APITCH + a_ck) * 2), A_ + go); \
    } \
    _Pragma("unroll") \
    for (int p = 0; p < 2; p++) { \
        int row = a_rw + 32 * p; \
        ll go = (ll)(n0 + row) * ldb + (K0) + a_ck; \
        CP16(bb + 18432u + (unsigned)((row * APITCH + a_ck) * 2), B_ + go); \
    } \
    CP_COMMIT(); \
} while (0)

    int nk = K >> 6;
    ISSUE(0, 0);
    if (nk > 1) ISSUE(1, 64);

    for (int c = 0; c < nk; c++) {
        if (c + 1 < nk) CP_WAIT1(); else CP_WAIT0();
        __syncthreads();
        if (c + 2 < nk) ISSUE((c + 2) % 3, (c + 2) << 6);

        unsigned bb = sb + (unsigned)(c % 3) * STAGE_B;
        unsigned ao = bb, bo = bb + 18432u;
#pragma unroll
        for (int ks = 0; ks < 4; ks++) {
            int kb = ks << 4;
            unsigned ah[2][4];
#pragma unroll
            for (int mi = 0; mi < 2; mi++) {
                unsigned off = (unsigned)(((wm + 16 * mi + ar_g) * APITCH + kb + a_cs) * 2);
                LDSM4(ah[mi][0], ah[mi][1], ah[mi][2], ah[mi][3], ao + off);
            }
            unsigned bh[4][2];
#pragma unroll
            for (int p = 0; p < 2; p++) {
                unsigned off = (unsigned)(((wn + 16 * p + btr_g) * APITCH + kb + bt_cs) * 2);
                LDSM4(bh[2 * p][0], bh[2 * p][1], bh[2 * p + 1][0], bh[2 * p + 1][1], bo + off);
            }
#pragma unroll
            for (int mi = 0; mi < 2; mi++)
#pragma unroll
                for (int j = 0; j < 4; j++)
                    mma_f16(acc[mi][j], ah[mi], bh[j][0], bh[j][1]);
        }
    }

#pragma unroll
    for (int mi = 0; mi < 2; mi++)
#pragma unroll
        for (int j = 0; j < 4; j++) {
            int col = n0 + wn + (j << 3) + cc2;
            int row = m0 + wm + (mi << 4) + gg;
            float b0v = bias ? bias[col] : 0.f;
            float b1v = bias ? bias[col + 1] : 0.f;
            float v00 = acc[mi][j][0] + b0v, v01 = acc[mi][j][1] + b1v;
            float v10 = acc[mi][j][2] + b0v, v11 = acc[mi][j][3] + b1v;
            ll g0 = (ll)row * ldc + col + coff;
            ll g1 = (ll)(row + 8) * ldc + col + coff;
            if (ep == 0) {
                *(float2 *)(Cf + g0) = make_float2(v00, v01);
                *(float2 *)(Cf + g1) = make_float2(v10, v11);
            } else if (ep == 2) {
                float2 o0 = *(float2 *)(Cf + g0), o1 = *(float2 *)(Cf + g1);
                *(float2 *)(Cf + g0) = make_float2(o0.x + v00, o0.y + v01);
                *(float2 *)(Cf + g1) = make_float2(o1.x + v10, o1.y + v11);
            } else if (ep == 1) {
                *(unsigned *)(Co + g0) = pack2h(gelu_exact(v00), gelu_exact(v01));
                *(unsigned *)(Co + g1) = pack2h(gelu_exact(v10), gelu_exact(v11));
            } else {
                *(unsigned *)(Co + g0) = pack2h(v00, v01);
                *(unsigned *)(Co + g1) = pack2h(v10, v11);
            }
        }
}

// ------------------------- flash attention ---------------------------------
// Q tile 64 rows, 4 warps (128 thr), grid (8, 64). K/V double-buffered cp.async.
#define FP 72
#define FQ_OFF 0
#define FK_OFF(buf) (4608 + (buf) * 4608)
#define FV_OFF(buf) (13824 + (buf) * 4608)
#define FL_BYTES 46080

__global__ __launch_bounds__(128)
void flash_kernel(const f16 *__restrict__ qkv, f16 *__restrict__ y)
{
    extern __shared__ __align__(16) f16 fs[];
    int qt = blockIdx.x, bh = blockIdx.y;
    int b = bh >> 3, h = bh & 7;
    int t = threadIdx.x, lane = t & 31, w = t >> 5;   // w in 0..3
    ll rowbase = (ll)b * 512 * 1536 + h * 64;
    const f16 *Qg = qkv + rowbase;
    const f16 *Kg = qkv + rowbase + 512;
    const f16 *Vg = qkv + rowbase + 1024;
    unsigned sb = smem_u32(fs);

    // Q tile (64 rows) - plain loads, covered by first barrier
    for (int i = t; i < 512; i += 128) {
        int r = i >> 3, ck = (i & 7) << 3;
        ll go = (ll)(qt * 64 + r) * 1536 + ck;
        *(uint4 *)(fs + FQ_OFF + r * FP + ck) = *(const uint4 *)(Qg + go);
    }

#define ISSUE_KV(BUF, KT) do { \
    _Pragma("unroll") \
    for (int p = 0; p < 4; p++) { \
        int idx = t + 128 * p; \
        int r = idx >> 3, ck = (idx & 7) << 3; \
        ll go = (ll)((KT) * 64 + r) * 1536 + ck; \
        CP16(sb + (unsigned)((FK_OFF(BUF) + r * FP + ck) * 2), Kg + go); \
        CP16(sb + (unsigned)((FV_OFF(BUF) + r * FP + ck) * 2), Vg + go); \
    } \
    CP_COMMIT(); \
} while (0)

    int sel = lane >> 3, lr = lane & 7;
    int a_r = lr + ((sel & 1) ? 8 : 0), a_c = (sel & 2) ? 8 : 0;
    int bt_r = lr + ((sel & 2) ? 8 : 0), bt_c = (sel & 1) ? 8 : 0;
    int bn_r = lr + ((sel & 1) ? 8 : 0), bn_c = (sel & 2) ? 8 : 0;
    int g = lane >> 2, q4 = lane & 3;

    float acc_o[8][4];
#pragma unroll
    for (int j = 0; j < 8; j++)
#pragma unroll
        for (int r = 0; r < 4; r++) acc_o[j][r] = 0.f;
    float m0 = -1e30f, m1 = -1e30f, l0 = 0.f, l1 = 0.f;

    ISSUE_KV(0, 0);

    for (int kt = 0; kt < 8; kt++) {
        CP_WAIT0();
        __syncthreads();
        if (kt + 1 < 8) ISSUE_KV((kt + 1) & 1, kt + 1);
        int buf = kt & 1;
        unsigned kbase = sb + (unsigned)(FK_OFF(buf) * 2);
        unsigned vbase = sb + (unsigned)(FV_OFF(buf) * 2);

        float s[8][4];
#pragma unroll
        for (int j = 0; j < 8; j++)
#pragma unroll
            for (int r = 0; r < 4; r++) s[j][r] = 0.f;
#pragma unroll
        for (int kc = 0; kc < 4; kc++) {
            int kb = kc << 4;
            unsigned qh_[4];
            unsigned qoff = (unsigned)(((w * 16 + a_r) * FP + kb + a_c) * 2);
            LDSM4(qh_[0], qh_[1], qh_[2], qh_[3], sb + FQ_OFF * 2 + qoff);
            unsigned kh_[8][2];
#pragma unroll
            for (int p = 0; p < 4; p++) {
                unsigned koff = (unsigned)(((p * 16 + bt_r) * FP + kb + bt_c) * 2);
                LDSM4(kh_[2 * p][0], kh_[2 * p][1], kh_[2 * p + 1][0], kh_[2 * p + 1][1],
                      kbase + koff);
            }
#pragma unroll
            for (int j = 0; j < 8; j++) mma_f16(s[j], qh_, kh_[j][0], kh_[j][1]);
        }

        float tm0 = -1e30f, tm1 = -1e30f;
#pragma unroll
        for (int j = 0; j < 8; j++) {
            s[j][0] *= 0.125f; s[j][1] *= 0.125f; s[j][2] *= 0.125f; s[j][3] *= 0.125f;
            tm0 = fmaxf(tm0, fmaxf(s[j][0], s[j][1]));
            tm1 = fmaxf(tm1, fmaxf(s[j][2], s[j][3]));
        }
        tm0 = fmaxf(tm0, __shfl_xor_sync(0xffffffffu, tm0, 1));
        tm0 = fmaxf(tm0, __shfl_xor_sync(0xffffffffu, tm0, 2));
        tm1 = fmaxf(tm1, __shfl_xor_sync(0xffffffffu, tm1, 1));
        tm1 = fmaxf(tm1, __shfl_xor_sync(0xffffffffu, tm1, 2));
        float nm0 = fmaxf(m0, tm0), nm1 = fmaxf(m1, tm1);
        float al0 = __expf(m0 - nm0), al1 = __expf(m1 - nm1);
        m0 = nm0; m1 = nm1;
        float sum0 = 0.f, sum1 = 0.f;
#pragma unroll
        for (int j = 0; j < 8; j++) {
            s[j][0] = __expf(s[j][0] - nm0); sum0 += s[j][0];
            s[j][1] = __expf(s[j][1] - nm0); sum0 += s[j][1];
            s[j][2] = __expf(s[j][2] - nm1); sum1 += s[j][2];
            s[j][3] = __expf(s[j][3] - nm1); sum1 += s[j][3];
        }
        sum0 += __shfl_xor_sync(0xffffffffu, sum0, 1);
        sum0 += __shfl_xor_sync(0xffffffffu, sum0, 2);
        sum1 += __shfl_xor_sync(0xffffffffu, sum1, 1);
        sum1 += __shfl_xor_sync(0xffffffffu, sum1, 2);
        l0 = l0 * al0 + sum0; l1 = l1 * al1 + sum1;
#pragma unroll
        for (int j = 0; j < 8; j++) {
            acc_o[j][0] *= al0; acc_o[j][1] *= al0;
            acc_o[j][2] *= al1; acc_o[j][3] *= al1;
        }

#pragma unroll
        for (int kc = 0; kc < 4; kc++) {
            unsigned pa[4];
            pa[0] = pack2h(s[2 * kc][0],     s[2 * kc][1]);
            pa[1] = pack2h(s[2 * kc][2],     s[2 * kc][3]);
            pa[2] = pack2h(s[2 * kc + 1][0], s[2 * kc + 1][1]);
            pa[3] = pack2h(s[2 * kc + 1][2], s[2 * kc + 1][3]);
            unsigned vh_[8][2];
#pragma unroll
            for (int p = 0; p < 4; p++) {
                unsigned voff = (unsigned)((((kc << 4) + bn_r) * FP + p * 16 + bn_c) * 2);
                LDSM4T(vh_[2 * p][0], vh_[2 * p][1], vh_[2 * p + 1][0], vh_[2 * p + 1][1],
                       vbase + voff);
            }
#pragma unroll
            for (int j = 0; j < 8; j++) mma_f16(acc_o[j], pa, vh_[j][0], vh_[j][1]);
        }
    }

    float i0 = 1.f / l0, i1 = 1.f / l1;
    int r0 = qt * 64 + w * 16 + g;
#pragma unroll
    for (int j = 0; j < 8; j++) {
        int col = h * 64 + j * 8 + 2 * q4;
        ll g0 = ((ll)(b * 512 + r0)) * 512 + col;
        ll g1 = ((ll)(b * 512 + r0 + 8)) * 512 + col;
        *(unsigned *)(y + g0) = pack2h(acc_o[j][0] * i0, acc_o[j][1] * i0);
        *(unsigned *)(y + g1) = pack2h(acc_o[j][2] * i1, acc_o[j][3] * i1);
    }
}

// ------------------------- merged one-time weight conv + bias cat ----------
struct WA {
    const float *src[13];
    ll doff[13];
    int K[13], N[13];
    const float *bq, *bk, *bv;
    float *bqkv;
};

__global__ __launch_bounds__(256)
void wconv_all(WA a, f16 *__restrict__ wh)
{
    int m = blockIdx.z;
    if (m == 13) {
        if (blockIdx.x == 0 && blockIdx.y == 0) {
            for (int i = threadIdx.x; i < LL * 3 * CC; i += 256) {
                int l = i / (3 * CC), c = i % (3 * CC);
                float v;
                if (c < CC) v = a.bq[l * CC + c];
                else if (c < 2 * CC) v = a.bk[l * CC + c - CC];
                else v = a.bv[l * CC + c - 2 * CC];
                a.bqkv[i] = v;
            }
        }
        return;
    }
    int K = a.K[m], N = a.N[m];
    int bx = blockIdx.x * 32, by = blockIdx.y * 32;
    if (bx >= N || by >= K) return;
    const float *W = a.src[m];
    f16 *th = wh + a.doff[m];
    __shared__ float tile[32][33];
    int tx = threadIdx.x & 31, ty = threadIdx.x >> 5;
#pragma unroll
    for (int j = 0; j < 4; j++) {
        int kk = ty + j * 8;
        tile[kk][tx] = W[(ll)(by + kk) * N + bx + tx];
    }
    __syncthreads();
#pragma unroll
    for (int j = 0; j < 4; j++) {
        int nn = ty + j * 8;
        th[(ll)(bx + nn) * K + by + tx] = __float2half_rn(tile[tx][nn]);
    }
}

// ------------------------- warp-per-row LN ---------------------------------
__device__ __forceinline__ void ln_row_body(float4 *v, int lane, ll orow,
                                            const float *__restrict__ gam,
                                            const float *__restrict__ bet,
                                            f16 *__restrict__ oh)
{
    float sum = 0.f;
#pragma unroll
    for (int k = 0; k < 4; k++) sum += v[k].x + v[k].y + v[k].z + v[k].w;
#pragma unroll
    for (int o = 16; o > 0; o >>= 1) sum += __shfl_xor_sync(0xffffffffu, sum, o);
    float mu = sum * (1.0f / CC);
    float var = 0.f;
#pragma unroll
    for (int k = 0; k < 4; k++) {
        v[k].x -= mu; v[k].y -= mu; v[k].z -= mu; v[k].w -= mu;
        var += v[k].x * v[k].x + v[k].y * v[k].y + v[k].z * v[k].z + v[k].w * v[k].w;
    }
#pragma unroll
    for (int o = 16; o > 0; o >>= 1) var += __shfl_xor_sync(0xffffffffu, var, o);
    float rstd = rsqrtf(var * (1.0f / CC) + 1e-5f);
#pragma unroll
    for (int k = 0; k < 4; k++) {
        int c = k * 128 + lane * 4;
        float r0 = v[k].x * rstd * gam[c]     + bet[c];
        float r1 = v[k].y * rstd * gam[c + 1] + bet[c + 1];
        float r2 = v[k].z * rstd * gam[c + 2] + bet[c + 2];
        float r3 = v[k].w * rstd * gam[c + 3] + bet[c + 3];
        *(uint2 *)(oh + orow + c) = make_uint2(pack2h(r0, r1), pack2h(r2, r3));
    }
}

__global__ __launch_bounds__(256)
void ln_kernel(const float *__restrict__ x, f16 *__restrict__ oh,
               const float *__restrict__ gam, const float *__restrict__ bet)
{
    int w = threadIdx.x >> 5, lane = threadIdx.x & 31;
    int row = blockIdx.x * 8 + w;
    const float *xr = x + (ll)row * CC;
    float4 v[4];
#pragma unroll
    for (int k = 0; k < 4; k++) v[k] = *(const float4 *)(xr + k * 128 + lane * 4);
    ln_row_body(v, lane, (ll)row * CC, gam, bet, oh);
}

__global__ __launch_bounds__(256)
void embed_ln_kernel(const int *__restrict__ idx, const float *__restrict__ tok,
                     const float *__restrict__ pos, float *__restrict__ x,
                     f16 *__restrict__ oh,
                     const float *__restrict__ gam, const float *__restrict__ bet)
{
    int w = threadIdx.x >> 5, lane = threadIdx.x & 31;
    int row = blockIdx.x * 8 + w;
    int tp = row & (TT - 1);
    int tr = idx[row];
    float4 v[4];
#pragma unroll
    for (int k = 0; k < 4; k++) {
        int c = k * 128 + lane * 4;
        float4 tv = *(const float4 *)(tok + (ll)tr * CC + c);
        float4 pv = *(const float4 *)(pos + (ll)tp * CC + c);
        v[k] = make_float4(tv.x + pv.x, tv.y + pv.y, tv.z + pv.z, tv.w + pv.w);
        *(float4 *)(x + (ll)row * CC + c) = v[k];
    }
    ln_row_body(v, lane, (ll)row * CC, gam, bet, oh);
}

// ------------------------- host orchestration ------------------------------
static void run_hm(const f16 *A, int lda, ll sA0, ll sA1,
                   const f16 *B, int ldb, ll sB0, ll sB1,
                   float *Cf, f16 *Co, int ldc, ll sC0, ll sC1,
                   int Mr, int Nc, int K, int zdiv, int Z,
                   const float *bias, int ep)
{
    dim3 g(Nc / 64, Mr / 128, Z);
    gemm_hmma<<<g, 256, SMEM_BYTES>>>(A, lda, sA0, sA1, B, ldb, sB0, sB1,
                                      Cf, Co, ldc, sC0, sC1, K, zdiv, bias, ep);
}

extern "C" void kernel_launch(void *const *d_in, const int *in_sizes, int n_in,
                              void *d_out, int out_size)
{
    (void)in_sizes; (void)n_in; (void)out_size;
    const int   *idx  = (const int *)d_in[0];
    const float *tok  = (const float *)d_in[1];
    const float *pos  = (const float *)d_in[2];
    const float *ln1g = (const float *)d_in[3];
    const float *ln1b = (const float *)d_in[4];
    const float *Wq   = (const float *)d_in[5];
    const float *bq   = (const float *)d_in[6];
    const float *Wk   = (const float *)d_in[7];
    const float *bk   = (const float *)d_in[8];
    const float *Wv   = (const float *)d_in[9];
    const float *bv   = (const float *)d_in[10];
    const float *Wp   = (const float *)d_in[11];
    const float *bp   = (const float *)d_in[12];
    const float *ln2g = (const float *)d_in[13];
    const float *ln2b = (const float *)d_in[14];
    const float *W1   = (const float *)d_in[15];
    const float *b1   = (const float *)d_in[16];
    const float *W2   = (const float *)d_in[17];
    const float *b2   = (const float *)d_in[18];
    const float *lnfg = (const float *)d_in[19];
    const float *lnfb = (const float *)d_in[20];
    const float *Wh   = (const float *)d_in[21];
    float *out = (float *)d_out;

    static int attr_set = 0;
    if (!attr_set) {
        cudaFuncSetAttribute(gemm_hmma, cudaFuncAttributeMaxDynamicSharedMemorySize, SMEM_BYTES);
        cudaFuncSetAttribute(flash_kernel, cudaFuncAttributeMaxDynamicSharedMemorySize, FL_BYTES);
        attr_set = 1;
    }

    float *x, *bqkv;
    f16 *xn, *qkv, *y, *h, *wh;
    cudaGetSymbolAddress((void **)&x, g_x);
    cudaGetSymbolAddress((void **)&bqkv, g_bqkv);
    cudaGetSymbolAddress((void **)&xn, g_xn);
    cudaGetSymbolAddress((void **)&qkv, g_qkv);
    cudaGetSymbolAddress((void **)&y, g_y);
    cudaGetSymbolAddress((void **)&h, g_h);
    cudaGetSymbolAddress((void **)&wh, g_wh);

    WA wa;
    for (int l = 0; l < LL; l++) {
        ll wb = (ll)l * WOFF_L;
        int base = l * 6;
        wa.src[base + 0] = Wq + (ll)l * CC * CC; wa.doff[base + 0] = wb;           wa.K[base + 0] = CC; wa.N[base + 0] = CC;
        wa.src[base + 1] = Wk + (ll)l * CC * CC; wa.doff[base + 1] = wb + 262144;  wa.K[base + 1] = CC; wa.N[base + 1] = CC;
        wa.src[base + 2] = Wv + (ll)l * CC * CC; wa.doff[base + 2] = wb + 524288;  wa.K[base + 2] = CC; wa.N[base + 2] = CC;
        wa.src[base + 3] = Wp + (ll)l * CC * CC; wa.doff[base + 3] = wb + WOFF_P;  wa.K[base + 3] = CC; wa.N[base + 3] = CC;
        wa.src[base + 4] = W1 + (ll)l * CC * FF; wa.doff[base + 4] = wb + WOFF_1;  wa.K[base + 4] = CC; wa.N[base + 4] = FF;
        wa.src[base + 5] = W2 + (ll)l * FF * CC; wa.doff[base + 5] = wb + WOFF_2;  wa.K[base + 5] = FF; wa.N[base + 5] = CC;
    }
    wa.src[12] = Wh; wa.doff[12] = WOFF_HD; wa.K[12] = CC; wa.N[12] = CC;
    wa.bq = bq; wa.bk = bk; wa.bv = bv; wa.bqkv = bqkv;
    wconv_all<<<dim3(64, 64, 14), 256>>>(wa, wh);
    embed_ln_kernel<<<MM / 8, 256>>>(idx, tok, pos, x, xn, ln1g, ln1b);

    const ll QKVROW = 3 * CC;

    for (int s = 0; s < STEPS; s++) {
        for (int l = 0; l < LL; l++) {
            ll wb = (ll)l * WOFF_L;
            if (!(s == 0 && l == 0))
                ln_kernel<<<MM / 8, 256>>>(x, xn, ln1g + l * CC, ln1b + l * CC);
            // fused QKV -> f16
            run_hm(xn, CC, 0, 0, wh + wb + WOFF_QKV, CC, 0, 0,
                   nullptr, qkv, (int)QKVROW, 0, 0,
                   MM, (int)QKVROW, CC, 1, 1, bqkv + l * QKVROW, 3);
            flash_kernel<<<dim3(8, 64), 128, FL_BYTES>>>(qkv, y);
            // x += y @ Wp + bp
            run_hm(y, CC, 0, 0, wh + wb + WOFF_P, CC, 0, 0,
                   x, nullptr, CC, 0, 0, MM, CC, CC, 1, 1, bp + l * CC, 2);
            ln_kernel<<<MM / 8, 256>>>(x, xn, ln2g + l * CC, ln2b + l * CC);
            // h = gelu(xn @ W1 + b1)
            run_hm(xn, CC, 0, 0, wh + wb + WOFF_1, CC, 0, 0,
                   nullptr, h, FF, 0, 0, MM, FF, CC, 1, 1, b1 + l * FF, 1);
            // x += h @ W2 + b2
            run_hm(h, FF, 0, 0, wh + wb + WOFF_2, FF, 0, 0,
                   x, nullptr, CC, 0, 0, MM, CC, FF, 1, 1, b2 + l * CC, 2);
        }
    }
    ln_kernel<<<MM / 8, 256>>>(x, xn, lnfg, lnfb);
    run_hm(xn, CC, 0, 0, wh + WOFF_HD, CC, 0, 0,
           out, nullptr, CC, 0, 0, MM, CC, CC, 1, 1, nullptr, 0);
}

// round 16
// speedup vs baseline: 2.8652x; 1.0418x over previous
#include <cuda_runtime.h>
#include <cuda_fp16.h>
#include <math.h>
#include <stdint.h>

#define BQ 8
#define TT 512
#define CC 512
#define HH 8
#define DHD 64
#define LL 2
#define MM (BQ * TT)
#define FF (4 * CC)
#define STEPS 4
typedef __half f16;
typedef long long ll;

// ------------------------- scratch (__device__ globals) --------------------
__device__ __align__(16) float g_x[MM * CC];
__device__ __align__(16) float g_bqkv[LL * 3 * CC];
__device__ __align__(16) f16 g_xn[MM * CC];
__device__ __align__(16) f16 g_qkv[MM * 3 * CC];
__device__ __align__(16) f16 g_y[MM * CC];
__device__ __align__(16) f16 g_h[MM * FF];
#define NW 6553600
__device__ __align__(16) f16 g_wh[NW];
#define WOFF_L   3145728
#define WOFF_QKV 0
#define WOFF_P   786432
#define WOFF_1   1048576
#define WOFF_2   2097152
#define WOFF_HD  6291456

// ------------------------- helpers -----------------------------------------
__device__ __forceinline__ unsigned pack2h(float x, float y) {
    __half2 r = __floats2half2_rn(x, y);
    return *(unsigned *)&r;
}
__device__ __forceinline__ unsigned smem_u32(const void *p) {
    return (unsigned)__cvta_generic_to_shared(p);
}
__device__ __forceinline__ float gelu_exact(float x) {
    return 0.5f * x * (1.0f + erff(x * 0.7071067811865476f));
}
__device__ __forceinline__ void mma_f16(float *d, const unsigned *a, unsigned b0, unsigned b1) {
    asm volatile(
        "mma.sync.aligned.m16n8k16.row.col.f32.f16.f16.f32 "
        "{%0,%1,%2,%3}, {%4,%5,%6,%7}, {%8,%9}, {%0,%1,%2,%3};\n"
        : "+f"(d[0]), "+f"(d[1]), "+f"(d[2]), "+f"(d[3])
        : "r"(a[0]), "r"(a[1]), "r"(a[2]), "r"(a[3]), "r"(b0), "r"(b1));
}
#define LDSM4(R0, R1, R2, R3, ADDR) \
    asm volatile("ldmatrix.sync.aligned.m8n8.x4.shared.b16 {%0,%1,%2,%3}, [%4];" \
                 : "=r"(R0), "=r"(R1), "=r"(R2), "=r"(R3) : "r"(ADDR))
#define LDSM4T(R0, R1, R2, R3, ADDR) \
    asm volatile("ldmatrix.sync.aligned.m8n8.x4.trans.shared.b16 {%0,%1,%2,%3}, [%4];" \
                 : "=r"(R0), "=r"(R1), "=r"(R2), "=r"(R3) : "r"(ADDR))
#define CP16(dst, src) \
    asm volatile("cp.async.cg.shared.global [%0], [%1], 16;" :: "r"(dst), "l"(src))
#define CP_COMMIT() asm volatile("cp.async.commit_group;" ::: "memory")
#define CP_WAIT0()  asm volatile("cp.async.wait_group 0;" ::: "memory")

// ------------------------- HMMA GEMM: fp16, tile 128x128, K-chunk 64 -------
// D = A@B^T. A K-major [m][k], B [N,K]. 8 warps (warp tile 32x64), 2-stage.
// ep: 0 fp32 store; 1 gelu->f16; 2 fp32 +=; 3 f16 store.
#define APITCH 72
// per-stage (f16 elems): A 128*72=9216 | B 128*72=9216 -> 18432 (36864 B)
#define STAGE_B 36864u
#define SMEM_BYTES (2 * 36864)

__global__ __launch_bounds__(256, 2)
void gemm_hmma(const f16 *__restrict__ A_, int lda, ll sA0, ll sA1,
               const f16 *__restrict__ B_, int ldb, ll sB0, ll sB1,
               float *__restrict__ Cf, f16 *__restrict__ Co,
               int ldc, ll sC0, ll sC1,
               int K, int zdiv, const float *__restrict__ bias, int ep)
{
    extern __shared__ __align__(16) f16 sm[];
    int z = blockIdx.z;
    ll zo0 = z / zdiv, zo1 = z % zdiv;
    A_ += zo0 * sA0 + zo1 * sA1;
    B_ += zo0 * sB0 + zo1 * sB1;
    ll coff = zo0 * sC0 + zo1 * sC1;
    int n0 = blockIdx.x * 128, m0 = blockIdx.y * 128;

    int t = threadIdx.x, lane = t & 31, warp = t >> 5;
    int wm = (warp & 3) << 5, wn = (warp >> 2) << 6;
    int gg = lane >> 2, cc2 = (lane & 3) << 1;

    int a_ck = (t & 7) << 3, a_rw = t >> 3;   // 32 rows/pass, 8 chunks/row

    unsigned sb = smem_u32(sm);

    int sel = lane >> 3, lr = lane & 7;
    int ar_g = lr + ((sel & 1) ? 8 : 0);
    int a_cs = (sel & 2) ? 8 : 0;
    int btr_g = lr + ((sel & 2) ? 8 : 0);
    int bt_cs = (sel & 1) ? 8 : 0;

    float acc[2][8][4];
#pragma unroll
    for (int mi = 0; mi < 2; mi++)
#pragma unroll
        for (int j = 0; j < 8; j++)
#pragma unroll
            for (int r = 0; r < 4; r++) acc[mi][j][r] = 0.f;

#define ISSUE(S, K0) do { \
    unsigned bb = sb + (unsigned)(S) * STAGE_B; \
    _Pragma("unroll") \
    for (int p = 0; p < 4; p++) { \
        int row = a_rw + 32 * p; \
        ll go = (ll)(m0 + row) * lda + (K0) + a_ck; \
        CP16(bb + (unsigned)((row * APITCH + a_ck) * 2), A_ + go); \
    } \
    _Pragma("unroll") \
    for (int p = 0; p < 4; p++) { \
        int row = a_rw + 32 * p; \
        ll go = (ll)(n0 + row) * ldb + (K0) + a_ck; \
        CP16(bb + 18432u + (unsigned)((row * APITCH + a_ck) * 2), B_ + go); \
    } \
    CP_COMMIT(); \
} while (0)

    int nk = K >> 6;
    ISSUE(0, 0);

    for (int c = 0; c < nk; c++) {
        CP_WAIT0();
        __syncthreads();
        if (c + 1 < nk) ISSUE((c + 1) & 1, (c + 1) << 6);

        unsigned bb = sb + (unsigned)(c & 1) * STAGE_B;
        unsigned ao = bb, bo = bb + 18432u;
#pragma unroll
        for (int ks = 0; ks < 4; ks++) {
            int kb = ks << 4;
            unsigned ah[2][4];
#pragma unroll
            for (int mi = 0; mi < 2; mi++) {
                unsigned off = (unsigned)(((wm + 16 * mi + ar_g) * APITCH + kb + a_cs) * 2);
                LDSM4(ah[mi][0], ah[mi][1], ah[mi][2], ah[mi][3], ao + off);
            }
            unsigned bh[8][2];
#pragma unroll
            for (int p = 0; p < 4; p++) {
                unsigned off = (unsigned)(((wn + 16 * p + btr_g) * APITCH + kb + bt_cs) * 2);
                LDSM4(bh[2 * p][0], bh[2 * p][1], bh[2 * p + 1][0], bh[2 * p + 1][1], bo + off);
            }
#pragma unroll
            for (int mi = 0; mi < 2; mi++)
#pragma unroll
                for (int j = 0; j < 8; j++)
                    mma_f16(acc[mi][j], ah[mi], bh[j][0], bh[j][1]);
        }
    }

#pragma unroll
    for (int mi = 0; mi < 2; mi++)
#pragma unroll
        for (int j = 0; j < 8; j++) {
            int col = n0 + wn + (j << 3) + cc2;
            int row = m0 + wm + (mi << 4) + gg;
            float b0v = bias ? bias[col] : 0.f;
            float b1v = bias ? bias[col + 1] : 0.f;
            float v00 = acc[mi][j][0] + b0v, v01 = acc[mi][j][1] + b1v;
            float v10 = acc[mi][j][2] + b0v, v11 = acc[mi][j][3] + b1v;
            ll g0 = (ll)row * ldc + col + coff;
            ll g1 = (ll)(row + 8) * ldc + col + coff;
            if (ep == 0) {
                *(float2 *)(Cf + g0) = make_float2(v00, v01);
                *(float2 *)(Cf + g1) = make_float2(v10, v11);
            } else if (ep == 2) {
                float2 o0 = *(float2 *)(Cf + g0), o1 = *(float2 *)(Cf + g1);
                *(float2 *)(Cf + g0) = make_float2(o0.x + v00, o0.y + v01);
                *(float2 *)(Cf + g1) = make_float2(o1.x + v10, o1.y + v11);
            } else if (ep == 1) {
                *(unsigned *)(Co + g0) = pack2h(gelu_exact(v00), gelu_exact(v01));
                *(unsigned *)(Co + g1) = pack2h(gelu_exact(v10), gelu_exact(v11));
            } else {
                *(unsigned *)(Co + g0) = pack2h(v00, v01);
                *(unsigned *)(Co + g1) = pack2h(v10, v11);
            }
        }
}

// ------------------------- flash attention (unchanged from R14) ------------
#define FP 72
#define FQ_OFF 0
#define FK_OFF(buf) (4608 + (buf) * 4608)
#define FV_OFF(buf) (13824 + (buf) * 4608)
#define FL_BYTES 46080

__global__ __launch_bounds__(128)
void flash_kernel(const f16 *__restrict__ qkv, f16 *__restrict__ y)
{
    extern __shared__ __align__(16) f16 fs[];
    int qt = blockIdx.x, bh = blockIdx.y;
    int b = bh >> 3, h = bh & 7;
    int t = threadIdx.x, lane = t & 31, w = t >> 5;
    ll rowbase = (ll)b * 512 * 1536 + h * 64;
    const f16 *Qg = qkv + rowbase;
    const f16 *Kg = qkv + rowbase + 512;
    const f16 *Vg = qkv + rowbase + 1024;
    unsigned sb = smem_u32(fs);

    for (int i = t; i < 512; i += 128) {
        int r = i >> 3, ck = (i & 7) << 3;
        ll go = (ll)(qt * 64 + r) * 1536 + ck;
        *(uint4 *)(fs + FQ_OFF + r * FP + ck) = *(const uint4 *)(Qg + go);
    }

#define ISSUE_KV(BUF, KT) do { \
    _Pragma("unroll") \
    for (int p = 0; p < 4; p++) { \
        int idx = t + 128 * p; \
        int r = idx >> 3, ck = (idx & 7) << 3; \
        ll go = (ll)((KT) * 64 + r) * 1536 + ck; \
        CP16(sb + (unsigned)((FK_OFF(BUF) + r * FP + ck) * 2), Kg + go); \
        CP16(sb + (unsigned)((FV_OFF(BUF) + r * FP + ck) * 2), Vg + go); \
    } \
    CP_COMMIT(); \
} while (0)

    int sel = lane >> 3, lr = lane & 7;
    int a_r = lr + ((sel & 1) ? 8 : 0), a_c = (sel & 2) ? 8 : 0;
    int bt_r = lr + ((sel & 2) ? 8 : 0), bt_c = (sel & 1) ? 8 : 0;
    int bn_r = lr + ((sel & 1) ? 8 : 0), bn_c = (sel & 2) ? 8 : 0;
    int g = lane >> 2, q4 = lane & 3;

    float acc_o[8][4];
#pragma unroll
    for (int j = 0; j < 8; j++)
#pragma unroll
        for (int r = 0; r < 4; r++) acc_o[j][r] = 0.f;
    float m0 = -1e30f, m1 = -1e30f, l0 = 0.f, l1 = 0.f;

    ISSUE_KV(0, 0);

    for (int kt = 0; kt < 8; kt++) {
        CP_WAIT0();
        __syncthreads();
        if (kt + 1 < 8) ISSUE_KV((kt + 1) & 1, kt + 1);
        int buf = kt & 1;
        unsigned kbase = sb + (unsigned)(FK_OFF(buf) * 2);
        unsigned vbase = sb + (unsigned)(FV_OFF(buf) * 2);

        float s[8][4];
#pragma unroll
        for (int j = 0; j < 8; j++)
#pragma unroll
            for (int r = 0; r < 4; r++) s[j][r] = 0.f;
#pragma unroll
        for (int kc = 0; kc < 4; kc++) {
            int kb = kc << 4;
            unsigned qh_[4];
            unsigned qoff = (unsigned)(((w * 16 + a_r) * FP + kb + a_c) * 2);
            LDSM4(qh_[0], qh_[1], qh_[2], qh_[3], sb + FQ_OFF * 2 + qoff);
            unsigned kh_[8][2];
#pragma unroll
            for (int p = 0; p < 4; p++) {
                unsigned koff = (unsigned)(((p * 16 + bt_r) * FP + kb + bt_c) * 2);
                LDSM4(kh_[2 * p][0], kh_[2 * p][1], kh_[2 * p + 1][0], kh_[2 * p + 1][1],
                      kbase + koff);
            }
#pragma unroll
            for (int j = 0; j < 8; j++) mma_f16(s[j], qh_, kh_[j][0], kh_[j][1]);
        }

        float tm0 = -1e30f, tm1 = -1e30f;
#pragma unroll
        for (int j = 0; j < 8; j++) {
            s[j][0] *= 0.125f; s[j][1] *= 0.125f; s[j][2] *= 0.125f; s[j][3] *= 0.125f;
            tm0 = fmaxf(tm0, fmaxf(s[j][0], s[j][1]));
            tm1 = fmaxf(tm1, fmaxf(s[j][2], s[j][3]));
        }
        tm0 = fmaxf(tm0, __shfl_xor_sync(0xffffffffu, tm0, 1));
        tm0 = fmaxf(tm0, __shfl_xor_sync(0xffffffffu, tm0, 2));
        tm1 = fmaxf(tm1, __shfl_xor_sync(0xffffffffu, tm1, 1));
        tm1 = fmaxf(tm1, __shfl_xor_sync(0xffffffffu, tm1, 2));
        float nm0 = fmaxf(m0, tm0), nm1 = fmaxf(m1, tm1);
        float al0 = __expf(m0 - nm0), al1 = __expf(m1 - nm1);
        m0 = nm0; m1 = nm1;
        float sum0 = 0.f, sum1 = 0.f;
#pragma unroll
        for (int j = 0; j < 8; j++) {
            s[j][0] = __expf(s[j][0] - nm0); sum0 += s[j][0];
            s[j][1] = __expf(s[j][1] - nm0); sum0 += s[j][1];
            s[j][2] = __expf(s[j][2] - nm1); sum1 += s[j][2];
            s[j][3] = __expf(s[j][3] - nm1); sum1 += s[j][3];
        }
        sum0 += __shfl_xor_sync(0xffffffffu, sum0, 1);
        sum0 += __shfl_xor_sync(0xffffffffu, sum0, 2);
        sum1 += __shfl_xor_sync(0xffffffffu, sum1, 1);
        sum1 += __shfl_xor_sync(0xffffffffu, sum1, 2);
        l0 = l0 * al0 + sum0; l1 = l1 * al1 + sum1;
#pragma unroll
        for (int j = 0; j < 8; j++) {
            acc_o[j][0] *= al0; acc_o[j][1] *= al0;
            acc_o[j][2] *= al1; acc_o[j][3] *= al1;
        }

#pragma unroll
        for (int kc = 0; kc < 4; kc++) {
            unsigned pa[4];
            pa[0] = pack2h(s[2 * kc][0],     s[2 * kc][1]);
            pa[1] = pack2h(s[2 * kc][2],     s[2 * kc][3]);
            pa[2] = pack2h(s[2 * kc + 1][0], s[2 * kc + 1][1]);
            pa[3] = pack2h(s[2 * kc + 1][2], s[2 * kc + 1][3]);
            unsigned vh_[8][2];
#pragma unroll
            for (int p = 0; p < 4; p++) {
                unsigned voff = (unsigned)((((kc << 4) + bn_r) * FP + p * 16 + bn_c) * 2);
                LDSM4T(vh_[2 * p][0], vh_[2 * p][1], vh_[2 * p + 1][0], vh_[2 * p + 1][1],
                       vbase + voff);
            }
#pragma unroll
            for (int j = 0; j < 8; j++) mma_f16(acc_o[j], pa, vh_[j][0], vh_[j][1]);
        }
    }

    float i0 = 1.f / l0, i1 = 1.f / l1;
    int r0 = qt * 64 + w * 16 + g;
#pragma unroll
    for (int j = 0; j < 8; j++) {
        int col = h * 64 + j * 8 + 2 * q4;
        ll g0 = ((ll)(b * 512 + r0)) * 512 + col;
        ll g1 = ((ll)(b * 512 + r0 + 8)) * 512 + col;
        *(unsigned *)(y + g0) = pack2h(acc_o[j][0] * i0, acc_o[j][1] * i0);
        *(unsigned *)(y + g1) = pack2h(acc_o[j][2] * i1, acc_o[j][3] * i1);
    }
}

// ------------------------- merged one-time weight conv + bias cat ----------
struct WA {
    const float *src[13];
    ll doff[13];
    int K[13], N[13];
    const float *bq, *bk, *bv;
    float *bqkv;
};

__global__ __launch_bounds__(256)
void wconv_all(WA a, f16 *__restrict__ wh)
{
    int m = blockIdx.z;
    if (m == 13) {
        if (blockIdx.x == 0 && blockIdx.y == 0) {
            for (int i = threadIdx.x; i < LL * 3 * CC; i += 256) {
                int l = i / (3 * CC), c = i % (3 * CC);
                float v;
                if (c < CC) v = a.bq[l * CC + c];
                else if (c < 2 * CC) v = a.bk[l * CC + c - CC];
                else v = a.bv[l * CC + c - 2 * CC];
                a.bqkv[i] = v;
            }
        }
        return;
    }
    int K = a.K[m], N = a.N[m];
    int bx = blockIdx.x * 32, by = blockIdx.y * 32;
    if (bx >= N || by >= K) return;
    const float *W = a.src[m];
    f16 *th = wh + a.doff[m];
    __shared__ float tile[32][33];
    int tx = threadIdx.x & 31, ty = threadIdx.x >> 5;
#pragma unroll
    for (int j = 0; j < 4; j++) {
        int kk = ty + j * 8;
        tile[kk][tx] = W[(ll)(by + kk) * N + bx + tx];
    }
    __syncthreads();
#pragma unroll
    for (int j = 0; j < 4; j++) {
        int nn = ty + j * 8;
        th[(ll)(bx + nn) * K + by + tx] = __float2half_rn(tile[tx][nn]);
    }
}

// ------------------------- warp-per-row LN ---------------------------------
__device__ __forceinline__ void ln_row_body(float4 *v, int lane, ll orow,
                                            const float *__restrict__ gam,
                                            const float *__restrict__ bet,
                                            f16 *__restrict__ oh)
{
    float sum = 0.f;
#pragma unroll
    for (int k = 0; k < 4; k++) sum += v[k].x + v[k].y + v[k].z + v[k].w;
#pragma unroll
    for (int o = 16; o > 0; o >>= 1) sum += __shfl_xor_sync(0xffffffffu, sum, o);
    float mu = sum * (1.0f / CC);
    float var = 0.f;
#pragma unroll
    for (int k = 0; k < 4; k++) {
        v[k].x -= mu; v[k].y -= mu; v[k].z -= mu; v[k].w -= mu;
        var += v[k].x * v[k].x + v[k].y * v[k].y + v[k].z * v[k].z + v[k].w * v[k].w;
    }
#pragma unroll
    for (int o = 16; o > 0; o >>= 1) var += __shfl_xor_sync(0xffffffffu, var, o);
    float rstd = rsqrtf(var * (1.0f / CC) + 1e-5f);
#pragma unroll
    for (int k = 0; k < 4; k++) {
        int c = k * 128 + lane * 4;
        float r0 = v[k].x * rstd * gam[c]     + bet[c];
        float r1 = v[k].y * rstd * gam[c + 1] + bet[c + 1];
        float r2 = v[k].z * rstd * gam[c + 2] + bet[c + 2];
        float r3 = v[k].w * rstd * gam[c + 3] + bet[c + 3];
        *(uint2 *)(oh + orow + c) = make_uint2(pack2h(r0, r1), pack2h(r2, r3));
    }
}

__global__ __launch_bounds__(256)
void ln_kernel(const float *__restrict__ x, f16 *__restrict__ oh,
               const float *__restrict__ gam, const float *__restrict__ bet)
{
    int w = threadIdx.x >> 5, lane = threadIdx.x & 31;
    int row = blockIdx.x * 8 + w;
    const float *xr = x + (ll)row * CC;
    float4 v[4];
#pragma unroll
    for (int k = 0; k < 4; k++) v[k] = *(const float4 *)(xr + k * 128 + lane * 4);
    ln_row_body(v, lane, (ll)row * CC, gam, bet, oh);
}

__global__ __launch_bounds__(256)
void embed_ln_kernel(const int *__restrict__ idx, const float *__restrict__ tok,
                     const float *__restrict__ pos, float *__restrict__ x,
                     f16 *__restrict__ oh,
                     const float *__restrict__ gam, const float *__restrict__ bet)
{
    int w = threadIdx.x >> 5, lane = threadIdx.x & 31;
    int row = blockIdx.x * 8 + w;
    int tp = row & (TT - 1);
    int tr = idx[row];
    float4 v[4];
#pragma unroll
    for (int k = 0; k < 4; k++) {
        int c = k * 128 + lane * 4;
        float4 tv = *(const float4 *)(tok + (ll)tr * CC + c);
        float4 pv = *(const float4 *)(pos + (ll)tp * CC + c);
        v[k] = make_float4(tv.x + pv.x, tv.y + pv.y, tv.z + pv.z, tv.w + pv.w);
        *(float4 *)(x + (ll)row * CC + c) = v[k];
    }
    ln_row_body(v, lane, (ll)row * CC, gam, bet, oh);
}

// ------------------------- host orchestration ------------------------------
static void run_hm(const f16 *A, int lda, ll sA0, ll sA1,
                   const f16 *B, int ldb, ll sB0, ll sB1,
                   float *Cf, f16 *Co, int ldc, ll sC0, ll sC1,
                   int Mr, int Nc, int K, int zdiv, int Z,
                   const float *bias, int ep)
{
    dim3 g(Nc / 128, Mr / 128, Z);
    gemm_hmma<<<g, 256, SMEM_BYTES>>>(A, lda, sA0, sA1, B, ldb, sB0, sB1,
                                      Cf, Co, ldc, sC0, sC1, K, zdiv, bias, ep);
}

extern "C" void kernel_launch(void *const *d_in, const int *in_sizes, int n_in,
                              void *d_out, int out_size)
{
    (void)in_sizes; (void)n_in; (void)out_size;
    const int   *idx  = (const int *)d_in[0];
    const float *tok  = (const float *)d_in[1];
    const float *pos  = (const float *)d_in[2];
    const float *ln1g = (const float *)d_in[3];
    const float *ln1b = (const float *)d_in[4];
    const float *Wq   = (const float *)d_in[5];
    const float *bq   = (const float *)d_in[6];
    const float *Wk   = (const float *)d_in[7];
    const float *bk   = (const float *)d_in[8];
    const float *Wv   = (const float *)d_in[9];
    const float *bv   = (const float *)d_in[10];
    const float *Wp   = (const float *)d_in[11];
    const float *bp   = (const float *)d_in[12];
    const float *ln2g = (const float *)d_in[13];
    const float *ln2b = (const float *)d_in[14];
    const float *W1   = (const float *)d_in[15];
    const float *b1   = (const float *)d_in[16];
    const float *W2   = (const float *)d_in[17];
    const float *b2   = (const float *)d_in[18];
    const float *lnfg = (const float *)d_in[19];
    const float *lnfb = (const float *)d_in[20];
    const float *Wh   = (const float *)d_in[21];
    float *out = (float *)d_out;

    static int attr_set = 0;
    if (!attr_set) {
        cudaFuncSetAttribute(gemm_hmma, cudaFuncAttributeMaxDynamicSharedMemorySize, SMEM_BYTES);
        cudaFuncSetAttribute(flash_kernel, cudaFuncAttributeMaxDynamicSharedMemorySize, FL_BYTES);
        attr_set = 1;
    }

    float *x, *bqkv;
    f16 *xn, *qkv, *y, *h, *wh;
    cudaGetSymbolAddress((void **)&x, g_x);
    cudaGetSymbolAddress((void **)&bqkv, g_bqkv);
    cudaGetSymbolAddress((void **)&xn, g_xn);
    cudaGetSymbolAddress((void **)&qkv, g_qkv);
    cudaGetSymbolAddress((void **)&y, g_y);
    cudaGetSymbolAddress((void **)&h, g_h);
    cudaGetSymbolAddress((void **)&wh, g_wh);

    WA wa;
    for (int l = 0; l < LL; l++) {
        ll wb = (ll)l * WOFF_L;
        int base = l * 6;
        wa.src[base + 0] = Wq + (ll)l * CC * CC; wa.doff[base + 0] = wb;           wa.K[base + 0] = CC; wa.N[base + 0] = CC;
        wa.src[base + 1] = Wk + (ll)l * CC * CC; wa.doff[base + 1] = wb + 262144;  wa.K[base + 1] = CC; wa.N[base + 1] = CC;
        wa.src[base + 2] = Wv + (ll)l * CC * CC; wa.doff[base + 2] = wb + 524288;  wa.K[base + 2] = CC; wa.N[base + 2] = CC;
        wa.src[base + 3] = Wp + (ll)l * CC * CC; wa.doff[base + 3] = wb + WOFF_P;  wa.K[base + 3] = CC; wa.N[base + 3] = CC;
        wa.src[base + 4] = W1 + (ll)l * CC * FF; wa.doff[base + 4] = wb + WOFF_1;  wa.K[base + 4] = CC; wa.N[base + 4] = FF;
        wa.src[base + 5] = W2 + (ll)l * FF * CC; wa.doff[base + 5] = wb + WOFF_2;  wa.K[base + 5] = FF; wa.N[base + 5] = CC;
    }
    wa.src[12] = Wh; wa.doff[12] = WOFF_HD; wa.K[12] = CC; wa.N[12] = CC;
    wa.bq = bq; wa.bk = bk; wa.bv = bv; wa.bqkv = bqkv;
    wconv_all<<<dim3(64, 64, 14), 256>>>(wa, wh);
    embed_ln_kernel<<<MM / 8, 256>>>(idx, tok, pos, x, xn, ln1g, ln1b);

    const ll QKVROW = 3 * CC;

    for (int s = 0; s < STEPS; s++) {
        for (int l = 0; l < LL; l++) {
            ll wb = (ll)l * WOFF_L;
            if (!(s == 0 && l == 0))
                ln_kernel<<<MM / 8, 256>>>(x, xn, ln1g + l * CC, ln1b + l * CC);
            // fused QKV -> f16
            run_hm(xn, CC, 0, 0, wh + wb + WOFF_QKV, CC, 0, 0,
                   nullptr, qkv, (int)QKVROW, 0, 0,
                   MM, (int)QKVROW, CC, 1, 1, bqkv + l * QKVROW, 3);
            flash_kernel<<<dim3(8, 64), 128, FL_BYTES>>>(qkv, y);
            // x += y @ Wp + bp
            run_hm(y, CC, 0, 0, wh + wb + WOFF_P, CC, 0, 0,
                   x, nullptr, CC, 0, 0, MM, CC, CC, 1, 1, bp + l * CC, 2);
            ln_kernel<<<MM / 8, 256>>>(x, xn, ln2g + l * CC, ln2b + l * CC);
            // h = gelu(xn @ W1 + b1)
            run_hm(xn, CC, 0, 0, wh + wb + WOFF_1, CC, 0, 0,
                   nullptr, h, FF, 0, 0, MM, FF, CC, 1, 1, b1 + l * FF, 1);
            // x += h @ W2 + b2
            run_hm(h, FF, 0, 0, wh + wb + WOFF_2, FF, 0, 0,
                   x, nullptr, CC, 0, 0, MM, CC, FF, 1, 1, b2 + l * CC, 2);
        }
    }
    ln_kernel<<<MM / 8, 256>>>(x, xn, lnfg, lnfb);
    run_hm(xn, CC, 0, 0, wh + WOFF_HD, CC, 0, 0,
           out, nullptr, CC, 0, 0, MM, CC, CC, 1, 1, nullptr, 0);
}